// round 2
// baseline (speedup 1.0000x reference)
#include <cuda_runtime.h>
#include <cuda_bf16.h>
#include <math.h>

// ---------------- problem constants ----------------
#define Nn   27
#define NA   33
#define OFF  6
#define ATK  27        // NA - OFF
#define HID  256
#define HEADS 4
#define HD   16
#define Vv   8
#define REL  5
#define TOPK 4
#define INW  322
#define FLAT 32        // HEADS*V
#define FUSE_SCALE 0.1f
#define NEG  (-10000000000.0f)
#define MAXROWS 27648

// ---------------- scratch (device globals; no allocation allowed) -------------
__device__ float g_x     [MAXROWS * 256];
__device__ float g_gi    [MAXROWS * 768];
__device__ float g_gh    [MAXROWS * 768];
__device__ float g_p     [MAXROWS * 256];
__device__ float g_logits[MAXROWS * 33];
__device__ float g_attack[MAXROWS * 27];
__device__ float g_sender[MAXROWS * 32];
__device__ float g_q     [MAXROWS * 64];
__device__ float g_keyh  [MAXROWS * 64];
__device__ float g_qr    [MAXROWS * 20];
__device__ float g_qb    [MAXROWS * 4];
__device__ float g_normed[MAXROWS * 32];
__device__ float g_fusion[MAXROWS * 288];
__device__ float g_g1    [MAXROWS * 256];
__device__ float g_d1    [MAXROWS * 256];
__device__ float g_hfb   [MAXROWS * 256];   // fallback h output if out buffer is small

// ---------------- generic tiled GEMM: C[m,n] = sum_k A[m,k]*B[n,k] (+bias)(relu) ----
// A row-major [M,lda], B row-major [N,ldb] (i.e. computes A @ B^T)
#define EPI_NONE 0
#define EPI_BIAS 1
#define EPI_BIAS_RELU 2

template<int EPI>
__global__ void __launch_bounds__(256)
gemm_tn(const float* __restrict__ A, int lda,
        const float* __restrict__ B, int ldb,
        const float* __restrict__ bias,
        float* __restrict__ C, int ldc,
        int M, int N, int K)
{
    constexpr int BM = 128, BN = 64, BK = 16, TM = 8, TN = 4;
    __shared__ float As[BK][BM + 4];
    __shared__ float Bs[BK][BN + 4];
    const int tid = threadIdx.x;
    const int tx = tid & 15, ty = tid >> 4;
    const int m0 = blockIdx.x * BM, n0 = blockIdx.y * BN;

    float acc[TM][TN];
#pragma unroll
    for (int a = 0; a < TM; a++)
#pragma unroll
        for (int b = 0; b < TN; b++) acc[a][b] = 0.f;

    for (int k0 = 0; k0 < K; k0 += BK) {
#pragma unroll
        for (int i = 0; i < (BM * BK) / 256; i++) {
            int idx = tid + i * 256;
            int m = idx / BK, k = idx % BK;
            int gm = m0 + m, gk = k0 + k;
            As[k][m] = (gm < M && gk < K) ? A[(size_t)gm * lda + gk] : 0.f;
        }
#pragma unroll
        for (int i = 0; i < (BN * BK) / 256; i++) {
            int idx = tid + i * 256;
            int n = idx / BK, k = idx % BK;
            int gn = n0 + n, gk = k0 + k;
            Bs[k][n] = (gn < N && gk < K) ? B[(size_t)gn * ldb + gk] : 0.f;
        }
        __syncthreads();
#pragma unroll
        for (int k = 0; k < BK; k++) {
            float a[TM], b[TN];
#pragma unroll
            for (int tm = 0; tm < TM; tm++) a[tm] = As[k][ty * TM + tm];
#pragma unroll
            for (int tn = 0; tn < TN; tn++) b[tn] = Bs[k][tx * TN + tn];
#pragma unroll
            for (int tm = 0; tm < TM; tm++)
#pragma unroll
                for (int tn = 0; tn < TN; tn++)
                    acc[tm][tn] += a[tm] * b[tn];
        }
        __syncthreads();
    }
#pragma unroll
    for (int tm = 0; tm < TM; tm++) {
        int gm = m0 + ty * TM + tm;
        if (gm >= M) continue;
#pragma unroll
        for (int tn = 0; tn < TN; tn++) {
            int gn = n0 + tx * TN + tn;
            if (gn >= N) continue;
            float v = acc[tm][tn];
            if (EPI >= EPI_BIAS) v += bias[gn];
            if (EPI == EPI_BIAS_RELU) v = fmaxf(v, 0.f);
            C[(size_t)gm * ldc + gn] = v;
        }
    }
}

// ---------------- GRU elementwise ----------------
__global__ void gru_kernel(const float* __restrict__ gi, const float* __restrict__ gh,
                           const float* __restrict__ hin, float* __restrict__ hout, int total)
{
    int idx = blockIdx.x * blockDim.x + threadIdx.x;
    if (idx >= total) return;
    int r = idx >> 8, c = idx & 255;
    size_t base = (size_t)r * 768;
    float ir = gi[base + c], iz = gi[base + 256 + c], in_ = gi[base + 512 + c];
    float hr = gh[base + c], hz = gh[base + 256 + c], hn = gh[base + 512 + c];
    float rg = 1.f / (1.f + expf(-(ir + hr)));
    float zg = 1.f / (1.f + expf(-(iz + hz)));
    float ng = tanhf(in_ + rg * hn);
    hout[idx] = (1.f - zg) * ng + zg * hin[idx];
}

// ---------------- logits post: softmax + value_source + sender_values + base copy -----
// one warp per row
__global__ void logits_post(const float* __restrict__ logits,   // [rows,33]
                            const float* __restrict__ Wv,       // [32,29]
                            const float* __restrict__ bv,       // [32]
                            float* __restrict__ out,            // [rows,33] (base written)
                            float* __restrict__ attack,         // [rows,27]
                            float* __restrict__ sender)         // [rows,32]
{
    int row = blockIdx.x;
    int lane = threadIdx.x;
    const float* lrow = logits + (size_t)row * 33;
    float al = (lane < 27) ? lrow[6 + lane] : -INFINITY;
    float mx = al;
#pragma unroll
    for (int o = 16; o > 0; o >>= 1) mx = fmaxf(mx, __shfl_xor_sync(0xffffffffu, mx, o));
    float e = (lane < 27) ? expf(al - mx) : 0.f;
    float sum = e;
#pragma unroll
    for (int o = 16; o > 0; o >>= 1) sum += __shfl_xor_sync(0xffffffffu, sum, o);
    __shared__ float vs[29];
    if (lane < 27) vs[lane] = e / sum;
    if (lane == 0) { vs[27] = 1.0f; vs[28] = 1.0f / sum; }   // can_attack=1, top1 = maxprob = 1/sum
    if (lane < 27) attack[(size_t)row * 27 + lane] = al;
    if (lane < 6)  out[(size_t)row * 33 + lane] = lrow[lane];
    __syncwarp();
    float s = bv[lane];
#pragma unroll
    for (int r = 0; r < 29; r++) s += vs[r] * Wv[lane * 29 + r];
    sender[(size_t)row * 32 + lane] = s;
}

// ---------------- qr / qb precompute: qr = q @ Wk_r, qb = q . bk ----------------
__global__ void qr_kernel(const float* __restrict__ q, const float* __restrict__ Wk,
                          const float* __restrict__ bk,
                          float* __restrict__ qr, float* __restrict__ qb, int rows)
{
    int idx = blockIdx.x * blockDim.x + threadIdx.x;
    if (idx >= rows * 4) return;
    int row = idx >> 2, h = idx & 3;
    const float* qp = q + (size_t)row * 64 + h * 16;
    float acc[5] = {0.f, 0.f, 0.f, 0.f, 0.f};
    float accb = 0.f;
#pragma unroll
    for (int d = 0; d < 16; d++) {
        float qd = qp[d];
        const float* wrow = Wk + (size_t)(h * 16 + d) * (HID + REL) + HID;
#pragma unroll
        for (int r = 0; r < 5; r++) acc[r] += qd * wrow[r];
        accb += qd * bk[h * 16 + d];
    }
#pragma unroll
    for (int r = 0; r < 5; r++) qr[(size_t)row * 20 + h * 5 + r] = acc[r];
    qb[(size_t)row * 4 + h] = accb;
}

// ---------------- attention + topk + softmax + messages + layernorm ----------------
// one block per (b,i) row, 128 threads
__global__ void __launch_bounds__(128)
attn_kernel(const float* __restrict__ q,      // [rows,64]
            const float* __restrict__ keyh,   // [rows,64]
            const float* __restrict__ qr,     // [rows,20]
            const float* __restrict__ qb,     // [rows,4]
            const float* __restrict__ rel,    // [bs,27,27,5]
            const float* __restrict__ sender, // [rows,32]
            const float* __restrict__ nullk,  // [4,16]
            const float* __restrict__ nullv,  // [4,8]
            const float* __restrict__ ln_g, const float* __restrict__ ln_b,
            float* __restrict__ normed)       // [rows,32]
{
    int row = blockIdx.x;
    int b = row / Nn, i = row % Nn;
    int tid = threadIdx.x;
    __shared__ float keyh_s[Nn * 64];
    __shared__ float sender_s[Nn * 32];
    __shared__ float rel_s[Nn * 5];
    __shared__ float q_s[64];
    __shared__ float qr_s[20];
    __shared__ float qb_s[4];
    __shared__ float nk_s[64];
    __shared__ float nv_s[32];
    __shared__ float sc[28 * 4];
    __shared__ float msg[32];

    const float* keyh_b = keyh + (size_t)b * Nn * 64;
    for (int t = tid; t < Nn * 64; t += 128) keyh_s[t] = keyh_b[t];
    const float* send_b = sender + (size_t)b * Nn * 32;
    for (int t = tid; t < Nn * 32; t += 128) sender_s[t] = send_b[t];
    const float* rel_bi = rel + ((size_t)b * Nn + i) * Nn * 5;
    for (int t = tid; t < Nn * 5; t += 128) rel_s[t] = rel_bi[t];
    if (tid < 64) { q_s[tid] = q[(size_t)row * 64 + tid]; nk_s[tid] = nullk[tid]; }
    if (tid < 20) qr_s[tid] = qr[(size_t)row * 20 + tid];
    if (tid < 4)  qb_s[tid] = qb[(size_t)row * 4 + tid];
    if (tid >= 64 && tid < 96) nv_s[tid - 64] = nullv[tid - 64];
    __syncthreads();

    if (tid < 108) {            // 27 real senders x 4 heads
        int j = tid >> 2, h = tid & 3;
        float s;
        if (j == i) s = NEG;
        else {
            float d = qb_s[h];
#pragma unroll
            for (int dd = 0; dd < 16; dd++) d += q_s[h * 16 + dd] * keyh_s[j * 64 + h * 16 + dd];
#pragma unroll
            for (int r = 0; r < 5; r++) d += qr_s[h * 5 + r] * rel_s[j * 5 + r];
            s = 0.25f * d;
        }
        sc[j * 4 + h] = s;
    } else if (tid < 112) {     // null key
        int h = tid - 108;
        float d = 0.f;
#pragma unroll
        for (int dd = 0; dd < 16; dd++) d += q_s[h * 16 + dd] * nk_s[h * 16 + dd];
        sc[27 * 4 + h] = 0.25f * d;
    }
    __syncthreads();

    if (tid < 4) {
        int h = tid;
        float t0 = -INFINITY, t1 = -INFINITY, t2 = -INFINITY, t3 = -INFINITY;
#pragma unroll
        for (int j = 0; j < 28; j++) {
            float v = sc[j * 4 + h];
            if (v > t0)      { t3 = t2; t2 = t1; t1 = t0; t0 = v; }
            else if (v > t1) { t3 = t2; t2 = t1; t1 = v; }
            else if (v > t2) { t3 = t2; t2 = v; }
            else if (v > t3) { t3 = v; }
        }
        float thr = t3, mxv = t0, sum = 0.f;
        float e[28];
#pragma unroll
        for (int j = 0; j < 28; j++) {
            float v = sc[j * 4 + h];
            float ev = (v >= thr) ? expf(v - mxv) : 0.f;
            e[j] = ev; sum += ev;
        }
        float inv = 1.f / sum;
#pragma unroll
        for (int j = 0; j < 28; j++) sc[j * 4 + h] = e[j] * inv;
    }
    __syncthreads();

    if (tid < 32) {
        int h = tid >> 3, v = tid & 7;
        float m = sc[27 * 4 + h] * nv_s[h * 8 + v];
#pragma unroll
        for (int j = 0; j < 27; j++) m += sc[j * 4 + h] * sender_s[j * 32 + h * 8 + v];
        msg[tid] = m;
    }
    __syncthreads();
    if (tid < 32) {
        float val = msg[tid];
        float s = val, s2 = val * val;
#pragma unroll
        for (int o = 16; o > 0; o >>= 1) {
            s  += __shfl_xor_sync(0xffffffffu, s, o);
            s2 += __shfl_xor_sync(0xffffffffu, s2, o);
        }
        float mu = s * (1.f / 32.f);
        float var = s2 * (1.f / 32.f) - mu * mu;
        normed[(size_t)row * 32 + tid] = (val - mu) * rsqrtf(var + 1e-5f) * ln_g[tid] + ln_b[tid];
    }
}

// ---------------- fusion concat ----------------
__global__ void fusion_kernel(const float* __restrict__ h, const float* __restrict__ normed,
                              float* __restrict__ fusion, int rows)
{
    int idx = blockIdx.x * blockDim.x + threadIdx.x;
    if (idx >= rows * 288) return;
    int r = idx / 288, c = idx % 288;
    fusion[idx] = (c < 256) ? h[(size_t)r * 256 + c] : normed[(size_t)r * 32 + (c - 256)];
}

// ---------------- final: gate, delta, fused output ----------------
// one warp per row
__global__ void final_kernel(const float* __restrict__ g1,   // [rows,256]
                             const float* __restrict__ d1,   // [rows,256]
                             const float* __restrict__ Wg2, const float* __restrict__ bg2,
                             const float* __restrict__ Wd2, const float* __restrict__ bd2,
                             const float* __restrict__ attack,
                             float* __restrict__ out)        // [rows,33]
{
    int row = blockIdx.x;
    int lane = threadIdx.x;
    __shared__ float d1s[256];
    const float* g1r = g1 + (size_t)row * 256;
    const float* d1r = d1 + (size_t)row * 256;
    float gs = 0.f;
#pragma unroll
    for (int i = 0; i < 8; i++) {
        int k = lane + i * 32;
        d1s[k] = d1r[k];
        gs += g1r[k] * Wg2[k];
    }
#pragma unroll
    for (int o = 16; o > 0; o >>= 1) gs += __shfl_xor_sync(0xffffffffu, gs, o);
    float gate = 1.f / (1.f + expf(-(gs + bg2[0])));
    __syncwarp();
    if (lane < 27) {
        float d = bd2[lane];
        const float* w = Wd2 + lane * 256;
#pragma unroll 8
        for (int k = 0; k < 256; k++) d += d1s[k] * w[k];
        out[(size_t)row * 33 + 6 + lane] = attack[(size_t)row * 27 + lane] + FUSE_SCALE * gate * d;
    }
}

// ---------------- host launcher ----------------
static float* sym(const void* symbol)
{
    void* p = nullptr;
    cudaGetSymbolAddress(&p, symbol);
    return (float*)p;
}

extern "C" void kernel_launch(void* const* d_in, const int* in_sizes, int n_in,
                              void* d_out, int out_size)
{
    const float* inputs  = (const float*)d_in[0];
    const float* hidden  = (const float*)d_in[1];
    const float* rel     = (const float*)d_in[2];
    const float* W1      = (const float*)d_in[3];
    const float* b1      = (const float*)d_in[4];
    const float* Wih     = (const float*)d_in[5];
    const float* bih     = (const float*)d_in[6];
    const float* Whh     = (const float*)d_in[7];
    const float* bhh     = (const float*)d_in[8];
    const float* Wp1     = (const float*)d_in[9];
    const float* bp1     = (const float*)d_in[10];
    const float* Wp2     = (const float*)d_in[11];
    const float* bp2     = (const float*)d_in[12];
    const float* Wq      = (const float*)d_in[13];
    const float* bq      = (const float*)d_in[14];
    const float* Wk      = (const float*)d_in[15];
    const float* bk      = (const float*)d_in[16];
    const float* Wv      = (const float*)d_in[17];
    const float* bv      = (const float*)d_in[18];
    const float* ln_g    = (const float*)d_in[19];
    const float* ln_b    = (const float*)d_in[20];
    const float* Wg1     = (const float*)d_in[21];
    const float* bg1     = (const float*)d_in[22];
    const float* Wg2     = (const float*)d_in[23];
    const float* bg2     = (const float*)d_in[24];
    const float* Wd1     = (const float*)d_in[25];
    const float* bd1     = (const float*)d_in[26];
    const float* Wd2     = (const float*)d_in[27];
    const float* bd2     = (const float*)d_in[28];
    const float* nullk   = (const float*)d_in[29];
    const float* nullv   = (const float*)d_in[30];

    const int rows = in_sizes[0] / INW;           // bs * N = 27648
    float* out = (float*)d_out;

    float* px      = sym(g_x);
    float* pgi     = sym(g_gi);
    float* pgh     = sym(g_gh);
    float* pp      = sym(g_p);
    float* plogits = sym(g_logits);
    float* pattack = sym(g_attack);
    float* psender = sym(g_sender);
    float* pq      = sym(g_q);
    float* pkeyh   = sym(g_keyh);
    float* pqr     = sym(g_qr);
    float* pqb     = sym(g_qb);
    float* pnormed = sym(g_normed);
    float* pfusion = sym(g_fusion);
    float* pg1     = sym(g_g1);
    float* pd1     = sym(g_d1);

    // h output location: second element of the returned tuple, after final [rows,33]
    float* hout = (out_size >= rows * (NA + HID)) ? out + (size_t)rows * NA : sym(g_hfb);

    auto grid = [&](int M, int Ncols) { return dim3((M + 127) / 128, (Ncols + 63) / 64); };

    // 1. x = relu(inputs @ W1^T + b1)
    gemm_tn<EPI_BIAS_RELU><<<grid(rows, 256), 256>>>(inputs, INW, W1, INW, b1, px, 256, rows, 256, INW);
    // 2. gi = x @ Wih^T + bih ; gh = h_in @ Whh^T + bhh
    gemm_tn<EPI_BIAS><<<grid(rows, 768), 256>>>(px, 256, Wih, 256, bih, pgi, 768, rows, 768, 256);
    gemm_tn<EPI_BIAS><<<grid(rows, 768), 256>>>(hidden, 256, Whh, 256, bhh, pgh, 768, rows, 768, 256);
    // 3. GRU combine -> h (written straight into output slice)
    gru_kernel<<<(rows * 256 + 255) / 256, 256>>>(pgi, pgh, hidden, hout, rows * 256);
    // 4. p = relu(h @ Wp1^T + bp1) ; logits = p @ Wp2^T + bp2
    gemm_tn<EPI_BIAS_RELU><<<grid(rows, 256), 256>>>(hout, 256, Wp1, 256, bp1, pp, 256, rows, 256, 256);
    gemm_tn<EPI_BIAS><<<grid(rows, NA), 256>>>(pp, 256, Wp2, 256, bp2, plogits, NA, rows, NA, 256);
    // 5. softmax / value_source / sender_values ; base logits -> out
    logits_post<<<rows, 32>>>(plogits, Wv, bv, out, pattack, psender);
    // 6. q = h @ Wq^T + bq ; key_h = h @ Wk[:, :256]^T
    gemm_tn<EPI_BIAS><<<grid(rows, 64), 256>>>(hout, 256, Wq, 256, bq, pq, 64, rows, 64, 256);
    gemm_tn<EPI_NONE><<<grid(rows, 64), 256>>>(hout, 256, Wk, HID + REL, nullptr, pkeyh, 64, rows, 64, 256);
    // 7. qr = q @ Wk_r ; qb = q . bk
    qr_kernel<<<(rows * 4 + 127) / 128, 128>>>(pq, Wk, bk, pqr, pqb, rows);
    // 8. attention + topk softmax + messages + layernorm
    attn_kernel<<<rows, 128>>>(pq, pkeyh, pqr, pqb, rel, psender, nullk, nullv, ln_g, ln_b, pnormed);
    // 9. fusion = [h, normed]
    fusion_kernel<<<(rows * 288 + 255) / 256, 256>>>(hout, pnormed, pfusion, rows);
    // 10. g1 = relu(fusion @ Wg1^T + bg1) ; d1 = relu(fusion @ Wd1^T + bd1)
    gemm_tn<EPI_BIAS_RELU><<<grid(rows, 256), 256>>>(pfusion, 288, Wg1, 288, bg1, pg1, 256, rows, 256, 288);
    gemm_tn<EPI_BIAS_RELU><<<grid(rows, 256), 256>>>(pfusion, 288, Wd1, 288, bd1, pd1, 256, rows, 256, 288);
    // 11. gate, delta, fused output
    final_kernel<<<rows, 32>>>(pg1, pd1, Wg2, bg2, Wd2, bd2, pattack, out);
}

// round 3
// speedup vs baseline: 1.3701x; 1.3701x over previous
#include <cuda_runtime.h>
#include <cuda_bf16.h>
#include <math.h>

// ---------------- problem constants ----------------
#define Nn   27
#define NA   33
#define OFF  6
#define ATK  27
#define HID  256
#define HEADS 4
#define HD   16
#define REL  5
#define INW  322
#define FUSE_SCALE 0.1f
#define NEG  (-10000000000.0f)
#define MAXROWS 27648

// ---------------- scratch (device globals) -------------
__device__ float g_x     [MAXROWS * 256];
__device__ float g_gi    [MAXROWS * 768];
__device__ float g_gh    [MAXROWS * 768];
__device__ float g_p     [MAXROWS * 256];
__device__ float g_logits[MAXROWS * 33];
__device__ float g_attack[MAXROWS * 27];
__device__ float g_sender[MAXROWS * 32];
__device__ float g_qk    [MAXROWS * 128];   // cols 0-63 = q, 64-127 = key_h
__device__ float g_qr    [MAXROWS * 20];
__device__ float g_qb    [MAXROWS * 4];
__device__ float g_fusion[MAXROWS * 288];
__device__ float g_gd    [MAXROWS * 512];   // cols 0-255 = g1, 256-511 = d1
__device__ float g_hfb   [MAXROWS * 256];
__device__ float g_Bqk   [128 * 256];
__device__ float g_bqk   [128];
__device__ float g_Bgd   [512 * 288];
__device__ float g_bgd   [512];

#define EPI_NONE 0
#define EPI_BIAS 1
#define EPI_BIAS_RELU 2

// ================= main 128x128 double-buffered GEMM =================
// C[M,N] = A[M,K] @ B[N,K]^T (+bias)(relu).  Requires M%128==0, N%128==0.
template<int EPI>
__global__ void __launch_bounds__(256, 2)
gemm128(const float* __restrict__ A, int lda,
        const float* __restrict__ B, int ldb,
        const float* __restrict__ bias,
        float* __restrict__ C, int ldc, int M, int N, int K)
{
    __shared__ float As[2][8][132];
    __shared__ float Bs[2][8][132];
    const int tid = threadIdx.x;
    const int m0 = blockIdx.x * 128, n0 = blockIdx.y * 128;
    const int lr = tid >> 1;            // 0..127
    const int lk = (tid & 1) * 4;       // 0 or 4

    const float* Aptr = A + (size_t)(m0 + lr) * lda + lk;
    const float* Bptr = B + (size_t)(n0 + lr) * ldb + lk;

    const int kTiles = (K + 7) / 8;
    float ra[4], rb[4];

    // preload tile 0
#pragma unroll
    for (int i = 0; i < 4; i++) {
        ra[i] = (lk + i < K) ? Aptr[i] : 0.f;
        rb[i] = (lk + i < K) ? Bptr[i] : 0.f;
    }
#pragma unroll
    for (int i = 0; i < 4; i++) { As[0][lk + i][lr] = ra[i]; Bs[0][lk + i][lr] = rb[i]; }
    __syncthreads();

    const int tx = tid & 15, ty = tid >> 4;
    float acc[8][8];
#pragma unroll
    for (int a = 0; a < 8; a++)
#pragma unroll
        for (int b = 0; b < 8; b++) acc[a][b] = 0.f;

    for (int t = 0; t < kTiles; t++) {
        const int cur = t & 1, nxt = cur ^ 1;
        const bool has_next = (t + 1 < kTiles);
        if (has_next) {
            const int gk = (t + 1) * 8 + lk;
            const float* Ap = Aptr + (t + 1) * 8;
            const float* Bp = Bptr + (t + 1) * 8;
#pragma unroll
            for (int i = 0; i < 4; i++) {
                ra[i] = (gk + i < K) ? Ap[i] : 0.f;
                rb[i] = (gk + i < K) ? Bp[i] : 0.f;
            }
        }
#pragma unroll
        for (int k = 0; k < 8; k++) {
            float av[8], bv[8];
            *(float4*)(av)     = *(const float4*)&As[cur][k][ty * 8];
            *(float4*)(av + 4) = *(const float4*)&As[cur][k][ty * 8 + 4];
            *(float4*)(bv)     = *(const float4*)&Bs[cur][k][tx * 8];
            *(float4*)(bv + 4) = *(const float4*)&Bs[cur][k][tx * 8 + 4];
#pragma unroll
            for (int a = 0; a < 8; a++)
#pragma unroll
                for (int b = 0; b < 8; b++)
                    acc[a][b] += av[a] * bv[b];
        }
        if (has_next) {
#pragma unroll
            for (int i = 0; i < 4; i++) { As[nxt][lk + i][lr] = ra[i]; Bs[nxt][lk + i][lr] = rb[i]; }
            __syncthreads();
        }
    }

    // epilogue (M,N exact multiples of tile)
    const int mb = m0 + ty * 8, nb = n0 + tx * 8;
    float bsv[8];
    if (EPI >= EPI_BIAS) {
        *(float4*)(bsv)     = *(const float4*)&bias[nb];
        *(float4*)(bsv + 4) = *(const float4*)&bias[nb + 4];
    }
#pragma unroll
    for (int a = 0; a < 8; a++) {
        float4 v0, v1;
        float* r = &acc[a][0];
        if (EPI >= EPI_BIAS) {
#pragma unroll
            for (int b = 0; b < 8; b++) {
                float v = r[b] + bsv[b];
                if (EPI == EPI_BIAS_RELU) v = fmaxf(v, 0.f);
                r[b] = v;
            }
        }
        v0 = make_float4(r[0], r[1], r[2], r[3]);
        v1 = make_float4(r[4], r[5], r[6], r[7]);
        float* cp = C + (size_t)(mb + a) * ldc + nb;
        *(float4*)cp = v0;
        *(float4*)(cp + 4) = v1;
    }
}

// ================= old generic GEMM (for N=33 only) =================
template<int EPI>
__global__ void __launch_bounds__(256)
gemm_tn(const float* __restrict__ A, int lda,
        const float* __restrict__ B, int ldb,
        const float* __restrict__ bias,
        float* __restrict__ C, int ldc,
        int M, int N, int K)
{
    constexpr int BM = 128, BN = 64, BK = 16, TM = 8, TN = 4;
    __shared__ float As[BK][BM + 4];
    __shared__ float Bs[BK][BN + 4];
    const int tid = threadIdx.x;
    const int tx = tid & 15, ty = tid >> 4;
    const int m0 = blockIdx.x * BM, n0 = blockIdx.y * BN;

    float acc[TM][TN];
#pragma unroll
    for (int a = 0; a < TM; a++)
#pragma unroll
        for (int b = 0; b < TN; b++) acc[a][b] = 0.f;

    for (int k0 = 0; k0 < K; k0 += BK) {
#pragma unroll
        for (int i = 0; i < (BM * BK) / 256; i++) {
            int idx = tid + i * 256;
            int m = idx / BK, k = idx % BK;
            int gm = m0 + m, gk = k0 + k;
            As[k][m] = (gm < M && gk < K) ? A[(size_t)gm * lda + gk] : 0.f;
        }
#pragma unroll
        for (int i = 0; i < (BN * BK) / 256; i++) {
            int idx = tid + i * 256;
            int n = idx / BK, k = idx % BK;
            int gn = n0 + n, gk = k0 + k;
            Bs[k][n] = (gn < N && gk < K) ? B[(size_t)gn * ldb + gk] : 0.f;
        }
        __syncthreads();
#pragma unroll
        for (int k = 0; k < BK; k++) {
            float a[TM], b[TN];
#pragma unroll
            for (int tm = 0; tm < TM; tm++) a[tm] = As[k][ty * TM + tm];
#pragma unroll
            for (int tn = 0; tn < TN; tn++) b[tn] = Bs[k][tx * TN + tn];
#pragma unroll
            for (int tm = 0; tm < TM; tm++)
#pragma unroll
                for (int tn = 0; tn < TN; tn++)
                    acc[tm][tn] += a[tm] * b[tn];
        }
        __syncthreads();
    }
#pragma unroll
    for (int tm = 0; tm < TM; tm++) {
        int gm = m0 + ty * TM + tm;
        if (gm >= M) continue;
#pragma unroll
        for (int tn = 0; tn < TN; tn++) {
            int gn = n0 + tx * TN + tn;
            if (gn >= N) continue;
            float v = acc[tm][tn];
            if (EPI >= EPI_BIAS) v += bias[gn];
            if (EPI == EPI_BIAS_RELU) v = fmaxf(v, 0.f);
            C[(size_t)gm * ldc + gn] = v;
        }
    }
}

// ================= weight packing =================
__global__ void pack_qk(const float* __restrict__ Wq, const float* __restrict__ bq,
                        const float* __restrict__ Wk,
                        float* __restrict__ Bp, float* __restrict__ biasp)
{
    int idx = blockIdx.x * blockDim.x + threadIdx.x;
    if (idx < 128 * 256) {
        int r = idx >> 8, c = idx & 255;
        Bp[idx] = (r < 64) ? Wq[r * 256 + c] : Wk[(size_t)(r - 64) * (HID + REL) + c];
    }
    if (idx < 128) biasp[idx] = (idx < 64) ? bq[idx] : 0.f;
}

__global__ void pack_gd(const float* __restrict__ Wg1, const float* __restrict__ bg1,
                        const float* __restrict__ Wd1, const float* __restrict__ bd1,
                        float* __restrict__ Bp, float* __restrict__ biasp)
{
    int idx = blockIdx.x * blockDim.x + threadIdx.x;
    if (idx < 512 * 288) {
        int r = idx / 288, c = idx % 288;
        Bp[idx] = (r < 256) ? Wg1[r * 288 + c] : Wd1[(r - 256) * 288 + c];
    }
    if (idx < 512) biasp[idx] = (idx < 256) ? bg1[idx] : bd1[idx - 256];
}

// ================= GRU (writes h and fusion[:,0:256]) =================
__global__ void gru_kernel(const float* __restrict__ gi, const float* __restrict__ gh,
                           const float* __restrict__ hin, float* __restrict__ hout,
                           float* __restrict__ fusion, int total)
{
    int idx = blockIdx.x * blockDim.x + threadIdx.x;
    if (idx >= total) return;
    int r = idx >> 8, c = idx & 255;
    size_t base = (size_t)r * 768;
    float ir = gi[base + c], iz = gi[base + 256 + c], in_ = gi[base + 512 + c];
    float hr = gh[base + c], hz = gh[base + 256 + c], hn = gh[base + 512 + c];
    float rg = 1.f / (1.f + expf(-(ir + hr)));
    float zg = 1.f / (1.f + expf(-(iz + hz)));
    float ng = tanhf(in_ + rg * hn);
    float v = (1.f - zg) * ng + zg * hin[idx];
    hout[idx] = v;
    fusion[(size_t)r * 288 + c] = v;
}

// ================= logits post: softmax + sender values =================
__global__ void __launch_bounds__(256)
logits_post(const float* __restrict__ logits, const float* __restrict__ Wv,
            const float* __restrict__ bv,
            float* __restrict__ out, float* __restrict__ attack,
            float* __restrict__ sender)
{
    __shared__ float Wvs[32 * 29];
    __shared__ float bvs[32];
    __shared__ float vs[8][29];
    int tid = threadIdx.x;
    for (int t = tid; t < 32 * 29; t += 256) Wvs[t] = Wv[t];
    if (tid < 32) bvs[tid] = bv[tid];
    int w = tid >> 5, l = tid & 31;
    int row = blockIdx.x * 8 + w;
    const float* lrow = logits + (size_t)row * 33;
    float al = (l < 27) ? lrow[6 + l] : -INFINITY;
    float mx = al;
#pragma unroll
    for (int o = 16; o > 0; o >>= 1) mx = fmaxf(mx, __shfl_xor_sync(0xffffffffu, mx, o));
    float e = (l < 27) ? expf(al - mx) : 0.f;
    float sum = e;
#pragma unroll
    for (int o = 16; o > 0; o >>= 1) sum += __shfl_xor_sync(0xffffffffu, sum, o);
    float inv = 1.f / sum;
    if (l < 27) vs[w][l] = e * inv;
    if (l == 27) vs[w][27] = 1.0f;
    if (l == 28) vs[w][28] = inv;   // top1 = max softmax = 1/sum
    if (l < 27) attack[(size_t)row * 27 + l] = al;
    if (l < 6)  out[(size_t)row * 33 + l] = lrow[l];
    __syncthreads();
    float s = bvs[l];
#pragma unroll
    for (int r = 0; r < 29; r++) s += vs[w][r] * Wvs[l * 29 + r];
    sender[(size_t)row * 32 + l] = s;
}

// ================= qr / qb precompute =================
__global__ void qr_kernel(const float* __restrict__ qk, const float* __restrict__ Wk,
                          const float* __restrict__ bk,
                          float* __restrict__ qr, float* __restrict__ qb, int rows)
{
    int idx = blockIdx.x * blockDim.x + threadIdx.x;
    if (idx >= rows * 4) return;
    int row = idx >> 2, h = idx & 3;
    const float* qp = qk + (size_t)row * 128 + h * 16;
    float acc[5] = {0.f, 0.f, 0.f, 0.f, 0.f};
    float accb = 0.f;
#pragma unroll
    for (int d = 0; d < 16; d++) {
        float qd = qp[d];
        const float* wrow = Wk + (size_t)(h * 16 + d) * (HID + REL) + HID;
#pragma unroll
        for (int r = 0; r < 5; r++) acc[r] += qd * wrow[r];
        accb += qd * bk[h * 16 + d];
    }
#pragma unroll
    for (int r = 0; r < 5; r++) qr[(size_t)row * 20 + h * 5 + r] = acc[r];
    qb[(size_t)row * 4 + h] = accb;
}

// ================= batched attention + topk + softmax + messages + LN =================
// one block per batch element b, 256 threads
__global__ void __launch_bounds__(256)
attn_batch(const float* __restrict__ qk,     // [rows,128]
           const float* __restrict__ qr,     // [rows,20]
           const float* __restrict__ qb,     // [rows,4]
           const float* __restrict__ rel,    // [bs,27,27,5]
           const float* __restrict__ sender, // [rows,32]
           const float* __restrict__ nullk, const float* __restrict__ nullv,
           const float* __restrict__ ln_g, const float* __restrict__ ln_b,
           float* __restrict__ fusion)       // [rows,288], writes cols 256..287
{
    __shared__ float qk_s[27 * 128];
    __shared__ float sender_s[27 * 32];
    __shared__ float rel_s[27 * 27 * 5];
    __shared__ float qr_s[27 * 20];
    __shared__ float qb_s[27 * 4];
    __shared__ float nk_s[64];
    __shared__ float nv_s[32];
    __shared__ float sc[27 * 112];

    const int b = blockIdx.x;
    const int tid = threadIdx.x;
    const size_t rbase = (size_t)b * 27;

    for (int t = tid; t < 27 * 128; t += 256) qk_s[t] = qk[rbase * 128 + t];
    for (int t = tid; t < 27 * 32; t += 256) sender_s[t] = sender[rbase * 32 + t];
    for (int t = tid; t < 27 * 27 * 5; t += 256) rel_s[t] = rel[(size_t)b * (27 * 27 * 5) + t];
    for (int t = tid; t < 27 * 20; t += 256) qr_s[t] = qr[rbase * 20 + t];
    for (int t = tid; t < 27 * 4; t += 256) qb_s[t] = qb[rbase * 4 + t];
    if (tid < 64) nk_s[tid] = nullk[tid];
    if (tid >= 64 && tid < 96) nv_s[tid - 64] = nullv[tid - 64];
    __syncthreads();

    // scores: t = i*112 + j*4 + h, j in [0,28)
    for (int t = tid; t < 27 * 112; t += 256) {
        int i = t / 112;
        int rem = t - i * 112;
        int j = rem >> 2, h = rem & 3;
        float s;
        if (j == 27) {
            float d = 0.f;
#pragma unroll
            for (int dd = 0; dd < 16; dd++) d += qk_s[i * 128 + h * 16 + dd] * nk_s[h * 16 + dd];
            s = 0.25f * d;
        } else if (j == i) {
            s = NEG;
        } else {
            float d = qb_s[i * 4 + h];
#pragma unroll
            for (int dd = 0; dd < 16; dd++)
                d += qk_s[i * 128 + h * 16 + dd] * qk_s[j * 128 + 64 + h * 16 + dd];
            const float* rr = &rel_s[(i * 27 + j) * 5];
#pragma unroll
            for (int r = 0; r < 5; r++) d += qr_s[i * 20 + h * 5 + r] * rr[r];
            s = 0.25f * d;
        }
        sc[t] = s;
    }
    __syncthreads();

    // topk(4) + softmax per (i,h)
    for (int t = tid; t < 108; t += 256) {
        int i = t >> 2, h = t & 3;
        float* scp = &sc[i * 112 + h];
        float t0 = -INFINITY, t1 = -INFINITY, t2 = -INFINITY, t3 = -INFINITY;
#pragma unroll
        for (int j = 0; j < 28; j++) {
            float v = scp[j * 4];
            if (v > t0)      { t3 = t2; t2 = t1; t1 = t0; t0 = v; }
            else if (v > t1) { t3 = t2; t2 = t1; t1 = v; }
            else if (v > t2) { t3 = t2; t2 = v; }
            else if (v > t3) { t3 = v; }
        }
        float thr = t3, mxv = t0, sum = 0.f;
        float e[28];
#pragma unroll
        for (int j = 0; j < 28; j++) {
            float v = scp[j * 4];
            float ev = (v >= thr) ? expf(v - mxv) : 0.f;
            e[j] = ev; sum += ev;
        }
        float inv = 1.f / sum;
#pragma unroll
        for (int j = 0; j < 28; j++) scp[j * 4] = e[j] * inv;
    }
    __syncthreads();

    // messages + layernorm: warp w handles rows i = w, w+8, ...
    int w = tid >> 5, l = tid & 31;
    int h = l >> 3, v = l & 7;
    for (int i = w; i < 27; i += 8) {
        const float* scp = &sc[i * 112];
        float m = scp[108 + h] * nv_s[l];
#pragma unroll
        for (int j = 0; j < 27; j++) m += scp[j * 4 + h] * sender_s[j * 32 + l];
        float s = m, s2 = m * m;
#pragma unroll
        for (int o = 16; o > 0; o >>= 1) {
            s  += __shfl_xor_sync(0xffffffffu, s, o);
            s2 += __shfl_xor_sync(0xffffffffu, s2, o);
        }
        float mu = s * (1.f / 32.f);
        float var = s2 * (1.f / 32.f) - mu * mu;
        float nm = (m - mu) * rsqrtf(var + 1e-5f) * ln_g[l] + ln_b[l];
        fusion[(rbase + i) * 288 + 256 + l] = nm;
    }
}

// ================= final: gate, delta, fused output =================
__global__ void __launch_bounds__(256)
final_kernel(const float* __restrict__ gd,   // [rows,512]
             const float* __restrict__ Wg2, const float* __restrict__ bg2,
             const float* __restrict__ Wd2, const float* __restrict__ bd2,
             const float* __restrict__ attack,
             float* __restrict__ out)
{
    __shared__ float Wd2s[256 * 28];   // transposed [k][l]
    __shared__ float wg2s[256];
    int tid = threadIdx.x;
    for (int t = tid; t < 27 * 256; t += 256) {
        int l = t >> 8, k = t & 255;
        Wd2s[k * 28 + l] = Wd2[t];
    }
    if (tid < 256) wg2s[tid] = Wg2[tid];
    __syncthreads();

    int w = tid >> 5, l = tid & 31;
    int row = blockIdx.x * 8 + w;
    const float* g1r = gd + (size_t)row * 512;
    const float* d1r = g1r + 256;
    float gs = 0.f;
#pragma unroll
    for (int i = 0; i < 8; i++) gs += g1r[l + i * 32] * wg2s[l + i * 32];
#pragma unroll
    for (int o = 16; o > 0; o >>= 1) gs += __shfl_xor_sync(0xffffffffu, gs, o);
    float gate = 1.f / (1.f + expf(-(gs + bg2[0])));
    if (l < 27) {
        float d = bd2[l];
#pragma unroll 8
        for (int k = 0; k < 256; k++) d += d1r[k] * Wd2s[k * 28 + l];
        out[(size_t)row * 33 + 6 + l] = attack[(size_t)row * 27 + l] + FUSE_SCALE * gate * d;
    }
}

// ================= host launcher =================
static float* sym(const void* symbol)
{
    void* p = nullptr;
    cudaGetSymbolAddress(&p, symbol);
    return (float*)p;
}

extern "C" void kernel_launch(void* const* d_in, const int* in_sizes, int n_in,
                              void* d_out, int out_size)
{
    const float* inputs = (const float*)d_in[0];
    const float* hidden = (const float*)d_in[1];
    const float* rel    = (const float*)d_in[2];
    const float* W1     = (const float*)d_in[3];
    const float* b1     = (const float*)d_in[4];
    const float* Wih    = (const float*)d_in[5];
    const float* bih    = (const float*)d_in[6];
    const float* Whh    = (const float*)d_in[7];
    const float* bhh    = (const float*)d_in[8];
    const float* Wp1    = (const float*)d_in[9];
    const float* bp1    = (const float*)d_in[10];
    const float* Wp2    = (const float*)d_in[11];
    const float* bp2    = (const float*)d_in[12];
    const float* Wq     = (const float*)d_in[13];
    const float* bq     = (const float*)d_in[14];
    const float* Wk     = (const float*)d_in[15];
    const float* bk     = (const float*)d_in[16];
    const float* Wv     = (const float*)d_in[17];
    const float* bv     = (const float*)d_in[18];
    const float* ln_g   = (const float*)d_in[19];
    const float* ln_b   = (const float*)d_in[20];
    const float* Wg1    = (const float*)d_in[21];
    const float* bg1    = (const float*)d_in[22];
    const float* Wg2    = (const float*)d_in[23];
    const float* bg2    = (const float*)d_in[24];
    const float* Wd1    = (const float*)d_in[25];
    const float* bd1    = (const float*)d_in[26];
    const float* Wd2    = (const float*)d_in[27];
    const float* bd2    = (const float*)d_in[28];
    const float* nullk  = (const float*)d_in[29];
    const float* nullv  = (const float*)d_in[30];

    const int rows = in_sizes[0] / INW;    // 27648
    const int bs = rows / Nn;              // 1024
    float* out = (float*)d_out;

    float* px      = sym(g_x);
    float* pgi     = sym(g_gi);
    float* pgh     = sym(g_gh);
    float* pp      = sym(g_p);
    float* plogits = sym(g_logits);
    float* pattack = sym(g_attack);
    float* psender = sym(g_sender);
    float* pqk     = sym(g_qk);
    float* pqr     = sym(g_qr);
    float* pqb     = sym(g_qb);
    float* pfusion = sym(g_fusion);
    float* pgd     = sym(g_gd);
    float* pBqk    = sym(g_Bqk);
    float* pbqk    = sym(g_bqk);
    float* pBgd    = sym(g_Bgd);
    float* pbgd    = sym(g_bgd);

    float* hout = (out_size >= rows * (NA + HID)) ? out + (size_t)rows * NA : sym(g_hfb);

    const int MB = rows / 128;   // 216

    // weight packing (tiny)
    pack_qk<<<(128 * 256 + 255) / 256, 256>>>(Wq, bq, Wk, pBqk, pbqk);
    pack_gd<<<(512 * 288 + 255) / 256, 256>>>(Wg1, bg1, Wd1, bd1, pBgd, pbgd);

    // 1. x = relu(inputs @ W1^T + b1)
    gemm128<EPI_BIAS_RELU><<<dim3(MB, 2), 256>>>(inputs, INW, W1, INW, b1, px, 256, rows, 256, INW);
    // 2. gi, gh
    gemm128<EPI_BIAS><<<dim3(MB, 6), 256>>>(px, 256, Wih, 256, bih, pgi, 768, rows, 768, 256);
    gemm128<EPI_BIAS><<<dim3(MB, 6), 256>>>(hidden, 256, Whh, 256, bhh, pgh, 768, rows, 768, 256);
    // 3. GRU -> h (+ fusion cols 0-255)
    gru_kernel<<<(rows * 256 + 255) / 256, 256>>>(pgi, pgh, hidden, hout, pfusion, rows * 256);
    // 4. p = relu(h @ Wp1^T + bp1); logits = p @ Wp2^T + bp2
    gemm128<EPI_BIAS_RELU><<<dim3(MB, 2), 256>>>(hout, 256, Wp1, 256, bp1, pp, 256, rows, 256, 256);
    gemm_tn<EPI_BIAS><<<dim3(MB, 1), 256>>>(pp, 256, Wp2, 256, bp2, plogits, NA, rows, NA, 256);
    // 5. softmax / sender values / base logits
    logits_post<<<rows / 8, 256>>>(plogits, Wv, bv, out, pattack, psender);
    // 6. [q | key_h] = h @ [Wq; Wk_h]^T (+ [bq; 0])
    gemm128<EPI_BIAS><<<dim3(MB, 1), 256>>>(hout, 256, pBqk, 256, pbqk, pqk, 128, rows, 128, 256);
    // 7. qr, qb
    qr_kernel<<<(rows * 4 + 127) / 128, 128>>>(pqk, Wk, bk, pqr, pqb, rows);
    // 8. attention (batched) -> fusion cols 256-287
    attn_batch<<<bs, 256>>>(pqk, pqr, pqb, rel, psender, nullk, nullv, ln_g, ln_b, pfusion);
    // 9. [g1 | d1] = relu(fusion @ [Wg1; Wd1]^T + [bg1; bd1])
    gemm128<EPI_BIAS_RELU><<<dim3(MB, 4), 256>>>(pfusion, 288, pBgd, 288, pbgd, pgd, 512, rows, 512, 288);
    // 10. gate, delta, fused output
    final_kernel<<<rows / 8, 256>>>(pgd, Wg2, bg2, Wd2, bd2, pattack, out);
}

// round 4
// speedup vs baseline: 1.5596x; 1.1383x over previous
#include <cuda_runtime.h>
#include <cuda_bf16.h>
#include <math.h>

// ---------------- problem constants ----------------
#define Nn   27
#define NA   33
#define OFF  6
#define ATK  27
#define HID  256
#define HEADS 4
#define HD   16
#define REL  5
#define INW  322
#define FUSE_SCALE 0.1f
#define NEG  (-10000000000.0f)
#define MAXROWS 27648

// ---------------- scratch (device globals) -------------
__device__ float g_x     [MAXROWS * 256];
__device__ float g_gi    [MAXROWS * 768];
__device__ float g_gh    [MAXROWS * 768];
__device__ float g_p     [MAXROWS * 256];
__device__ float g_logits[MAXROWS * 33];
__device__ float g_attack[MAXROWS * 27];
__device__ float g_sender[MAXROWS * 32];
__device__ float g_qk    [MAXROWS * 128];
__device__ float g_qr    [MAXROWS * 20];
__device__ float g_qb    [MAXROWS * 4];
__device__ float g_fusion[MAXROWS * 288];
__device__ float g_gd    [MAXROWS * 512];
__device__ float g_hfb   [MAXROWS * 256];
__device__ float g_Bqk   [128 * 256];
__device__ float g_bqk   [128];
__device__ float g_Bgd   [512 * 288];
__device__ float g_bgd   [512];

#define EPI_NONE 0
#define EPI_BIAS 1
#define EPI_BIAS_RELU 2

// ================= 128x128 double-buffered GEMM, conflict-free warp tiling ========
// C[M,N] = A[M,K] @ B[N,K]^T (+bias)(relu).  Requires M%128==0, N%128==0.
// 8 warps as 2(m) x 4(n); warp tile 64x32; lanes 8(m) x 4(n); thread tile 8x8.
template<int EPI>
__global__ void __launch_bounds__(256, 2)
gemm128(const float* __restrict__ A, int lda,
        const float* __restrict__ B, int ldb,
        const float* __restrict__ bias,
        float* __restrict__ C, int ldc, int M, int N, int K)
{
    __shared__ float As[2][8][132];
    __shared__ float Bs[2][8][132];
    const int tid = threadIdx.x;
    const int m0 = blockIdx.x * 128, n0 = blockIdx.y * 128;
    const int lr = tid >> 1;            // 0..127
    const int lk = (tid & 1) * 4;       // 0 or 4

    const float* Aptr = A + (size_t)(m0 + lr) * lda + lk;
    const float* Bptr = B + (size_t)(n0 + lr) * ldb + lk;

    const int kTiles = (K + 7) / 8;
    float ra[4], rb[4];

#pragma unroll
    for (int i = 0; i < 4; i++) {
        ra[i] = (lk + i < K) ? Aptr[i] : 0.f;
        rb[i] = (lk + i < K) ? Bptr[i] : 0.f;
    }
#pragma unroll
    for (int i = 0; i < 4; i++) { As[0][lk + i][lr] = ra[i]; Bs[0][lk + i][lr] = rb[i]; }
    __syncthreads();

    const int wid  = tid >> 5, lane = tid & 31;
    const int wm = (wid & 1) * 64 + (lane >> 2) * 8;   // m offset of thread's 8 rows
    const int wn = (wid >> 1) * 32 + (lane & 3) * 8;   // n offset of thread's 8 cols

    float acc[8][8];
#pragma unroll
    for (int a = 0; a < 8; a++)
#pragma unroll
        for (int b = 0; b < 8; b++) acc[a][b] = 0.f;

    for (int t = 0; t < kTiles; t++) {
        const int cur = t & 1, nxt = cur ^ 1;
        const bool has_next = (t + 1 < kTiles);
        if (has_next) {
            const int gk = (t + 1) * 8 + lk;
            const float* Ap = Aptr + (t + 1) * 8;
            const float* Bp = Bptr + (t + 1) * 8;
#pragma unroll
            for (int i = 0; i < 4; i++) {
                ra[i] = (gk + i < K) ? Ap[i] : 0.f;
                rb[i] = (gk + i < K) ? Bp[i] : 0.f;
            }
        }
#pragma unroll
        for (int k = 0; k < 8; k++) {
            float av[8], bv[8];
            *(float4*)(av)     = *(const float4*)&As[cur][k][wm];
            *(float4*)(av + 4) = *(const float4*)&As[cur][k][wm + 4];
            *(float4*)(bv)     = *(const float4*)&Bs[cur][k][wn];
            *(float4*)(bv + 4) = *(const float4*)&Bs[cur][k][wn + 4];
#pragma unroll
            for (int a = 0; a < 8; a++)
#pragma unroll
                for (int b = 0; b < 8; b++)
                    acc[a][b] += av[a] * bv[b];
        }
        if (has_next) {
#pragma unroll
            for (int i = 0; i < 4; i++) { As[nxt][lk + i][lr] = ra[i]; Bs[nxt][lk + i][lr] = rb[i]; }
            __syncthreads();
        }
    }

    const int mb = m0 + wm, nb = n0 + wn;
    float bsv[8];
    if (EPI >= EPI_BIAS) {
        *(float4*)(bsv)     = *(const float4*)&bias[nb];
        *(float4*)(bsv + 4) = *(const float4*)&bias[nb + 4];
    }
#pragma unroll
    for (int a = 0; a < 8; a++) {
        float* r = &acc[a][0];
        if (EPI >= EPI_BIAS) {
#pragma unroll
            for (int b = 0; b < 8; b++) {
                float v = r[b] + bsv[b];
                if (EPI == EPI_BIAS_RELU) v = fmaxf(v, 0.f);
                r[b] = v;
            }
        }
        float* cp = C + (size_t)(mb + a) * ldc + nb;
        *(float4*)cp = make_float4(r[0], r[1], r[2], r[3]);
        *(float4*)(cp + 4) = make_float4(r[4], r[5], r[6], r[7]);
    }
}

// ================= generic GEMM (for N=33 only) =================
template<int EPI>
__global__ void __launch_bounds__(256)
gemm_tn(const float* __restrict__ A, int lda,
        const float* __restrict__ B, int ldb,
        const float* __restrict__ bias,
        float* __restrict__ C, int ldc,
        int M, int N, int K)
{
    constexpr int BM = 128, BN = 64, BK = 16, TM = 8, TN = 4;
    __shared__ float As[BK][BM + 4];
    __shared__ float Bs[BK][BN + 4];
    const int tid = threadIdx.x;
    const int tx = tid & 15, ty = tid >> 4;
    const int m0 = blockIdx.x * BM, n0 = blockIdx.y * BN;

    float acc[TM][TN];
#pragma unroll
    for (int a = 0; a < TM; a++)
#pragma unroll
        for (int b = 0; b < TN; b++) acc[a][b] = 0.f;

    for (int k0 = 0; k0 < K; k0 += BK) {
#pragma unroll
        for (int i = 0; i < (BM * BK) / 256; i++) {
            int idx = tid + i * 256;
            int m = idx / BK, k = idx % BK;
            int gm = m0 + m, gk = k0 + k;
            As[k][m] = (gm < M && gk < K) ? A[(size_t)gm * lda + gk] : 0.f;
        }
#pragma unroll
        for (int i = 0; i < (BN * BK) / 256; i++) {
            int idx = tid + i * 256;
            int n = idx / BK, k = idx % BK;
            int gn = n0 + n, gk = k0 + k;
            Bs[k][n] = (gn < N && gk < K) ? B[(size_t)gn * ldb + gk] : 0.f;
        }
        __syncthreads();
#pragma unroll
        for (int k = 0; k < BK; k++) {
            float a[TM], b[TN];
#pragma unroll
            for (int tm = 0; tm < TM; tm++) a[tm] = As[k][ty * TM + tm];
#pragma unroll
            for (int tn = 0; tn < TN; tn++) b[tn] = Bs[k][tx * TN + tn];
#pragma unroll
            for (int tm = 0; tm < TM; tm++)
#pragma unroll
                for (int tn = 0; tn < TN; tn++)
                    acc[tm][tn] += a[tm] * b[tn];
        }
        __syncthreads();
    }
#pragma unroll
    for (int tm = 0; tm < TM; tm++) {
        int gm = m0 + ty * TM + tm;
        if (gm >= M) continue;
#pragma unroll
        for (int tn = 0; tn < TN; tn++) {
            int gn = n0 + tx * TN + tn;
            if (gn >= N) continue;
            float v = acc[tm][tn];
            if (EPI >= EPI_BIAS) v += bias[gn];
            if (EPI == EPI_BIAS_RELU) v = fmaxf(v, 0.f);
            C[(size_t)gm * ldc + gn] = v;
        }
    }
}

// ================= weight packing =================
__global__ void pack_qk(const float* __restrict__ Wq, const float* __restrict__ bq,
                        const float* __restrict__ Wk,
                        float* __restrict__ Bp, float* __restrict__ biasp)
{
    int idx = blockIdx.x * blockDim.x + threadIdx.x;
    if (idx < 128 * 256) {
        int r = idx >> 8, c = idx & 255;
        Bp[idx] = (r < 64) ? Wq[r * 256 + c] : Wk[(size_t)(r - 64) * (HID + REL) + c];
    }
    if (idx < 128) biasp[idx] = (idx < 64) ? bq[idx] : 0.f;
}

__global__ void pack_gd(const float* __restrict__ Wg1, const float* __restrict__ bg1,
                        const float* __restrict__ Wd1, const float* __restrict__ bd1,
                        float* __restrict__ Bp, float* __restrict__ biasp)
{
    int idx = blockIdx.x * blockDim.x + threadIdx.x;
    if (idx < 512 * 288) {
        int r = idx / 288, c = idx % 288;
        Bp[idx] = (r < 256) ? Wg1[r * 288 + c] : Wd1[(r - 256) * 288 + c];
    }
    if (idx < 512) biasp[idx] = (idx < 256) ? bg1[idx] : bd1[idx - 256];
}

// ================= GRU (writes h and fusion[:,0:256]) =================
__global__ void gru_kernel(const float* __restrict__ gi, const float* __restrict__ gh,
                           const float* __restrict__ hin, float* __restrict__ hout,
                           float* __restrict__ fusion, int total)
{
    int idx = blockIdx.x * blockDim.x + threadIdx.x;
    if (idx >= total) return;
    int r = idx >> 8, c = idx & 255;
    size_t base = (size_t)r * 768;
    float ir = gi[base + c], iz = gi[base + 256 + c], in_ = gi[base + 512 + c];
    float hr = gh[base + c], hz = gh[base + 256 + c], hn = gh[base + 512 + c];
    float rg = 1.f / (1.f + expf(-(ir + hr)));
    float zg = 1.f / (1.f + expf(-(iz + hz)));
    float ng = tanhf(in_ + rg * hn);
    float v = (1.f - zg) * ng + zg * hin[idx];
    hout[idx] = v;
    fusion[(size_t)r * 288 + c] = v;
}

// ================= logits post =================
__global__ void __launch_bounds__(256)
logits_post(const float* __restrict__ logits, const float* __restrict__ Wv,
            const float* __restrict__ bv,
            float* __restrict__ out, float* __restrict__ attack,
            float* __restrict__ sender)
{
    __shared__ float Wvs[32 * 29];
    __shared__ float bvs[32];
    __shared__ float vs[8][29];
    int tid = threadIdx.x;
    for (int t = tid; t < 32 * 29; t += 256) Wvs[t] = Wv[t];
    if (tid < 32) bvs[tid] = bv[tid];
    int w = tid >> 5, l = tid & 31;
    int row = blockIdx.x * 8 + w;
    const float* lrow = logits + (size_t)row * 33;
    float al = (l < 27) ? lrow[6 + l] : -INFINITY;
    float mx = al;
#pragma unroll
    for (int o = 16; o > 0; o >>= 1) mx = fmaxf(mx, __shfl_xor_sync(0xffffffffu, mx, o));
    float e = (l < 27) ? expf(al - mx) : 0.f;
    float sum = e;
#pragma unroll
    for (int o = 16; o > 0; o >>= 1) sum += __shfl_xor_sync(0xffffffffu, sum, o);
    float inv = 1.f / sum;
    if (l < 27) vs[w][l] = e * inv;
    if (l == 27) vs[w][27] = 1.0f;
    if (l == 28) vs[w][28] = inv;
    if (l < 27) attack[(size_t)row * 27 + l] = al;
    if (l < 6)  out[(size_t)row * 33 + l] = lrow[l];
    __syncthreads();
    float s = bvs[l];
#pragma unroll
    for (int r = 0; r < 29; r++) s += vs[w][r] * Wvs[l * 29 + r];
    sender[(size_t)row * 32 + l] = s;
}

// ================= qr / qb precompute =================
__global__ void qr_kernel(const float* __restrict__ qk, const float* __restrict__ Wk,
                          const float* __restrict__ bk,
                          float* __restrict__ qr, float* __restrict__ qb, int rows)
{
    int idx = blockIdx.x * blockDim.x + threadIdx.x;
    if (idx >= rows * 4) return;
    int row = idx >> 2, h = idx & 3;
    const float* qp = qk + (size_t)row * 128 + h * 16;
    float acc[5] = {0.f, 0.f, 0.f, 0.f, 0.f};
    float accb = 0.f;
#pragma unroll
    for (int d = 0; d < 16; d++) {
        float qd = qp[d];
        const float* wrow = Wk + (size_t)(h * 16 + d) * (HID + REL) + HID;
#pragma unroll
        for (int r = 0; r < 5; r++) acc[r] += qd * wrow[r];
        accb += qd * bk[h * 16 + d];
    }
#pragma unroll
    for (int r = 0; r < 5; r++) qr[(size_t)row * 20 + h * 5 + r] = acc[r];
    qb[(size_t)row * 4 + h] = accb;
}

// ================= batched attention =================
__global__ void __launch_bounds__(256)
attn_batch(const float* __restrict__ qk, const float* __restrict__ qr,
           const float* __restrict__ qb, const float* __restrict__ rel,
           const float* __restrict__ sender,
           const float* __restrict__ nullk, const float* __restrict__ nullv,
           const float* __restrict__ ln_g, const float* __restrict__ ln_b,
           float* __restrict__ fusion)
{
    __shared__ float qk_s[27 * 128];
    __shared__ float sender_s[27 * 32];
    __shared__ float rel_s[27 * 27 * 5];
    __shared__ float qr_s[27 * 20];
    __shared__ float qb_s[27 * 4];
    __shared__ float nk_s[64];
    __shared__ float nv_s[32];
    __shared__ float sc[27 * 112];

    const int b = blockIdx.x;
    const int tid = threadIdx.x;
    const size_t rbase = (size_t)b * 27;

    for (int t = tid; t < 27 * 128; t += 256) qk_s[t] = qk[rbase * 128 + t];
    for (int t = tid; t < 27 * 32; t += 256) sender_s[t] = sender[rbase * 32 + t];
    for (int t = tid; t < 27 * 27 * 5; t += 256) rel_s[t] = rel[(size_t)b * (27 * 27 * 5) + t];
    for (int t = tid; t < 27 * 20; t += 256) qr_s[t] = qr[rbase * 20 + t];
    for (int t = tid; t < 27 * 4; t += 256) qb_s[t] = qb[rbase * 4 + t];
    if (tid < 64) nk_s[tid] = nullk[tid];
    if (tid >= 64 && tid < 96) nv_s[tid - 64] = nullv[tid - 64];
    __syncthreads();

    for (int t = tid; t < 27 * 112; t += 256) {
        int i = t / 112;
        int rem = t - i * 112;
        int j = rem >> 2, h = rem & 3;
        float s;
        if (j == 27) {
            float d = 0.f;
#pragma unroll
            for (int dd = 0; dd < 16; dd++) d += qk_s[i * 128 + h * 16 + dd] * nk_s[h * 16 + dd];
            s = 0.25f * d;
        } else if (j == i) {
            s = NEG;
        } else {
            float d = qb_s[i * 4 + h];
#pragma unroll
            for (int dd = 0; dd < 16; dd++)
                d += qk_s[i * 128 + h * 16 + dd] * qk_s[j * 128 + 64 + h * 16 + dd];
            const float* rr = &rel_s[(i * 27 + j) * 5];
#pragma unroll
            for (int r = 0; r < 5; r++) d += qr_s[i * 20 + h * 5 + r] * rr[r];
            s = 0.25f * d;
        }
        sc[t] = s;
    }
    __syncthreads();

    for (int t = tid; t < 108; t += 256) {
        int i = t >> 2, h = t & 3;
        float* scp = &sc[i * 112 + h];
        float t0 = -INFINITY, t1 = -INFINITY, t2 = -INFINITY, t3 = -INFINITY;
#pragma unroll
        for (int j = 0; j < 28; j++) {
            float v = scp[j * 4];
            if (v > t0)      { t3 = t2; t2 = t1; t1 = t0; t0 = v; }
            else if (v > t1) { t3 = t2; t2 = t1; t1 = v; }
            else if (v > t2) { t3 = t2; t2 = v; }
            else if (v > t3) { t3 = v; }
        }
        float thr = t3, mxv = t0, sum = 0.f;
        float e[28];
#pragma unroll
        for (int j = 0; j < 28; j++) {
            float v = scp[j * 4];
            float ev = (v >= thr) ? expf(v - mxv) : 0.f;
            e[j] = ev; sum += ev;
        }
        float inv = 1.f / sum;
#pragma unroll
        for (int j = 0; j < 28; j++) scp[j * 4] = e[j] * inv;
    }
    __syncthreads();

    int w = tid >> 5, l = tid & 31;
    int h = l >> 3;
    for (int i = w; i < 27; i += 8) {
        const float* scp = &sc[i * 112];
        float m = scp[108 + h] * nv_s[l];
#pragma unroll
        for (int j = 0; j < 27; j++) m += scp[j * 4 + h] * sender_s[j * 32 + l];
        float s = m, s2 = m * m;
#pragma unroll
        for (int o = 16; o > 0; o >>= 1) {
            s  += __shfl_xor_sync(0xffffffffu, s, o);
            s2 += __shfl_xor_sync(0xffffffffu, s2, o);
        }
        float mu = s * (1.f / 32.f);
        float var = s2 * (1.f / 32.f) - mu * mu;
        float nm = (m - mu) * rsqrtf(var + 1e-5f) * ln_g[l] + ln_b[l];
        fusion[(rbase + i) * 288 + 256 + l] = nm;
    }
}

// ================= final =================
__global__ void __launch_bounds__(256)
final_kernel(const float* __restrict__ gd,
             const float* __restrict__ Wg2, const float* __restrict__ bg2,
             const float* __restrict__ Wd2, const float* __restrict__ bd2,
             const float* __restrict__ attack,
             float* __restrict__ out)
{
    __shared__ float Wd2s[256 * 28];
    __shared__ float wg2s[256];
    int tid = threadIdx.x;
    for (int t = tid; t < 27 * 256; t += 256) {
        int l = t >> 8, k = t & 255;
        Wd2s[k * 28 + l] = Wd2[t];
    }
    if (tid < 256) wg2s[tid] = Wg2[tid];
    __syncthreads();

    int w = tid >> 5, l = tid & 31;
    int row = blockIdx.x * 8 + w;
    const float* g1r = gd + (size_t)row * 512;
    const float* d1r = g1r + 256;
    float gs = 0.f;
#pragma unroll
    for (int i = 0; i < 8; i++) gs += g1r[l + i * 32] * wg2s[l + i * 32];
#pragma unroll
    for (int o = 16; o > 0; o >>= 1) gs += __shfl_xor_sync(0xffffffffu, gs, o);
    float gate = 1.f / (1.f + expf(-(gs + bg2[0])));
    if (l < 27) {
        float d = bd2[l];
#pragma unroll 8
        for (int k = 0; k < 256; k++) d += d1r[k] * Wd2s[k * 28 + l];
        out[(size_t)row * 33 + 6 + l] = attack[(size_t)row * 27 + l] + FUSE_SCALE * gate * d;
    }
}

// ================= host launcher =================
static float* sym(const void* symbol)
{
    void* p = nullptr;
    cudaGetSymbolAddress(&p, symbol);
    return (float*)p;
}

extern "C" void kernel_launch(void* const* d_in, const int* in_sizes, int n_in,
                              void* d_out, int out_size)
{
    const float* inputs = (const float*)d_in[0];
    const float* hidden = (const float*)d_in[1];
    const float* rel    = (const float*)d_in[2];
    const float* W1     = (const float*)d_in[3];
    const float* b1     = (const float*)d_in[4];
    const float* Wih    = (const float*)d_in[5];
    const float* bih    = (const float*)d_in[6];
    const float* Whh    = (const float*)d_in[7];
    const float* bhh    = (const float*)d_in[8];
    const float* Wp1    = (const float*)d_in[9];
    const float* bp1    = (const float*)d_in[10];
    const float* Wp2    = (const float*)d_in[11];
    const float* bp2    = (const float*)d_in[12];
    const float* Wq     = (const float*)d_in[13];
    const float* bq     = (const float*)d_in[14];
    const float* Wk     = (const float*)d_in[15];
    const float* bk     = (const float*)d_in[16];
    const float* Wv     = (const float*)d_in[17];
    const float* bv     = (const float*)d_in[18];
    const float* ln_g   = (const float*)d_in[19];
    const float* ln_b   = (const float*)d_in[20];
    const float* Wg1    = (const float*)d_in[21];
    const float* bg1    = (const float*)d_in[22];
    const float* Wg2    = (const float*)d_in[23];
    const float* bg2    = (const float*)d_in[24];
    const float* Wd1    = (const float*)d_in[25];
    const float* bd1    = (const float*)d_in[26];
    const float* Wd2    = (const float*)d_in[27];
    const float* bd2    = (const float*)d_in[28];
    const float* nullk  = (const float*)d_in[29];
    const float* nullv  = (const float*)d_in[30];

    const int rows = in_sizes[0] / INW;
    const int bs = rows / Nn;
    float* out = (float*)d_out;

    float* px      = sym(g_x);
    float* pgi     = sym(g_gi);
    float* pgh     = sym(g_gh);
    float* pp      = sym(g_p);
    float* plogits = sym(g_logits);
    float* pattack = sym(g_attack);
    float* psender = sym(g_sender);
    float* pqk     = sym(g_qk);
    float* pqr     = sym(g_qr);
    float* pqb     = sym(g_qb);
    float* pfusion = sym(g_fusion);
    float* pgd     = sym(g_gd);
    float* pBqk    = sym(g_Bqk);
    float* pbqk    = sym(g_bqk);
    float* pBgd    = sym(g_Bgd);
    float* pbgd    = sym(g_bgd);

    float* hout = (out_size >= rows * (NA + HID)) ? out + (size_t)rows * NA : sym(g_hfb);

    const int MB = rows / 128;

    pack_qk<<<(128 * 256 + 255) / 256, 256>>>(Wq, bq, Wk, pBqk, pbqk);
    pack_gd<<<(512 * 288 + 255) / 256, 256>>>(Wg1, bg1, Wd1, bd1, pBgd, pbgd);

    gemm128<EPI_BIAS_RELU><<<dim3(MB, 2), 256>>>(inputs, INW, W1, INW, b1, px, 256, rows, 256, INW);
    gemm128<EPI_BIAS><<<dim3(MB, 6), 256>>>(px, 256, Wih, 256, bih, pgi, 768, rows, 768, 256);
    gemm128<EPI_BIAS><<<dim3(MB, 6), 256>>>(hidden, 256, Whh, 256, bhh, pgh, 768, rows, 768, 256);
    gru_kernel<<<(rows * 256 + 255) / 256, 256>>>(pgi, pgh, hidden, hout, pfusion, rows * 256);
    gemm128<EPI_BIAS_RELU><<<dim3(MB, 2), 256>>>(hout, 256, Wp1, 256, bp1, pp, 256, rows, 256, 256);
    gemm_tn<EPI_BIAS><<<dim3(MB, 1), 256>>>(pp, 256, Wp2, 256, bp2, plogits, NA, rows, NA, 256);
    logits_post<<<rows / 8, 256>>>(plogits, Wv, bv, out, pattack, psender);
    gemm128<EPI_BIAS><<<dim3(MB, 1), 256>>>(hout, 256, pBqk, 256, pbqk, pqk, 128, rows, 128, 256);
    qr_kernel<<<(rows * 4 + 127) / 128, 128>>>(pqk, Wk, bk, pqr, pqb, rows);
    attn_batch<<<bs, 256>>>(pqk, pqr, pqb, rel, psender, nullk, nullv, ln_g, ln_b, pfusion);
    gemm128<EPI_BIAS_RELU><<<dim3(MB, 4), 256>>>(pfusion, 288, pBgd, 288, pbgd, pgd, 512, rows, 512, 288);
    final_kernel<<<rows / 8, 256>>>(pgd, Wg2, bg2, Wd2, bd2, pattack, out);
}

// round 6
// speedup vs baseline: 2.5559x; 1.6388x over previous
#include <cuda_runtime.h>
#include <cuda_bf16.h>
#include <math.h>
#include <stdint.h>

// ---------------- problem constants ----------------
#define Nn   27
#define NA   33
#define HID  256
#define REL  5
#define INW  322
#define FUSE_SCALE 0.1f
#define NEG  (-10000000000.0f)
#define MAXROWS 27648

// ---------------- scratch (device globals) -------------
__device__ float g_x     [MAXROWS * 256];
__device__ float g_gi    [MAXROWS * 768];
__device__ float g_gh    [MAXROWS * 768];
__device__ float g_p     [MAXROWS * 256];
__device__ float g_logits[MAXROWS * 33];
__device__ float g_attack[MAXROWS * 27];
__device__ float g_sender[MAXROWS * 32];
__device__ float g_qk    [MAXROWS * 128];
__device__ float g_qr    [MAXROWS * 20];
__device__ float g_qb    [MAXROWS * 4];
__device__ float g_fusion[MAXROWS * 288];
__device__ float g_gd    [MAXROWS * 512];
__device__ float g_hfb   [MAXROWS * 256];
__device__ float g_Bqk   [128 * 256];
__device__ float g_Bgd   [512 * 288];
__device__ float g_bqk   [128];
__device__ float g_bgd   [512];
// bf16 hi/lo weight planes (K padded to 32-multiples)
__device__ __nv_bfloat16 g_W1h [256 * 352],  g_W1l [256 * 352];
__device__ __nv_bfloat16 g_Wihh[768 * 256],  g_Wihl[768 * 256];
__device__ __nv_bfloat16 g_Whhh[768 * 256],  g_Whhl[768 * 256];
__device__ __nv_bfloat16 g_Wp1h[256 * 256],  g_Wp1l[256 * 256];
__device__ __nv_bfloat16 g_Bqkh[128 * 256],  g_Bqkl[128 * 256];
__device__ __nv_bfloat16 g_Bgdh[512 * 288],  g_Bgdl[512 * 288];

#define EPI_BIAS 1
#define EPI_BIAS_RELU 2

// =================== helpers ===============
__device__ __forceinline__ uint32_t smem_u32(const void* p) {
    uint32_t a;
    asm("{ .reg .u64 t; cvta.to.shared.u64 t, %1; cvt.u32.u64 %0, t; }" : "=r"(a) : "l"(p));
    return a;
}
#define STS128(a, r0, r1, r2, r3) \
    asm volatile("st.shared.v4.b32 [%0], {%1, %2, %3, %4};" :: "r"(a), "r"(r0), "r"(r1), "r"(r2), "r"(r3) : "memory")

__device__ __forceinline__ uint32_t packbf(__nv_bfloat16 a, __nv_bfloat16 b) {
    __nv_bfloat162 t(a, b);
    return *reinterpret_cast<uint32_t*>(&t);
}
__device__ __forceinline__ void ldsm4(uint32_t* d, uint32_t addr) {
    asm volatile("ldmatrix.sync.aligned.m8n8.x4.shared.b16 {%0,%1,%2,%3}, [%4];"
                 : "=r"(d[0]), "=r"(d[1]), "=r"(d[2]), "=r"(d[3]) : "r"(addr));
}
__device__ __forceinline__ void mma16816(float* c, const uint32_t* a, const uint32_t* b) {
    asm volatile("mma.sync.aligned.m16n8k16.row.col.f32.bf16.bf16.f32 "
                 "{%0,%1,%2,%3}, {%4,%5,%6,%7}, {%8,%9}, {%0,%1,%2,%3};"
                 : "+f"(c[0]), "+f"(c[1]), "+f"(c[2]), "+f"(c[3])
                 : "r"(a[0]), "r"(a[1]), "r"(a[2]), "r"(a[3]), "r"(b[0]), "r"(b[1]));
}

// =================== mma.sync bf16 3-pass GEMM ===================
// C[M,N] = A[M,K](fp32) @ (Bhi+Blo)[N,Kpad]^T (+bias)(relu)
// Block tile 128x128, 8 warps (2m x 4n), warp tile 64x32, BK=32.
// Smem planes: 128 rows x 40 bf16 (80-byte stride -> conflict-free LDSM).
#define PLN 5120   // plane size in bf16 elems (128*40)

template<int EPI>
__global__ void __launch_bounds__(256, 2)
gemm_mma(const float* __restrict__ A, int lda,
         const __nv_bfloat16* __restrict__ Bhi, const __nv_bfloat16* __restrict__ Blo, int ldb,
         const float* __restrict__ bias,
         float* __restrict__ C, int ldc, int K, int nChunks)
{
    __shared__ __align__(16) __nv_bfloat16 sm[4 * PLN];   // Ahi, Alo, Bhi, Blo

    const int tid = threadIdx.x;
    const int wid = tid >> 5, lane = tid & 31;
    const int m0 = blockIdx.x * 128, n0 = blockIdx.y * 128;
    const int r = tid >> 1, hf = tid & 1;

    const uint32_t sAhi = smem_u32(sm);
    const uint32_t sAlo = sAhi + PLN * 2;
    const uint32_t sBhi = sAhi + 2 * PLN * 2;
    const uint32_t sBlo = sAhi + 3 * PLN * 2;

    // fragment-load lane addressing
    const int warp_m = (wid & 1) * 64, warp_n = (wid >> 1) * 32;
    const uint32_t aOff = (uint32_t)(warp_m + (lane & 15)) * 80 + (lane >> 4) * 16;
    const uint32_t bRow = (uint32_t)(warp_n + (lane & 7) + ((lane >> 4) << 3));
    const uint32_t bOff = bRow * 80 + ((lane >> 3) & 1) * 16;

    float c[4][4][4];
#pragma unroll
    for (int mt = 0; mt < 4; mt++)
#pragma unroll
        for (int nt = 0; nt < 4; nt++)
#pragma unroll
            for (int q = 0; q < 4; q++) c[mt][nt][q] = 0.f;

    const uint32_t stA = r * 80 + hf * 32;   // byte offset for producer stores

    for (int ch = 0; ch < nChunks; ch++) {
        const int kc = ch * 32;

        // ---- produce A (fp32 -> bf16 hi/lo) ----
        {
            const float* ap = A + (size_t)(m0 + r) * lda + kc + hf * 16;
            float v[16];
            if (kc + 32 <= K) {
                const float2* ap2 = (const float2*)ap;
#pragma unroll
                for (int i = 0; i < 8; i++) { float2 t = ap2[i]; v[2 * i] = t.x; v[2 * i + 1] = t.y; }
            } else {
#pragma unroll
                for (int i = 0; i < 16; i++) {
                    int gk = kc + hf * 16 + i;
                    v[i] = (gk < K) ? ap[i] : 0.f;
                }
            }
            uint32_t hi[8], lo[8];
#pragma unroll
            for (int p = 0; p < 8; p++) {
                __nv_bfloat16 h0 = __float2bfloat16(v[2 * p]);
                __nv_bfloat16 h1 = __float2bfloat16(v[2 * p + 1]);
                __nv_bfloat16 l0 = __float2bfloat16(v[2 * p]     - __bfloat162float(h0));
                __nv_bfloat16 l1 = __float2bfloat16(v[2 * p + 1] - __bfloat162float(h1));
                hi[p] = packbf(h0, h1);
                lo[p] = packbf(l0, l1);
            }
            STS128(sAhi + stA,      hi[0], hi[1], hi[2], hi[3]);
            STS128(sAhi + stA + 16, hi[4], hi[5], hi[6], hi[7]);
            STS128(sAlo + stA,      lo[0], lo[1], lo[2], lo[3]);
            STS128(sAlo + stA + 16, lo[4], lo[5], lo[6], lo[7]);
        }
        // ---- produce B (pre-split bf16) ----
        {
            const size_t boff = (size_t)(n0 + r) * ldb + kc + hf * 16;
            const uint4* bh = (const uint4*)(Bhi + boff);
            const uint4* bl = (const uint4*)(Blo + boff);
            uint4 h0 = bh[0], h1 = bh[1], l0 = bl[0], l1 = bl[1];
            STS128(sBhi + stA,      h0.x, h0.y, h0.z, h0.w);
            STS128(sBhi + stA + 16, h1.x, h1.y, h1.z, h1.w);
            STS128(sBlo + stA,      l0.x, l0.y, l0.z, l0.w);
            STS128(sBlo + stA + 16, l1.x, l1.y, l1.z, l1.w);
        }
        __syncthreads();

        // ---- consume: 2 k16 steps x 3 passes ----
#pragma unroll
        for (int ks = 0; ks < 2; ks++) {
            const uint32_t ko = ks * 32;
            uint32_t aF[4][4], bF[4][2];

            // pass 1: Ahi x Bhi
#pragma unroll
            for (int mt = 0; mt < 4; mt++) ldsm4(aF[mt], sAhi + aOff + ko + mt * (16 * 80));
#pragma unroll
            for (int p = 0; p < 2; p++) {
                uint32_t t[4];
                ldsm4(t, sBhi + bOff + ko + p * (16 * 80));
                bF[2 * p][0] = t[0]; bF[2 * p][1] = t[1];
                bF[2 * p + 1][0] = t[2]; bF[2 * p + 1][1] = t[3];
            }
#pragma unroll
            for (int mt = 0; mt < 4; mt++)
#pragma unroll
                for (int nt = 0; nt < 4; nt++) mma16816(c[mt][nt], aF[mt], bF[nt]);

            // pass 2: Ahi x Blo (reuse A frags)
#pragma unroll
            for (int p = 0; p < 2; p++) {
                uint32_t t[4];
                ldsm4(t, sBlo + bOff + ko + p * (16 * 80));
                bF[2 * p][0] = t[0]; bF[2 * p][1] = t[1];
                bF[2 * p + 1][0] = t[2]; bF[2 * p + 1][1] = t[3];
            }
#pragma unroll
            for (int mt = 0; mt < 4; mt++)
#pragma unroll
                for (int nt = 0; nt < 4; nt++) mma16816(c[mt][nt], aF[mt], bF[nt]);

            // pass 3: Alo x Bhi
#pragma unroll
            for (int mt = 0; mt < 4; mt++) ldsm4(aF[mt], sAlo + aOff + ko + mt * (16 * 80));
#pragma unroll
            for (int p = 0; p < 2; p++) {
                uint32_t t[4];
                ldsm4(t, sBhi + bOff + ko + p * (16 * 80));
                bF[2 * p][0] = t[0]; bF[2 * p][1] = t[1];
                bF[2 * p + 1][0] = t[2]; bF[2 * p + 1][1] = t[3];
            }
#pragma unroll
            for (int mt = 0; mt < 4; mt++)
#pragma unroll
                for (int nt = 0; nt < 4; nt++) mma16816(c[mt][nt], aF[mt], bF[nt]);
        }
        __syncthreads();
    }

    // ---- epilogue ----
#pragma unroll
    for (int mt = 0; mt < 4; mt++) {
        const int row = m0 + warp_m + mt * 16 + (lane >> 2);
#pragma unroll
        for (int nt = 0; nt < 4; nt++) {
            const int col = n0 + warp_n + nt * 8 + (lane & 3) * 2;
            const float b0 = bias[col], b1 = bias[col + 1];
            float v0 = c[mt][nt][0] + b0, v1 = c[mt][nt][1] + b1;
            float v2 = c[mt][nt][2] + b0, v3 = c[mt][nt][3] + b1;
            if (EPI == EPI_BIAS_RELU) {
                v0 = fmaxf(v0, 0.f); v1 = fmaxf(v1, 0.f);
                v2 = fmaxf(v2, 0.f); v3 = fmaxf(v3, 0.f);
            }
            *(float2*)(C + (size_t)row * ldc + col) = make_float2(v0, v1);
            *(float2*)(C + (size_t)(row + 8) * ldc + col) = make_float2(v2, v3);
        }
    }
}

// ================= weight conversion: fp32 [N,K] -> bf16 hi/lo [N,Kpad] =================
__global__ void conv_w(const float* __restrict__ src, __nv_bfloat16* __restrict__ hi,
                       __nv_bfloat16* __restrict__ lo, int Nrows, int K, int Kpad)
{
    int idx = blockIdx.x * blockDim.x + threadIdx.x;
    if (idx >= Nrows * Kpad) return;
    int n = idx / Kpad, k = idx - n * Kpad;
    float v = (k < K) ? src[(size_t)n * K + k] : 0.f;
    __nv_bfloat16 h = __float2bfloat16(v);
    hi[idx] = h;
    lo[idx] = __float2bfloat16(v - __bfloat162float(h));
}

// ================= generic GEMM (Wp2, N=33 only) =================
template<int EPI>
__global__ void __launch_bounds__(256)
gemm_tn(const float* __restrict__ A, int lda,
        const float* __restrict__ B, int ldb,
        const float* __restrict__ bias,
        float* __restrict__ C, int ldc, int M, int N, int K)
{
    constexpr int BM = 128, BN = 64, BK = 16, TM = 8, TN = 4;
    __shared__ float As[BK][BM + 4];
    __shared__ float Bs[BK][BN + 4];
    const int tid = threadIdx.x;
    const int tx = tid & 15, ty = tid >> 4;
    const int m0 = blockIdx.x * BM, n0 = blockIdx.y * BN;

    float acc[TM][TN];
#pragma unroll
    for (int a = 0; a < TM; a++)
#pragma unroll
        for (int b = 0; b < TN; b++) acc[a][b] = 0.f;

    for (int k0 = 0; k0 < K; k0 += BK) {
#pragma unroll
        for (int i = 0; i < (BM * BK) / 256; i++) {
            int idx = tid + i * 256;
            int m = idx / BK, k = idx % BK;
            int gm = m0 + m, gk = k0 + k;
            As[k][m] = (gm < M && gk < K) ? A[(size_t)gm * lda + gk] : 0.f;
        }
#pragma unroll
        for (int i = 0; i < (BN * BK) / 256; i++) {
            int idx = tid + i * 256;
            int n = idx / BK, k = idx % BK;
            int gn = n0 + n, gk = k0 + k;
            Bs[k][n] = (gn < N && gk < K) ? B[(size_t)gn * ldb + gk] : 0.f;
        }
        __syncthreads();
#pragma unroll
        for (int k = 0; k < BK; k++) {
            float a[TM], b[TN];
#pragma unroll
            for (int tm = 0; tm < TM; tm++) a[tm] = As[k][ty * TM + tm];
#pragma unroll
            for (int tn = 0; tn < TN; tn++) b[tn] = Bs[k][tx * TN + tn];
#pragma unroll
            for (int tm = 0; tm < TM; tm++)
#pragma unroll
                for (int tn = 0; tn < TN; tn++)
                    acc[tm][tn] += a[tm] * b[tn];
        }
        __syncthreads();
    }
#pragma unroll
    for (int tm = 0; tm < TM; tm++) {
        int gm = m0 + ty * TM + tm;
        if (gm >= M) continue;
#pragma unroll
        for (int tn = 0; tn < TN; tn++) {
            int gn = n0 + tx * TN + tn;
            if (gn >= N) continue;
            float v = acc[tm][tn];
            if (EPI >= EPI_BIAS) v += bias[gn];
            if (EPI == EPI_BIAS_RELU) v = fmaxf(v, 0.f);
            C[(size_t)gm * ldc + gn] = v;
        }
    }
}

// ================= weight packing =================
__global__ void pack_qk(const float* __restrict__ Wq, const float* __restrict__ Wk,
                        float* __restrict__ Bp)
{
    int idx = blockIdx.x * blockDim.x + threadIdx.x;
    if (idx < 128 * 256) {
        int r = idx >> 8, c = idx & 255;
        Bp[idx] = (r < 64) ? Wq[r * 256 + c] : Wk[(size_t)(r - 64) * (HID + REL) + c];
    }
}
__global__ void pack_gd(const float* __restrict__ Wg1, const float* __restrict__ Wd1,
                        float* __restrict__ Bp)
{
    int idx = blockIdx.x * blockDim.x + threadIdx.x;
    if (idx < 512 * 288) {
        int r = idx / 288, c = idx % 288;
        Bp[idx] = (r < 256) ? Wg1[r * 288 + c] : Wd1[(r - 256) * 288 + c];
    }
}
__global__ void pack_bias2(const float* __restrict__ a, int na, const float* __restrict__ b, int nb_,
                           float* __restrict__ dst)
{
    int idx = blockIdx.x * blockDim.x + threadIdx.x;
    if (idx < na) dst[idx] = a[idx];
    else if (idx < na + nb_) dst[idx] = b ? b[idx - na] : 0.f;
}

// ================= GRU (writes h and fusion[:,0:256]) =================
__global__ void gru_kernel(const float* __restrict__ gi, const float* __restrict__ gh,
                           const float* __restrict__ hin, float* __restrict__ hout,
                           float* __restrict__ fusion, int total)
{
    int idx = blockIdx.x * blockDim.x + threadIdx.x;
    if (idx >= total) return;
    int r = idx >> 8, c = idx & 255;
    size_t base = (size_t)r * 768;
    float ir = gi[base + c], iz = gi[base + 256 + c], in_ = gi[base + 512 + c];
    float hr = gh[base + c], hz = gh[base + 256 + c], hn = gh[base + 512 + c];
    float rg = 1.f / (1.f + expf(-(ir + hr)));
    float zg = 1.f / (1.f + expf(-(iz + hz)));
    float ng = tanhf(in_ + rg * hn);
    float v = (1.f - zg) * ng + zg * hin[idx];
    hout[idx] = v;
    fusion[(size_t)r * 288 + c] = v;
}

// ================= logits post =================
__global__ void __launch_bounds__(256)
logits_post(const float* __restrict__ logits, const float* __restrict__ Wv,
            const float* __restrict__ bv,
            float* __restrict__ out, float* __restrict__ attack,
            float* __restrict__ sender)
{
    __shared__ float Wvs[32 * 29];
    __shared__ float bvs[32];
    __shared__ float vs[8][29];
    int tid = threadIdx.x;
    for (int t = tid; t < 32 * 29; t += 256) Wvs[t] = Wv[t];
    if (tid < 32) bvs[tid] = bv[tid];
    int w = tid >> 5, l = tid & 31;
    int row = blockIdx.x * 8 + w;
    const float* lrow = logits + (size_t)row * 33;
    float al = (l < 27) ? lrow[6 + l] : -INFINITY;
    float mx = al;
#pragma unroll
    for (int o = 16; o > 0; o >>= 1) mx = fmaxf(mx, __shfl_xor_sync(0xffffffffu, mx, o));
    float e = (l < 27) ? expf(al - mx) : 0.f;
    float sum = e;
#pragma unroll
    for (int o = 16; o > 0; o >>= 1) sum += __shfl_xor_sync(0xffffffffu, sum, o);
    float inv = 1.f / sum;
    if (l < 27) vs[w][l] = e * inv;
    if (l == 27) vs[w][27] = 1.0f;
    if (l == 28) vs[w][28] = inv;
    if (l < 27) attack[(size_t)row * 27 + l] = al;
    if (l < 6)  out[(size_t)row * 33 + l] = lrow[l];
    __syncthreads();
    float s = bvs[l];
#pragma unroll
    for (int r = 0; r < 29; r++) s += vs[w][r] * Wvs[l * 29 + r];
    sender[(size_t)row * 32 + l] = s;
}

// ================= qr / qb precompute =================
__global__ void qr_kernel(const float* __restrict__ qk, const float* __restrict__ Wk,
                          const float* __restrict__ bk,
                          float* __restrict__ qr, float* __restrict__ qb, int rows)
{
    int idx = blockIdx.x * blockDim.x + threadIdx.x;
    if (idx >= rows * 4) return;
    int row = idx >> 2, h = idx & 3;
    const float* qp = qk + (size_t)row * 128 + h * 16;
    float acc[5] = {0.f, 0.f, 0.f, 0.f, 0.f};
    float accb = 0.f;
#pragma unroll
    for (int d = 0; d < 16; d++) {
        float qd = qp[d];
        const float* wrow = Wk + (size_t)(h * 16 + d) * (HID + REL) + HID;
#pragma unroll
        for (int r = 0; r < 5; r++) acc[r] += qd * wrow[r];
        accb += qd * bk[h * 16 + d];
    }
#pragma unroll
    for (int r = 0; r < 5; r++) qr[(size_t)row * 20 + h * 5 + r] = acc[r];
    qb[(size_t)row * 4 + h] = accb;
}

// ================= batched attention =================
__global__ void __launch_bounds__(256)
attn_batch(const float* __restrict__ qk, const float* __restrict__ qr,
           const float* __restrict__ qb, const float* __restrict__ rel,
           const float* __restrict__ sender,
           const float* __restrict__ nullk, const float* __restrict__ nullv,
           const float* __restrict__ ln_g, const float* __restrict__ ln_b,
           float* __restrict__ fusion)
{
    __shared__ float qk_s[27 * 128];
    __shared__ float sender_s[27 * 32];
    __shared__ float rel_s[27 * 27 * 5];
    __shared__ float qr_s[27 * 20];
    __shared__ float qb_s[27 * 4];
    __shared__ float nk_s[64];
    __shared__ float nv_s[32];
    __shared__ float sc[27 * 112];

    const int b = blockIdx.x;
    const int tid = threadIdx.x;
    const size_t rbase = (size_t)b * 27;

    for (int t = tid; t < 27 * 128; t += 256) qk_s[t] = qk[rbase * 128 + t];
    for (int t = tid; t < 27 * 32; t += 256) sender_s[t] = sender[rbase * 32 + t];
    for (int t = tid; t < 27 * 27 * 5; t += 256) rel_s[t] = rel[(size_t)b * (27 * 27 * 5) + t];
    for (int t = tid; t < 27 * 20; t += 256) qr_s[t] = qr[rbase * 20 + t];
    for (int t = tid; t < 27 * 4; t += 256) qb_s[t] = qb[rbase * 4 + t];
    if (tid < 64) nk_s[tid] = nullk[tid];
    if (tid >= 64 && tid < 96) nv_s[tid - 64] = nullv[tid - 64];
    __syncthreads();

    for (int t = tid; t < 27 * 112; t += 256) {
        int i = t / 112;
        int rem = t - i * 112;
        int j = rem >> 2, h = rem & 3;
        float s;
        if (j == 27) {
            float d = 0.f;
#pragma unroll
            for (int dd = 0; dd < 16; dd++) d += qk_s[i * 128 + h * 16 + dd] * nk_s[h * 16 + dd];
            s = 0.25f * d;
        } else if (j == i) {
            s = NEG;
        } else {
            float d = qb_s[i * 4 + h];
#pragma unroll
            for (int dd = 0; dd < 16; dd++)
                d += qk_s[i * 128 + h * 16 + dd] * qk_s[j * 128 + 64 + h * 16 + dd];
            const float* rr = &rel_s[(i * 27 + j) * 5];
#pragma unroll
            for (int r = 0; r < 5; r++) d += qr_s[i * 20 + h * 5 + r] * rr[r];
            s = 0.25f * d;
        }
        sc[t] = s;
    }
    __syncthreads();

    for (int t = tid; t < 108; t += 256) {
        int i = t >> 2, h = t & 3;
        float* scp = &sc[i * 112 + h];
        float t0 = -INFINITY, t1 = -INFINITY, t2 = -INFINITY, t3 = -INFINITY;
#pragma unroll
        for (int j = 0; j < 28; j++) {
            float v = scp[j * 4];
            if (v > t0)      { t3 = t2; t2 = t1; t1 = t0; t0 = v; }
            else if (v > t1) { t3 = t2; t2 = t1; t1 = v; }
            else if (v > t2) { t3 = t2; t2 = v; }
            else if (v > t3) { t3 = v; }
        }
        float thr = t3, mxv = t0, sum = 0.f;
        float e[28];
#pragma unroll
        for (int j = 0; j < 28; j++) {
            float v = scp[j * 4];
            float ev = (v >= thr) ? expf(v - mxv) : 0.f;
            e[j] = ev; sum += ev;
        }
        float inv = 1.f / sum;
#pragma unroll
        for (int j = 0; j < 28; j++) scp[j * 4] = e[j] * inv;
    }
    __syncthreads();

    int w = tid >> 5, l = tid & 31;
    int h = l >> 3;
    for (int i = w; i < 27; i += 8) {
        const float* scp = &sc[i * 112];
        float m = scp[108 + h] * nv_s[l];
#pragma unroll
        for (int j = 0; j < 27; j++) m += scp[j * 4 + h] * sender_s[j * 32 + l];
        float s = m, s2 = m * m;
#pragma unroll
        for (int o = 16; o > 0; o >>= 1) {
            s  += __shfl_xor_sync(0xffffffffu, s, o);
            s2 += __shfl_xor_sync(0xffffffffu, s2, o);
        }
        float mu = s * (1.f / 32.f);
        float var = s2 * (1.f / 32.f) - mu * mu;
        float nm = (m - mu) * rsqrtf(var + 1e-5f) * ln_g[l] + ln_b[l];
        fusion[(rbase + i) * 288 + 256 + l] = nm;
    }
}

// ================= final =================
__global__ void __launch_bounds__(256)
final_kernel(const float* __restrict__ gd,
             const float* __restrict__ Wg2, const float* __restrict__ bg2,
             const float* __restrict__ Wd2, const float* __restrict__ bd2,
             const float* __restrict__ attack,
             float* __restrict__ out)
{
    __shared__ float Wd2s[256 * 28];
    __shared__ float wg2s[256];
    int tid = threadIdx.x;
    for (int t = tid; t < 27 * 256; t += 256) {
        int l = t >> 8, k = t & 255;
        Wd2s[k * 28 + l] = Wd2[t];
    }
    if (tid < 256) wg2s[tid] = Wg2[tid];
    __syncthreads();

    int w = tid >> 5, l = tid & 31;
    int row = blockIdx.x * 8 + w;
    const float* g1r = gd + (size_t)row * 512;
    const float* d1r = g1r + 256;
    float gs = 0.f;
#pragma unroll
    for (int i = 0; i < 8; i++) gs += g1r[l + i * 32] * wg2s[l + i * 32];
#pragma unroll
    for (int o = 16; o > 0; o >>= 1) gs += __shfl_xor_sync(0xffffffffu, gs, o);
    float gate = 1.f / (1.f + expf(-(gs + bg2[0])));
    if (l < 27) {
        float d = bd2[l];
#pragma unroll 8
        for (int k = 0; k < 256; k++) d += d1r[k] * Wd2s[k * 28 + l];
        out[(size_t)row * 33 + 6 + l] = attack[(size_t)row * 27 + l] + FUSE_SCALE * gate * d;
    }
}

// ================= host launcher =================
static float* sym(const void* symbol)
{
    void* p = nullptr;
    cudaGetSymbolAddress(&p, symbol);
    return (float*)p;
}
static __nv_bfloat16* symb(const void* symbol)
{
    void* p = nullptr;
    cudaGetSymbolAddress(&p, symbol);
    return (__nv_bfloat16*)p;
}

extern "C" void kernel_launch(void* const* d_in, const int* in_sizes, int n_in,
                              void* d_out, int out_size)
{
    const float* inputs = (const float*)d_in[0];
    const float* hidden = (const float*)d_in[1];
    const float* rel    = (const float*)d_in[2];
    const float* W1     = (const float*)d_in[3];
    const float* b1     = (const float*)d_in[4];
    const float* Wih    = (const float*)d_in[5];
    const float* bih    = (const float*)d_in[6];
    const float* Whh    = (const float*)d_in[7];
    const float* bhh    = (const float*)d_in[8];
    const float* Wp1    = (const float*)d_in[9];
    const float* bp1    = (const float*)d_in[10];
    const float* Wp2    = (const float*)d_in[11];
    const float* bp2    = (const float*)d_in[12];
    const float* Wq     = (const float*)d_in[13];
    const float* bq     = (const float*)d_in[14];
    const float* Wk     = (const float*)d_in[15];
    const float* bk     = (const float*)d_in[16];
    const float* Wv     = (const float*)d_in[17];
    const float* bv     = (const float*)d_in[18];
    const float* ln_g   = (const float*)d_in[19];
    const float* ln_b   = (const float*)d_in[20];
    const float* Wg1    = (const float*)d_in[21];
    const float* bg1    = (const float*)d_in[22];
    const float* Wg2    = (const float*)d_in[23];
    const float* bg2    = (const float*)d_in[24];
    const float* Wd1    = (const float*)d_in[25];
    const float* bd1    = (const float*)d_in[26];
    const float* Wd2    = (const float*)d_in[27];
    const float* bd2    = (const float*)d_in[28];
    const float* nullk  = (const float*)d_in[29];
    const float* nullv  = (const float*)d_in[30];

    const int rows = in_sizes[0] / INW;    // 27648
    const int bs = rows / Nn;
    float* out = (float*)d_out;

    float* px      = sym(g_x);
    float* pgi     = sym(g_gi);
    float* pgh     = sym(g_gh);
    float* pp      = sym(g_p);
    float* plogits = sym(g_logits);
    float* pattack = sym(g_attack);
    float* psender = sym(g_sender);
    float* pqk     = sym(g_qk);
    float* pqr     = sym(g_qr);
    float* pqb     = sym(g_qb);
    float* pfusion = sym(g_fusion);
    float* pgd     = sym(g_gd);
    float* pBqk    = sym(g_Bqk);
    float* pBgd    = sym(g_Bgd);
    float* pbqk    = sym(g_bqk);
    float* pbgd    = sym(g_bgd);

    __nv_bfloat16 *pW1h = symb(g_W1h),  *pW1l = symb(g_W1l);
    __nv_bfloat16 *pWihh = symb(g_Wihh), *pWihl = symb(g_Wihl);
    __nv_bfloat16 *pWhhh = symb(g_Whhh), *pWhhl = symb(g_Whhl);
    __nv_bfloat16 *pWp1h = symb(g_Wp1h), *pWp1l = symb(g_Wp1l);
    __nv_bfloat16 *pBqkh = symb(g_Bqkh), *pBqkl = symb(g_Bqkl);
    __nv_bfloat16 *pBgdh = symb(g_Bgdh), *pBgdl = symb(g_Bgdl);

    float* hout = (out_size >= rows * (NA + HID)) ? out + (size_t)rows * NA : sym(g_hfb);

    const int MB = rows / 128;   // 216

    // --- weight packing / bf16 split ---
    pack_qk<<<(128 * 256 + 255) / 256, 256>>>(Wq, Wk, pBqk);
    pack_gd<<<(512 * 288 + 255) / 256, 256>>>(Wg1, Wd1, pBgd);
    pack_bias2<<<1, 128>>>(bq, 64, nullptr, 64, pbqk);
    pack_bias2<<<2, 256>>>(bg1, 256, bd1, 256, pbgd);
    conv_w<<<(256 * 352 + 255) / 256, 256>>>(W1, pW1h, pW1l, 256, 322, 352);
    conv_w<<<(768 * 256 + 255) / 256, 256>>>(Wih, pWihh, pWihl, 768, 256, 256);
    conv_w<<<(768 * 256 + 255) / 256, 256>>>(Whh, pWhhh, pWhhl, 768, 256, 256);
    conv_w<<<(256 * 256 + 255) / 256, 256>>>(Wp1, pWp1h, pWp1l, 256, 256, 256);
    conv_w<<<(128 * 256 + 255) / 256, 256>>>(pBqk, pBqkh, pBqkl, 128, 256, 256);
    conv_w<<<(512 * 288 + 255) / 256, 256>>>(pBgd, pBgdh, pBgdl, 512, 288, 288);

    // 1. x = relu(inputs @ W1^T + b1)            K=322 -> 11 chunks
    gemm_mma<EPI_BIAS_RELU><<<dim3(MB, 2), 256>>>(inputs, INW, pW1h, pW1l, 352, b1, px, 256, 322, 11);
    // 2. gi, gh                                  K=256 -> 8 chunks
    gemm_mma<EPI_BIAS><<<dim3(MB, 6), 256>>>(px, 256, pWihh, pWihl, 256, bih, pgi, 768, 256, 8);
    gemm_mma<EPI_BIAS><<<dim3(MB, 6), 256>>>(hidden, 256, pWhhh, pWhhl, 256, bhh, pgh, 768, 256, 8);
    // 3. GRU -> h (+ fusion[:,0:256])
    gru_kernel<<<(rows * 256 + 255) / 256, 256>>>(pgi, pgh, hidden, hout, pfusion, rows * 256);
    // 4. p = relu(h @ Wp1^T + bp1); logits = p @ Wp2^T + bp2
    gemm_mma<EPI_BIAS_RELU><<<dim3(MB, 2), 256>>>(hout, 256, pWp1h, pWp1l, 256, bp1, pp, 256, 256, 8);
    gemm_tn<EPI_BIAS><<<dim3(MB, 1), 256>>>(pp, 256, Wp2, 256, bp2, plogits, NA, rows, NA, 256);
    // 5. softmax / sender values / base logits
    logits_post<<<rows / 8, 256>>>(plogits, Wv, bv, out, pattack, psender);
    // 6. [q | key_h] = h @ [Wq; Wk_h]^T + [bq; 0]
    gemm_mma<EPI_BIAS><<<dim3(MB, 1), 256>>>(hout, 256, pBqkh, pBqkl, 256, pbqk, pqk, 128, 256, 8);
    // 7. qr, qb
    qr_kernel<<<(rows * 4 + 127) / 128, 128>>>(pqk, Wk, bk, pqr, pqb, rows);
    // 8. attention (batched) -> fusion[:,256:288]
    attn_batch<<<bs, 256>>>(pqk, pqr, pqb, rel, psender, nullk, nullv, ln_g, ln_b, pfusion);
    // 9. [g1 | d1] = relu(fusion @ [Wg1; Wd1]^T + [bg1; bd1])   K=288 -> 9 chunks
    gemm_mma<EPI_BIAS_RELU><<<dim3(MB, 4), 256>>>(pfusion, 288, pBgdh, pBgdl, 288, pbgd, pgd, 512, 288, 9);
    // 10. gate, delta, fused output
    final_kernel<<<rows / 8, 256>>>(pgd, Wg2, bg2, Wd2, bd2, pattack, out);
}

// round 7
// speedup vs baseline: 2.7831x; 1.0889x over previous
#include <cuda_runtime.h>
#include <cuda_bf16.h>
#include <math.h>
#include <stdint.h>

// ---------------- problem constants ----------------
#define Nn   27
#define NA   33
#define HID  256
#define REL  5
#define INW  322
#define FUSE_SCALE 0.1f
#define NEG  (-10000000000.0f)
#define MAXROWS 27648

// ---------------- scratch (device globals) -------------
__device__ float g_x     [MAXROWS * 256];
__device__ float g_gi    [MAXROWS * 768];
__device__ float g_gh    [MAXROWS * 768];
__device__ float g_p     [MAXROWS * 256];
__device__ float g_logits[MAXROWS * 33];
__device__ float g_attack[MAXROWS * 27];
__device__ float g_sender[MAXROWS * 32];
__device__ float g_qk    [MAXROWS * 128];
__device__ float g_qr    [MAXROWS * 20];
__device__ float g_qb    [MAXROWS * 4];
__device__ float g_fusion[MAXROWS * 288];
__device__ float g_gd    [MAXROWS * 512];
__device__ float g_hfb   [MAXROWS * 256];
__device__ float g_bqk   [128];
__device__ float g_bgd   [512];
// bf16 hi/lo weight planes (K padded to 32-multiples)
__device__ __nv_bfloat16 g_W1h [256 * 352],  g_W1l [256 * 352];
__device__ __nv_bfloat16 g_Wihh[768 * 256],  g_Wihl[768 * 256];
__device__ __nv_bfloat16 g_Whhh[768 * 256],  g_Whhl[768 * 256];
__device__ __nv_bfloat16 g_Wp1h[256 * 256],  g_Wp1l[256 * 256];
__device__ __nv_bfloat16 g_Bqkh[128 * 256],  g_Bqkl[128 * 256];
__device__ __nv_bfloat16 g_Bgdh[512 * 288],  g_Bgdl[512 * 288];

#define EPI_BIAS 1
#define EPI_BIAS_RELU 2

// =================== helpers ===============
__device__ __forceinline__ uint32_t smem_u32(const void* p) {
    uint32_t a;
    asm("{ .reg .u64 t; cvta.to.shared.u64 t, %1; cvt.u32.u64 %0, t; }" : "=r"(a) : "l"(p));
    return a;
}
#define STS128(a, r0, r1, r2, r3) \
    asm volatile("st.shared.v4.b32 [%0], {%1, %2, %3, %4};" :: "r"(a), "r"(r0), "r"(r1), "r"(r2), "r"(r3) : "memory")
#define CP_ASYNC16(dst, src) \
    asm volatile("cp.async.cg.shared.global [%0], [%1], 16;" :: "r"(dst), "l"(src) : "memory")
#define CP_COMMIT() asm volatile("cp.async.commit_group;" ::: "memory")
#define CP_WAIT0()  asm volatile("cp.async.wait_group 0;" ::: "memory")

__device__ __forceinline__ uint32_t packbf(__nv_bfloat16 a, __nv_bfloat16 b) {
    __nv_bfloat162 t(a, b);
    return *reinterpret_cast<uint32_t*>(&t);
}
__device__ __forceinline__ void ldsm4(uint32_t* d, uint32_t addr) {
    asm volatile("ldmatrix.sync.aligned.m8n8.x4.shared.b16 {%0,%1,%2,%3}, [%4];"
                 : "=r"(d[0]), "=r"(d[1]), "=r"(d[2]), "=r"(d[3]) : "r"(addr));
}
__device__ __forceinline__ void mma16816(float* c, const uint32_t* a, const uint32_t* b) {
    asm volatile("mma.sync.aligned.m16n8k16.row.col.f32.bf16.bf16.f32 "
                 "{%0,%1,%2,%3}, {%4,%5,%6,%7}, {%8,%9}, {%0,%1,%2,%3};"
                 : "+f"(c[0]), "+f"(c[1]), "+f"(c[2]), "+f"(c[3])
                 : "r"(a[0]), "r"(a[1]), "r"(a[2]), "r"(a[3]), "r"(b[0]), "r"(b[1]));
}

// =================== pipelined mma.sync bf16 3-pass GEMM ===================
// C[M,N] = A[M,K](fp32) @ (Bhi+Blo)[N,Kpad]^T (+bias)(relu)
// Block tile 128x128, 8 warps (2m x 4n), warp tile 64x32, BK=32.
// 2-stage double buffer: cp.async for B planes, register prefetch for A.
// Plane: 128 rows x 40 bf16 (80B stride, conflict-free LDSM).
#define PLN    5120
#define PLNB   (PLN * 2)          // plane bytes = 10240
#define STAGEB (4 * PLNB)         // Ahi,Alo,Bhi,Blo = 40960
#define GSMEM  (2 * STAGEB)       // 81920

template<int EPI>
__global__ void __launch_bounds__(256)
gemm_mma(const float* __restrict__ A, int lda,
         const __nv_bfloat16* __restrict__ Bhi, const __nv_bfloat16* __restrict__ Blo, int ldb,
         const float* __restrict__ bias,
         float* __restrict__ C, int ldc, int K, int nChunks)
{
    extern __shared__ __align__(16) char smx[];

    const int tid = threadIdx.x;
    const int wid = tid >> 5, lane = tid & 31;
    const int m0 = blockIdx.x * 128, n0 = blockIdx.y * 128;
    const int r = tid >> 1, hf = tid & 1;

    const uint32_t sbase = smem_u32(smx);
    const uint32_t stA = (uint32_t)r * 80 + hf * 32;   // producer store offset within a plane

    // fragment-load lane addressing
    const int warp_m = (wid & 1) * 64, warp_n = (wid >> 1) * 32;
    const uint32_t aOff = (uint32_t)(warp_m + (lane & 15)) * 80 + (lane >> 4) * 16;
    const uint32_t bRow = (uint32_t)(warp_n + (lane & 7) + ((lane >> 4) << 3));
    const uint32_t bOff = bRow * 80 + ((lane >> 3) & 1) * 16;

    float c[4][4][4];
#pragma unroll
    for (int mt = 0; mt < 4; mt++)
#pragma unroll
        for (int nt = 0; nt < 4; nt++)
#pragma unroll
            for (int q = 0; q < 4; q++) c[mt][nt][q] = 0.f;

    const float* Arow = A + (size_t)(m0 + r) * lda + hf * 16;
    const __nv_bfloat16* BhiRow = Bhi + (size_t)(n0 + r) * ldb + hf * 16;
    const __nv_bfloat16* BloRow = Blo + (size_t)(n0 + r) * ldb + hf * 16;

    float v[16];

    // ---- helpers as lambdas ----
    auto loadA = [&](int ch) {
        const int kc = ch * 32;
        const float* ap = Arow + kc;
        if (kc + 32 <= K) {
            const float2* ap2 = (const float2*)ap;
#pragma unroll
            for (int i = 0; i < 8; i++) { float2 t = ap2[i]; v[2 * i] = t.x; v[2 * i + 1] = t.y; }
        } else {
#pragma unroll
            for (int i = 0; i < 16; i++) {
                int gk = kc + hf * 16 + i;
                v[i] = (gk < K) ? ap[i] : 0.f;
            }
        }
    };
    auto issueB = [&](int ch, int st) {
        const int kc = ch * 32;
        const uint32_t base = sbase + st * STAGEB;
        CP_ASYNC16(base + 2 * PLNB + stA,      BhiRow + kc);
        CP_ASYNC16(base + 2 * PLNB + stA + 16, BhiRow + kc + 8);
        CP_ASYNC16(base + 3 * PLNB + stA,      BloRow + kc);
        CP_ASYNC16(base + 3 * PLNB + stA + 16, BloRow + kc + 8);
    };
    auto stsA = [&](int st) {
        uint32_t hi[8], lo[8];
#pragma unroll
        for (int p = 0; p < 8; p++) {
            __nv_bfloat16 h0 = __float2bfloat16(v[2 * p]);
            __nv_bfloat16 h1 = __float2bfloat16(v[2 * p + 1]);
            __nv_bfloat16 l0 = __float2bfloat16(v[2 * p]     - __bfloat162float(h0));
            __nv_bfloat16 l1 = __float2bfloat16(v[2 * p + 1] - __bfloat162float(h1));
            hi[p] = packbf(h0, h1);
            lo[p] = packbf(l0, l1);
        }
        const uint32_t base = sbase + st * STAGEB;
        STS128(base + stA,             hi[0], hi[1], hi[2], hi[3]);
        STS128(base + stA + 16,        hi[4], hi[5], hi[6], hi[7]);
        STS128(base + PLNB + stA,      lo[0], lo[1], lo[2], lo[3]);
        STS128(base + PLNB + stA + 16, lo[4], lo[5], lo[6], lo[7]);
    };

    // ---- prologue: fill stage 0 ----
    issueB(0, 0); CP_COMMIT();
    loadA(0);
    stsA(0);
    CP_WAIT0();
    __syncthreads();

    for (int ch = 0; ch < nChunks; ch++) {
        const int cur = ch & 1, nxt = cur ^ 1;
        const bool more = (ch + 1 < nChunks);
        if (more) {
            issueB(ch + 1, nxt); CP_COMMIT();
            loadA(ch + 1);
        }

        // ---- consume stage cur: 2 k16 steps x 3 passes ----
        const uint32_t base = sbase + cur * STAGEB;
        const uint32_t sAhi = base, sAlo = base + PLNB;
        const uint32_t sBhi = base + 2 * PLNB, sBlo = base + 3 * PLNB;
#pragma unroll
        for (int ks = 0; ks < 2; ks++) {
            const uint32_t ko = ks * 32;
            uint32_t aF[4][4], bF[4][2];

            // pass 1: Ahi x Bhi
#pragma unroll
            for (int mt = 0; mt < 4; mt++) ldsm4(aF[mt], sAhi + aOff + ko + mt * (16 * 80));
#pragma unroll
            for (int p = 0; p < 2; p++) {
                uint32_t t[4];
                ldsm4(t, sBhi + bOff + ko + p * (16 * 80));
                bF[2 * p][0] = t[0]; bF[2 * p][1] = t[1];
                bF[2 * p + 1][0] = t[2]; bF[2 * p + 1][1] = t[3];
            }
#pragma unroll
            for (int mt = 0; mt < 4; mt++)
#pragma unroll
                for (int nt = 0; nt < 4; nt++) mma16816(c[mt][nt], aF[mt], bF[nt]);

            // pass 2: Ahi x Blo (reuse A frags)
#pragma unroll
            for (int p = 0; p < 2; p++) {
                uint32_t t[4];
                ldsm4(t, sBlo + bOff + ko + p * (16 * 80));
                bF[2 * p][0] = t[0]; bF[2 * p][1] = t[1];
                bF[2 * p + 1][0] = t[2]; bF[2 * p + 1][1] = t[3];
            }
#pragma unroll
            for (int mt = 0; mt < 4; mt++)
#pragma unroll
                for (int nt = 0; nt < 4; nt++) mma16816(c[mt][nt], aF[mt], bF[nt]);

            // pass 3: Alo x Bhi
#pragma unroll
            for (int mt = 0; mt < 4; mt++) ldsm4(aF[mt], sAlo + aOff + ko + mt * (16 * 80));
#pragma unroll
            for (int p = 0; p < 2; p++) {
                uint32_t t[4];
                ldsm4(t, sBhi + bOff + ko + p * (16 * 80));
                bF[2 * p][0] = t[0]; bF[2 * p][1] = t[1];
                bF[2 * p + 1][0] = t[2]; bF[2 * p + 1][1] = t[3];
            }
#pragma unroll
            for (int mt = 0; mt < 4; mt++)
#pragma unroll
                for (int nt = 0; nt < 4; nt++) mma16816(c[mt][nt], aF[mt], bF[nt]);
        }

        if (more) {
            stsA(nxt);
            CP_WAIT0();
        }
        __syncthreads();
    }

    // ---- epilogue ----
#pragma unroll
    for (int mt = 0; mt < 4; mt++) {
        const int row = m0 + warp_m + mt * 16 + (lane >> 2);
#pragma unroll
        for (int nt = 0; nt < 4; nt++) {
            const int col = n0 + warp_n + nt * 8 + (lane & 3) * 2;
            const float b0 = bias[col], b1 = bias[col + 1];
            float v0 = c[mt][nt][0] + b0, v1 = c[mt][nt][1] + b1;
            float v2 = c[mt][nt][2] + b0, v3 = c[mt][nt][3] + b1;
            if (EPI == EPI_BIAS_RELU) {
                v0 = fmaxf(v0, 0.f); v1 = fmaxf(v1, 0.f);
                v2 = fmaxf(v2, 0.f); v3 = fmaxf(v3, 0.f);
            }
            *(float2*)(C + (size_t)row * ldc + col) = make_float2(v0, v1);
            *(float2*)(C + (size_t)(row + 8) * ldc + col) = make_float2(v2, v3);
        }
    }
}

// ================= one-shot weight prep: split/pack everything =================
// segments (element counts):
// 0: W1   256x352 (K=322)      1: Wih 768x256    2: Whh 768x256
// 3: Wp1  256x256              4: Bqk 128x256 (from Wq/Wk)
// 5: Bgd  512x288 (from Wg1/Wd1)   6: biases (128 + 512)
#define S0 (256*352)
#define S1 (768*256)
#define S2 (768*256)
#define S3 (256*256)
#define S4 (128*256)
#define S5 (512*288)
#define S6 (128+512)
#define STOT (S0+S1+S2+S3+S4+S5+S6)

__global__ void prep_all(const float* __restrict__ W1,  const float* __restrict__ Wih,
                         const float* __restrict__ Whh, const float* __restrict__ Wp1,
                         const float* __restrict__ Wq,  const float* __restrict__ Wk,
                         const float* __restrict__ Wg1, const float* __restrict__ Wd1,
                         const float* __restrict__ bq,  const float* __restrict__ bg1,
                         const float* __restrict__ bd1,
                         __nv_bfloat16* __restrict__ W1h,  __nv_bfloat16* __restrict__ W1l,
                         __nv_bfloat16* __restrict__ Wihh, __nv_bfloat16* __restrict__ Wihl,
                         __nv_bfloat16* __restrict__ Whhh, __nv_bfloat16* __restrict__ Whhl,
                         __nv_bfloat16* __restrict__ Wp1h, __nv_bfloat16* __restrict__ Wp1l,
                         __nv_bfloat16* __restrict__ Bqkh, __nv_bfloat16* __restrict__ Bqkl,
                         __nv_bfloat16* __restrict__ Bgdh, __nv_bfloat16* __restrict__ Bgdl,
                         float* __restrict__ pbqk, float* __restrict__ pbgd)
{
    int idx = blockIdx.x * blockDim.x + threadIdx.x;
    if (idx >= STOT) return;
    float src;
    __nv_bfloat16 *hi, *lo;
    int off;
    if (idx < S0) {
        off = idx;
        int k = off % 352;
        src = (k < 322) ? W1[(off / 352) * 322 + k] : 0.f;
        hi = W1h; lo = W1l;
    } else if (idx < S0 + S1) {
        off = idx - S0; src = Wih[off]; hi = Wihh; lo = Wihl;
    } else if (idx < S0 + S1 + S2) {
        off = idx - S0 - S1; src = Whh[off]; hi = Whhh; lo = Whhl;
    } else if (idx < S0 + S1 + S2 + S3) {
        off = idx - S0 - S1 - S2; src = Wp1[off]; hi = Wp1h; lo = Wp1l;
    } else if (idx < S0 + S1 + S2 + S3 + S4) {
        off = idx - S0 - S1 - S2 - S3;
        int rr = off >> 8, cc = off & 255;
        src = (rr < 64) ? Wq[rr * 256 + cc] : Wk[(size_t)(rr - 64) * (HID + REL) + cc];
        hi = Bqkh; lo = Bqkl;
    } else if (idx < S0 + S1 + S2 + S3 + S4 + S5) {
        off = idx - S0 - S1 - S2 - S3 - S4;
        int rr = off / 288, cc = off % 288;
        src = (rr < 256) ? Wg1[rr * 288 + cc] : Wd1[(rr - 256) * 288 + cc];
        hi = Bgdh; lo = Bgdl;
    } else {
        off = idx - (S0 + S1 + S2 + S3 + S4 + S5);
        if (off < 128) pbqk[off] = (off < 64) ? bq[off] : 0.f;
        else { int o = off - 128; pbgd[o] = (o < 256) ? bg1[o] : bd1[o - 256]; }
        return;
    }
    __nv_bfloat16 h = __float2bfloat16(src);
    hi[off] = h;
    lo[off] = __float2bfloat16(src - __bfloat162float(h));
}

// ================= generic GEMM (Wp2, N=33 only) =================
template<int EPI>
__global__ void __launch_bounds__(256)
gemm_tn(const float* __restrict__ A, int lda,
        const float* __restrict__ B, int ldb,
        const float* __restrict__ bias,
        float* __restrict__ C, int ldc, int M, int N, int K)
{
    constexpr int BM = 128, BN = 64, BK = 16, TM = 8, TN = 4;
    __shared__ float As[BK][BM + 4];
    __shared__ float Bs[BK][BN + 4];
    const int tid = threadIdx.x;
    const int tx = tid & 15, ty = tid >> 4;
    const int m0 = blockIdx.x * BM, n0 = blockIdx.y * BN;

    float acc[TM][TN];
#pragma unroll
    for (int a = 0; a < TM; a++)
#pragma unroll
        for (int b = 0; b < TN; b++) acc[a][b] = 0.f;

    for (int k0 = 0; k0 < K; k0 += BK) {
#pragma unroll
        for (int i = 0; i < (BM * BK) / 256; i++) {
            int idx = tid + i * 256;
            int m = idx / BK, k = idx % BK;
            int gm = m0 + m, gk = k0 + k;
            As[k][m] = (gm < M && gk < K) ? A[(size_t)gm * lda + gk] : 0.f;
        }
#pragma unroll
        for (int i = 0; i < (BN * BK) / 256; i++) {
            int idx = tid + i * 256;
            int n = idx / BK, k = idx % BK;
            int gn = n0 + n, gk = k0 + k;
            Bs[k][n] = (gn < N && gk < K) ? B[(size_t)gn * ldb + gk] : 0.f;
        }
        __syncthreads();
#pragma unroll
        for (int k = 0; k < BK; k++) {
            float a[TM], b[TN];
#pragma unroll
            for (int tm = 0; tm < TM; tm++) a[tm] = As[k][ty * TM + tm];
#pragma unroll
            for (int tn = 0; tn < TN; tn++) b[tn] = Bs[k][tx * TN + tn];
#pragma unroll
            for (int tm = 0; tm < TM; tm++)
#pragma unroll
                for (int tn = 0; tn < TN; tn++)
                    acc[tm][tn] += a[tm] * b[tn];
        }
        __syncthreads();
    }
#pragma unroll
    for (int tm = 0; tm < TM; tm++) {
        int gm = m0 + ty * TM + tm;
        if (gm >= M) continue;
#pragma unroll
        for (int tn = 0; tn < TN; tn++) {
            int gn = n0 + tx * TN + tn;
            if (gn >= N) continue;
            float v = acc[tm][tn];
            if (EPI >= EPI_BIAS) v += bias[gn];
            if (EPI == EPI_BIAS_RELU) v = fmaxf(v, 0.f);
            C[(size_t)gm * ldc + gn] = v;
        }
    }
}

// ================= GRU (writes h and fusion[:,0:256]) =================
__global__ void gru_kernel(const float* __restrict__ gi, const float* __restrict__ gh,
                           const float* __restrict__ hin, float* __restrict__ hout,
                           float* __restrict__ fusion, int total)
{
    int idx = blockIdx.x * blockDim.x + threadIdx.x;
    if (idx >= total) return;
    int r = idx >> 8, c = idx & 255;
    size_t base = (size_t)r * 768;
    float ir = gi[base + c], iz = gi[base + 256 + c], in_ = gi[base + 512 + c];
    float hr = gh[base + c], hz = gh[base + 256 + c], hn = gh[base + 512 + c];
    float rg = 1.f / (1.f + expf(-(ir + hr)));
    float zg = 1.f / (1.f + expf(-(iz + hz)));
    float ng = tanhf(in_ + rg * hn);
    float v = (1.f - zg) * ng + zg * hin[idx];
    hout[idx] = v;
    fusion[(size_t)r * 288 + c] = v;
}

// ================= logits post =================
__global__ void __launch_bounds__(256)
logits_post(const float* __restrict__ logits, const float* __restrict__ Wv,
            const float* __restrict__ bv,
            float* __restrict__ out, float* __restrict__ attack,
            float* __restrict__ sender)
{
    __shared__ float Wvs[32 * 29];
    __shared__ float bvs[32];
    __shared__ float vs[8][29];
    int tid = threadIdx.x;
    for (int t = tid; t < 32 * 29; t += 256) Wvs[t] = Wv[t];
    if (tid < 32) bvs[tid] = bv[tid];
    int w = tid >> 5, l = tid & 31;
    int row = blockIdx.x * 8 + w;
    const float* lrow = logits + (size_t)row * 33;
    float al = (l < 27) ? lrow[6 + l] : -INFINITY;
    float mx = al;
#pragma unroll
    for (int o = 16; o > 0; o >>= 1) mx = fmaxf(mx, __shfl_xor_sync(0xffffffffu, mx, o));
    float e = (l < 27) ? expf(al - mx) : 0.f;
    float sum = e;
#pragma unroll
    for (int o = 16; o > 0; o >>= 1) sum += __shfl_xor_sync(0xffffffffu, sum, o);
    float inv = 1.f / sum;
    if (l < 27) vs[w][l] = e * inv;
    if (l == 27) vs[w][27] = 1.0f;
    if (l == 28) vs[w][28] = inv;
    if (l < 27) attack[(size_t)row * 27 + l] = al;
    if (l < 6)  out[(size_t)row * 33 + l] = lrow[l];
    __syncthreads();
    float s = bvs[l];
#pragma unroll
    for (int r = 0; r < 29; r++) s += vs[w][r] * Wvs[l * 29 + r];
    sender[(size_t)row * 32 + l] = s;
}

// ================= qr / qb precompute =================
__global__ void qr_kernel(const float* __restrict__ qk, const float* __restrict__ Wk,
                          const float* __restrict__ bk,
                          float* __restrict__ qr, float* __restrict__ qb, int rows)
{
    int idx = blockIdx.x * blockDim.x + threadIdx.x;
    if (idx >= rows * 4) return;
    int row = idx >> 2, h = idx & 3;
    const float* qp = qk + (size_t)row * 128 + h * 16;
    float acc[5] = {0.f, 0.f, 0.f, 0.f, 0.f};
    float accb = 0.f;
#pragma unroll
    for (int d = 0; d < 16; d++) {
        float qd = qp[d];
        const float* wrow = Wk + (size_t)(h * 16 + d) * (HID + REL) + HID;
#pragma unroll
        for (int r = 0; r < 5; r++) acc[r] += qd * wrow[r];
        accb += qd * bk[h * 16 + d];
    }
#pragma unroll
    for (int r = 0; r < 5; r++) qr[(size_t)row * 20 + h * 5 + r] = acc[r];
    qb[(size_t)row * 4 + h] = accb;
}

// ================= batched attention =================
__global__ void __launch_bounds__(256)
attn_batch(const float* __restrict__ qk, const float* __restrict__ qr,
           const float* __restrict__ qb, const float* __restrict__ rel,
           const float* __restrict__ sender,
           const float* __restrict__ nullk, const float* __restrict__ nullv,
           const float* __restrict__ ln_g, const float* __restrict__ ln_b,
           float* __restrict__ fusion)
{
    __shared__ float qk_s[27 * 128];
    __shared__ float sender_s[27 * 32];
    __shared__ float rel_s[27 * 27 * 5];
    __shared__ float qr_s[27 * 20];
    __shared__ float qb_s[27 * 4];
    __shared__ float nk_s[64];
    __shared__ float nv_s[32];
    __shared__ float sc[27 * 112];

    const int b = blockIdx.x;
    const int tid = threadIdx.x;
    const size_t rbase = (size_t)b * 27;

    for (int t = tid; t < 27 * 128; t += 256) qk_s[t] = qk[rbase * 128 + t];
    for (int t = tid; t < 27 * 32; t += 256) sender_s[t] = sender[rbase * 32 + t];
    for (int t = tid; t < 27 * 27 * 5; t += 256) rel_s[t] = rel[(size_t)b * (27 * 27 * 5) + t];
    for (int t = tid; t < 27 * 20; t += 256) qr_s[t] = qr[rbase * 20 + t];
    for (int t = tid; t < 27 * 4; t += 256) qb_s[t] = qb[rbase * 4 + t];
    if (tid < 64) nk_s[tid] = nullk[tid];
    if (tid >= 64 && tid < 96) nv_s[tid - 64] = nullv[tid - 64];
    __syncthreads();

    for (int t = tid; t < 27 * 112; t += 256) {
        int i = t / 112;
        int rem = t - i * 112;
        int j = rem >> 2, h = rem & 3;
        float s;
        if (j == 27) {
            float d = 0.f;
#pragma unroll
            for (int dd = 0; dd < 16; dd++) d += qk_s[i * 128 + h * 16 + dd] * nk_s[h * 16 + dd];
            s = 0.25f * d;
        } else if (j == i) {
            s = NEG;
        } else {
            float d = qb_s[i * 4 + h];
#pragma unroll
            for (int dd = 0; dd < 16; dd++)
                d += qk_s[i * 128 + h * 16 + dd] * qk_s[j * 128 + 64 + h * 16 + dd];
            const float* rr = &rel_s[(i * 27 + j) * 5];
#pragma unroll
            for (int r = 0; r < 5; r++) d += qr_s[i * 20 + h * 5 + r] * rr[r];
            s = 0.25f * d;
        }
        sc[t] = s;
    }
    __syncthreads();

    for (int t = tid; t < 108; t += 256) {
        int i = t >> 2, h = t & 3;
        float* scp = &sc[i * 112 + h];
        float t0 = -INFINITY, t1 = -INFINITY, t2 = -INFINITY, t3 = -INFINITY;
#pragma unroll
        for (int j = 0; j < 28; j++) {
            float v = scp[j * 4];
            if (v > t0)      { t3 = t2; t2 = t1; t1 = t0; t0 = v; }
            else if (v > t1) { t3 = t2; t2 = t1; t1 = v; }
            else if (v > t2) { t3 = t2; t2 = v; }
            else if (v > t3) { t3 = v; }
        }
        float thr = t3, mxv = t0, sum = 0.f;
        float e[28];
#pragma unroll
        for (int j = 0; j < 28; j++) {
            float v = scp[j * 4];
            float ev = (v >= thr) ? expf(v - mxv) : 0.f;
            e[j] = ev; sum += ev;
        }
        float inv = 1.f / sum;
#pragma unroll
        for (int j = 0; j < 28; j++) scp[j * 4] = e[j] * inv;
    }
    __syncthreads();

    int w = tid >> 5, l = tid & 31;
    int h = l >> 3;
    for (int i = w; i < 27; i += 8) {
        const float* scp = &sc[i * 112];
        float m = scp[108 + h] * nv_s[l];
#pragma unroll
        for (int j = 0; j < 27; j++) m += scp[j * 4 + h] * sender_s[j * 32 + l];
        float s = m, s2 = m * m;
#pragma unroll
        for (int o = 16; o > 0; o >>= 1) {
            s  += __shfl_xor_sync(0xffffffffu, s, o);
            s2 += __shfl_xor_sync(0xffffffffu, s2, o);
        }
        float mu = s * (1.f / 32.f);
        float var = s2 * (1.f / 32.f) - mu * mu;
        float nm = (m - mu) * rsqrtf(var + 1e-5f) * ln_g[l] + ln_b[l];
        fusion[(rbase + i) * 288 + 256 + l] = nm;
    }
}

// ================= final =================
__global__ void __launch_bounds__(256)
final_kernel(const float* __restrict__ gd,
             const float* __restrict__ Wg2, const float* __restrict__ bg2,
             const float* __restrict__ Wd2, const float* __restrict__ bd2,
             const float* __restrict__ attack,
             float* __restrict__ out)
{
    __shared__ float Wd2s[256 * 28];
    __shared__ float wg2s[256];
    int tid = threadIdx.x;
    for (int t = tid; t < 27 * 256; t += 256) {
        int l = t >> 8, k = t & 255;
        Wd2s[k * 28 + l] = Wd2[t];
    }
    if (tid < 256) wg2s[tid] = Wg2[tid];
    __syncthreads();

    int w = tid >> 5, l = tid & 31;
    int row = blockIdx.x * 8 + w;
    const float* g1r = gd + (size_t)row * 512;
    const float* d1r = g1r + 256;
    float gs = 0.f;
#pragma unroll
    for (int i = 0; i < 8; i++) gs += g1r[l + i * 32] * wg2s[l + i * 32];
#pragma unroll
    for (int o = 16; o > 0; o >>= 1) gs += __shfl_xor_sync(0xffffffffu, gs, o);
    float gate = 1.f / (1.f + expf(-(gs + bg2[0])));
    if (l < 27) {
        float d = bd2[l];
#pragma unroll 8
        for (int k = 0; k < 256; k++) d += d1r[k] * Wd2s[k * 28 + l];
        out[(size_t)row * 33 + 6 + l] = attack[(size_t)row * 27 + l] + FUSE_SCALE * gate * d;
    }
}

// ================= host launcher =================
static float* sym(const void* symbol)
{
    void* p = nullptr;
    cudaGetSymbolAddress(&p, symbol);
    return (float*)p;
}
static __nv_bfloat16* symb(const void* symbol)
{
    void* p = nullptr;
    cudaGetSymbolAddress(&p, symbol);
    return (__nv_bfloat16*)p;
}

extern "C" void kernel_launch(void* const* d_in, const int* in_sizes, int n_in,
                              void* d_out, int out_size)
{
    const float* inputs = (const float*)d_in[0];
    const float* hidden = (const float*)d_in[1];
    const float* rel    = (const float*)d_in[2];
    const float* W1     = (const float*)d_in[3];
    const float* b1     = (const float*)d_in[4];
    const float* Wih    = (const float*)d_in[5];
    const float* bih    = (const float*)d_in[6];
    const float* Whh    = (const float*)d_in[7];
    const float* bhh    = (const float*)d_in[8];
    const float* Wp1    = (const float*)d_in[9];
    const float* bp1    = (const float*)d_in[10];
    const float* Wp2    = (const float*)d_in[11];
    const float* bp2    = (const float*)d_in[12];
    const float* Wq     = (const float*)d_in[13];
    const float* bq     = (const float*)d_in[14];
    const float* Wk     = (const float*)d_in[15];
    const float* bk     = (const float*)d_in[16];
    const float* Wv     = (const float*)d_in[17];
    const float* bv     = (const float*)d_in[18];
    const float* ln_g   = (const float*)d_in[19];
    const float* ln_b   = (const float*)d_in[20];
    const float* Wg1    = (const float*)d_in[21];
    const float* bg1    = (const float*)d_in[22];
    const float* Wg2    = (const float*)d_in[23];
    const float* bg2    = (const float*)d_in[24];
    const float* Wd1    = (const float*)d_in[25];
    const float* bd1    = (const float*)d_in[26];
    const float* Wd2    = (const float*)d_in[27];
    const float* bd2    = (const float*)d_in[28];
    const float* nullk  = (const float*)d_in[29];
    const float* nullv  = (const float*)d_in[30];

    const int rows = in_sizes[0] / INW;    // 27648
    const int bs = rows / Nn;
    float* out = (float*)d_out;

    float* px      = sym(g_x);
    float* pgi     = sym(g_gi);
    float* pgh     = sym(g_gh);
    float* pp      = sym(g_p);
    float* plogits = sym(g_logits);
    float* pattack = sym(g_attack);
    float* psender = sym(g_sender);
    float* pqk     = sym(g_qk);
    float* pqr     = sym(g_qr);
    float* pqb     = sym(g_qb);
    float* pfusion = sym(g_fusion);
    float* pgd     = sym(g_gd);
    float* pbqk    = sym(g_bqk);
    float* pbgd    = sym(g_bgd);

    __nv_bfloat16 *pW1h = symb(g_W1h),  *pW1l = symb(g_W1l);
    __nv_bfloat16 *pWihh = symb(g_Wihh), *pWihl = symb(g_Wihl);
    __nv_bfloat16 *pWhhh = symb(g_Whhh), *pWhhl = symb(g_Whhl);
    __nv_bfloat16 *pWp1h = symb(g_Wp1h), *pWp1l = symb(g_Wp1l);
    __nv_bfloat16 *pBqkh = symb(g_Bqkh), *pBqkl = symb(g_Bqkl);
    __nv_bfloat16 *pBgdh = symb(g_Bgdh), *pBgdl = symb(g_Bgdl);

    float* hout = (out_size >= rows * (NA + HID)) ? out + (size_t)rows * NA : sym(g_hfb);

    const int MB = rows / 128;   // 216

    cudaFuncSetAttribute((const void*)gemm_mma<EPI_BIAS>,      cudaFuncAttributeMaxDynamicSharedMemorySize, GSMEM);
    cudaFuncSetAttribute((const void*)gemm_mma<EPI_BIAS_RELU>, cudaFuncAttributeMaxDynamicSharedMemorySize, GSMEM);

    // --- single prep kernel: all weight splits/packs ---
    prep_all<<<(STOT + 255) / 256, 256>>>(W1, Wih, Whh, Wp1, Wq, Wk, Wg1, Wd1, bq, bg1, bd1,
                                          pW1h, pW1l, pWihh, pWihl, pWhhh, pWhhl, pWp1h, pWp1l,
                                          pBqkh, pBqkl, pBgdh, pBgdl, pbqk, pbgd);

    // 1. x = relu(inputs @ W1^T + b1)            K=322 -> 11 chunks
    gemm_mma<EPI_BIAS_RELU><<<dim3(MB, 2), 256, GSMEM>>>(inputs, INW, pW1h, pW1l, 352, b1, px, 256, 322, 11);
    // 2. gi, gh                                  K=256 -> 8 chunks
    gemm_mma<EPI_BIAS><<<dim3(MB, 6), 256, GSMEM>>>(px, 256, pWihh, pWihl, 256, bih, pgi, 768, 256, 8);
    gemm_mma<EPI_BIAS><<<dim3(MB, 6), 256, GSMEM>>>(hidden, 256, pWhhh, pWhhl, 256, bhh, pgh, 768, 256, 8);
    // 3. GRU -> h (+ fusion[:,0:256])
    gru_kernel<<<(rows * 256 + 255) / 256, 256>>>(pgi, pgh, hidden, hout, pfusion, rows * 256);
    // 4. p = relu(h @ Wp1^T + bp1); logits = p @ Wp2^T + bp2
    gemm_mma<EPI_BIAS_RELU><<<dim3(MB, 2), 256, GSMEM>>>(hout, 256, pWp1h, pWp1l, 256, bp1, pp, 256, 256, 8);
    gemm_tn<EPI_BIAS><<<dim3(MB, 1), 256>>>(pp, 256, Wp2, 256, bp2, plogits, NA, rows, NA, 256);
    // 5. softmax / sender values / base logits
    logits_post<<<rows / 8, 256>>>(plogits, Wv, bv, out, pattack, psender);
    // 6. [q | key_h] = h @ [Wq; Wk_h]^T + [bq; 0]
    gemm_mma<EPI_BIAS><<<dim3(MB, 1), 256, GSMEM>>>(hout, 256, pBqkh, pBqkl, 256, pbqk, pqk, 128, 256, 8);
    // 7. qr, qb
    qr_kernel<<<(rows * 4 + 127) / 128, 128>>>(pqk, Wk, bk, pqr, pqb, rows);
    // 8. attention (batched) -> fusion[:,256:288]
    attn_batch<<<bs, 256>>>(pqk, pqr, pqb, rel, psender, nullk, nullv, ln_g, ln_b, pfusion);
    // 9. [g1 | d1] = relu(fusion @ [Wg1; Wd1]^T + [bg1; bd1])   K=288 -> 9 chunks
    gemm_mma<EPI_BIAS_RELU><<<dim3(MB, 4), 256, GSMEM>>>(pfusion, 288, pBgdh, pBgdl, 288, pbgd, pgd, 512, 288, 9);
    // 10. gate, delta, fused output
    final_kernel<<<rows / 8, 256>>>(pgd, Wg2, bg2, Wd2, bd2, pattack, out);
}

// round 8
// speedup vs baseline: 2.9987x; 1.0775x over previous
#include <cuda_runtime.h>
#include <cuda_bf16.h>
#include <math.h>
#include <stdint.h>

// ---------------- problem constants ----------------
#define Nn   27
#define NA   33
#define HID  256
#define REL  5
#define INW  322
#define FUSE_SCALE 0.1f
#define NEG  (-10000000000.0f)
#define MAXROWS 27648

// ---------------- scratch (device globals) -------------
__device__ float g_gi    [MAXROWS * 768];
__device__ float g_gh    [MAXROWS * 768];
__device__ float g_p     [MAXROWS * 256];
__device__ float g_logits[MAXROWS * 33];
__device__ float g_attack[MAXROWS * 27];
__device__ float g_sender[MAXROWS * 32];
__device__ float g_qk    [MAXROWS * 128];
__device__ float g_qr    [MAXROWS * 20];
__device__ float g_qb    [MAXROWS * 4];
__device__ float g_gd    [MAXROWS * 512];
__device__ float g_hfb   [MAXROWS * 256];
__device__ float g_bqk   [128];
__device__ float g_bgd   [512];
// bf16 hi/lo weight planes (K padded to 32-multiples)
__device__ __nv_bfloat16 g_W1h [256 * 352],  g_W1l [256 * 352];
__device__ __nv_bfloat16 g_Wihh[768 * 256],  g_Wihl[768 * 256];
__device__ __nv_bfloat16 g_Whhh[768 * 256],  g_Whhl[768 * 256];
__device__ __nv_bfloat16 g_Wp1h[256 * 256],  g_Wp1l[256 * 256];
__device__ __nv_bfloat16 g_Bqkh[128 * 256],  g_Bqkl[128 * 256];
__device__ __nv_bfloat16 g_Bgdh[512 * 288],  g_Bgdl[512 * 288];
// bf16 hi/lo activation planes
__device__ __nv_bfloat16 g_inh [MAXROWS * 352], g_inl [MAXROWS * 352];
__device__ __nv_bfloat16 g_hidh[MAXROWS * 256], g_hidl[MAXROWS * 256];
__device__ __nv_bfloat16 g_xh  [MAXROWS * 256], g_xl  [MAXROWS * 256];
__device__ __nv_bfloat16 g_hh  [MAXROWS * 256], g_hl  [MAXROWS * 256];
__device__ __nv_bfloat16 g_fh  [MAXROWS * 288], g_fl  [MAXROWS * 288];

#define EPI_BIAS 1
#define EPI_BIAS_RELU 2
#define EPI_PLANES_RELU 3

// =================== helpers ===============
__device__ __forceinline__ uint32_t smem_u32(const void* p) {
    uint32_t a;
    asm("{ .reg .u64 t; cvta.to.shared.u64 t, %1; cvt.u32.u64 %0, t; }" : "=r"(a) : "l"(p));
    return a;
}
#define CP_ASYNC16(dst, src) \
    asm volatile("cp.async.cg.shared.global [%0], [%1], 16;" :: "r"(dst), "l"(src) : "memory")
#define CP_COMMIT() asm volatile("cp.async.commit_group;" ::: "memory")
#define CP_WAIT0()  asm volatile("cp.async.wait_group 0;" ::: "memory")

__device__ __forceinline__ void ldsm4(uint32_t* d, uint32_t addr) {
    asm volatile("ldmatrix.sync.aligned.m8n8.x4.shared.b16 {%0,%1,%2,%3}, [%4];"
                 : "=r"(d[0]), "=r"(d[1]), "=r"(d[2]), "=r"(d[3]) : "r"(addr));
}
__device__ __forceinline__ void mma16816(float* c, const uint32_t* a, const uint32_t* b) {
    asm volatile("mma.sync.aligned.m16n8k16.row.col.f32.bf16.bf16.f32 "
                 "{%0,%1,%2,%3}, {%4,%5,%6,%7}, {%8,%9}, {%0,%1,%2,%3};"
                 : "+f"(c[0]), "+f"(c[1]), "+f"(c[2]), "+f"(c[3])
                 : "r"(a[0]), "r"(a[1]), "r"(a[2]), "r"(a[3]), "r"(b[0]), "r"(b[1]));
}

// =================== pipelined mma.sync bf16 3-pass GEMM (all-plane cp.async) =========
// C[M,N] = (Ahi+Alo)[M,Kpad] @ (Bhi+Blo)[N,Kpad]^T (+bias)(relu)
// Block tile 128x128, 8 warps (2m x 4n), warp tile 64x32, BK=32, 2-stage cp.async.
// Plane: 128 rows x 40 bf16 (80B stride, conflict-free LDSM). 2 CTAs/SM.
#define PLNB   10240              // plane bytes (128*80)
#define STAGEB (4 * PLNB)         // Ahi,Alo,Bhi,Blo = 40960
#define GSMEM  (2 * STAGEB)       // 81920

template<int EPI>
__global__ void __launch_bounds__(256, 2)
gemm_mma(const __nv_bfloat16* __restrict__ Ahi, const __nv_bfloat16* __restrict__ Alo, int lda,
         const __nv_bfloat16* __restrict__ Bhi, const __nv_bfloat16* __restrict__ Blo, int ldb,
         const float* __restrict__ bias,
         float* __restrict__ C, __nv_bfloat16* __restrict__ Ch, __nv_bfloat16* __restrict__ Cl,
         int ldc, int nChunks)
{
    extern __shared__ __align__(16) char smx[];

    const int tid = threadIdx.x;
    const int wid = tid >> 5, lane = tid & 31;
    const int m0 = blockIdx.x * 128, n0 = blockIdx.y * 128;
    const int r = tid >> 1, hf = tid & 1;

    const uint32_t sbase = smem_u32(smx);
    const uint32_t stO = (uint32_t)r * 80 + hf * 32;   // store offset within a plane

    const int warp_m = (wid & 1) * 64, warp_n = (wid >> 1) * 32;
    const uint32_t aOff = (uint32_t)(warp_m + (lane & 15)) * 80 + (lane >> 4) * 16;
    const uint32_t bRow = (uint32_t)(warp_n + (lane & 7) + ((lane >> 4) << 3));
    const uint32_t bOff = bRow * 80 + ((lane >> 3) & 1) * 16;

    float c[4][4][4];
#pragma unroll
    for (int mt = 0; mt < 4; mt++)
#pragma unroll
        for (int nt = 0; nt < 4; nt++)
#pragma unroll
            for (int q = 0; q < 4; q++) c[mt][nt][q] = 0.f;

    const __nv_bfloat16* ArH = Ahi + (size_t)(m0 + r) * lda + hf * 16;
    const __nv_bfloat16* ArL = Alo + (size_t)(m0 + r) * lda + hf * 16;
    const __nv_bfloat16* BrH = Bhi + (size_t)(n0 + r) * ldb + hf * 16;
    const __nv_bfloat16* BrL = Blo + (size_t)(n0 + r) * ldb + hf * 16;

    auto issue = [&](int ch, int st) {
        const int kc = ch * 32;
        const uint32_t base = sbase + st * STAGEB;
        CP_ASYNC16(base + stO,                ArH + kc);
        CP_ASYNC16(base + stO + 16,           ArH + kc + 8);
        CP_ASYNC16(base + PLNB + stO,         ArL + kc);
        CP_ASYNC16(base + PLNB + stO + 16,    ArL + kc + 8);
        CP_ASYNC16(base + 2 * PLNB + stO,     BrH + kc);
        CP_ASYNC16(base + 2 * PLNB + stO + 16, BrH + kc + 8);
        CP_ASYNC16(base + 3 * PLNB + stO,     BrL + kc);
        CP_ASYNC16(base + 3 * PLNB + stO + 16, BrL + kc + 8);
        CP_COMMIT();
    };

    issue(0, 0);
    CP_WAIT0();
    __syncthreads();

    for (int ch = 0; ch < nChunks; ch++) {
        const int cur = ch & 1, nxt = cur ^ 1;
        const bool more = (ch + 1 < nChunks);
        if (more) issue(ch + 1, nxt);

        const uint32_t base = sbase + cur * STAGEB;
        const uint32_t sAhi = base, sAlo = base + PLNB;
        const uint32_t sBhi = base + 2 * PLNB, sBlo = base + 3 * PLNB;
#pragma unroll
        for (int ks = 0; ks < 2; ks++) {
            const uint32_t ko = ks * 32;
            uint32_t aF[4][4], bF[4][2];

            // pass 1: Ahi x Bhi
#pragma unroll
            for (int mt = 0; mt < 4; mt++) ldsm4(aF[mt], sAhi + aOff + ko + mt * (16 * 80));
#pragma unroll
            for (int p = 0; p < 2; p++) {
                uint32_t t[4];
                ldsm4(t, sBhi + bOff + ko + p * (16 * 80));
                bF[2 * p][0] = t[0]; bF[2 * p][1] = t[1];
                bF[2 * p + 1][0] = t[2]; bF[2 * p + 1][1] = t[3];
            }
#pragma unroll
            for (int mt = 0; mt < 4; mt++)
#pragma unroll
                for (int nt = 0; nt < 4; nt++) mma16816(c[mt][nt], aF[mt], bF[nt]);

            // pass 2: Ahi x Blo (reuse A frags)
#pragma unroll
            for (int p = 0; p < 2; p++) {
                uint32_t t[4];
                ldsm4(t, sBlo + bOff + ko + p * (16 * 80));
                bF[2 * p][0] = t[0]; bF[2 * p][1] = t[1];
                bF[2 * p + 1][0] = t[2]; bF[2 * p + 1][1] = t[3];
            }
#pragma unroll
            for (int mt = 0; mt < 4; mt++)
#pragma unroll
                for (int nt = 0; nt < 4; nt++) mma16816(c[mt][nt], aF[mt], bF[nt]);

            // pass 3: Alo x Bhi
#pragma unroll
            for (int mt = 0; mt < 4; mt++) ldsm4(aF[mt], sAlo + aOff + ko + mt * (16 * 80));
#pragma unroll
            for (int p = 0; p < 2; p++) {
                uint32_t t[4];
                ldsm4(t, sBhi + bOff + ko + p * (16 * 80));
                bF[2 * p][0] = t[0]; bF[2 * p][1] = t[1];
                bF[2 * p + 1][0] = t[2]; bF[2 * p + 1][1] = t[3];
            }
#pragma unroll
            for (int mt = 0; mt < 4; mt++)
#pragma unroll
                for (int nt = 0; nt < 4; nt++) mma16816(c[mt][nt], aF[mt], bF[nt]);
        }

        if (more) CP_WAIT0();
        __syncthreads();
    }

    // ---- epilogue ----
#pragma unroll
    for (int mt = 0; mt < 4; mt++) {
        const int row = m0 + warp_m + mt * 16 + (lane >> 2);
#pragma unroll
        for (int nt = 0; nt < 4; nt++) {
            const int col = n0 + warp_n + nt * 8 + (lane & 3) * 2;
            const float b0 = bias[col], b1 = bias[col + 1];
            float v0 = c[mt][nt][0] + b0, v1 = c[mt][nt][1] + b1;
            float v2 = c[mt][nt][2] + b0, v3 = c[mt][nt][3] + b1;
            if (EPI != EPI_BIAS) {
                v0 = fmaxf(v0, 0.f); v1 = fmaxf(v1, 0.f);
                v2 = fmaxf(v2, 0.f); v3 = fmaxf(v3, 0.f);
            }
            if (EPI == EPI_PLANES_RELU) {
                __nv_bfloat16 h0 = __float2bfloat16(v0), h1 = __float2bfloat16(v1);
                __nv_bfloat16 h2 = __float2bfloat16(v2), h3 = __float2bfloat16(v3);
                *(__nv_bfloat162*)(Ch + (size_t)row * ldc + col) = __nv_bfloat162(h0, h1);
                *(__nv_bfloat162*)(Ch + (size_t)(row + 8) * ldc + col) = __nv_bfloat162(h2, h3);
                *(__nv_bfloat162*)(Cl + (size_t)row * ldc + col) =
                    __nv_bfloat162(__float2bfloat16(v0 - __bfloat162float(h0)),
                                   __float2bfloat16(v1 - __bfloat162float(h1)));
                *(__nv_bfloat162*)(Cl + (size_t)(row + 8) * ldc + col) =
                    __nv_bfloat162(__float2bfloat16(v2 - __bfloat162float(h2)),
                                   __float2bfloat16(v3 - __bfloat162float(h3)));
            } else {
                *(float2*)(C + (size_t)row * ldc + col) = make_float2(v0, v1);
                *(float2*)(C + (size_t)(row + 8) * ldc + col) = make_float2(v2, v3);
            }
        }
    }
}

// ================= activation split: fp32 [M,K] -> bf16 hi/lo [M,Kpad] =================
__global__ void conv_split(const float* __restrict__ src, __nv_bfloat16* __restrict__ hi,
                           __nv_bfloat16* __restrict__ lo, int Mrows, int K, int Kpad)
{
    int idx = blockIdx.x * blockDim.x + threadIdx.x;
    if (idx >= Mrows * Kpad) return;
    int m = idx / Kpad, k = idx - m * Kpad;
    float v = (k < K) ? src[(size_t)m * K + k] : 0.f;
    __nv_bfloat16 h = __float2bfloat16(v);
    hi[idx] = h;
    lo[idx] = __float2bfloat16(v - __bfloat162float(h));
}

// ================= one-shot weight prep =================
#define S0 (256*352)
#define S1 (768*256)
#define S2 (768*256)
#define S3 (256*256)
#define S4 (128*256)
#define S5 (512*288)
#define S6 (128+512)
#define STOT (S0+S1+S2+S3+S4+S5+S6)

__global__ void prep_all(const float* __restrict__ W1,  const float* __restrict__ Wih,
                         const float* __restrict__ Whh, const float* __restrict__ Wp1,
                         const float* __restrict__ Wq,  const float* __restrict__ Wk,
                         const float* __restrict__ Wg1, const float* __restrict__ Wd1,
                         const float* __restrict__ bq,  const float* __restrict__ bg1,
                         const float* __restrict__ bd1,
                         __nv_bfloat16* __restrict__ W1h,  __nv_bfloat16* __restrict__ W1l,
                         __nv_bfloat16* __restrict__ Wihh, __nv_bfloat16* __restrict__ Wihl,
                         __nv_bfloat16* __restrict__ Whhh, __nv_bfloat16* __restrict__ Whhl,
                         __nv_bfloat16* __restrict__ Wp1h, __nv_bfloat16* __restrict__ Wp1l,
                         __nv_bfloat16* __restrict__ Bqkh, __nv_bfloat16* __restrict__ Bqkl,
                         __nv_bfloat16* __restrict__ Bgdh, __nv_bfloat16* __restrict__ Bgdl,
                         float* __restrict__ pbqk, float* __restrict__ pbgd)
{
    int idx = blockIdx.x * blockDim.x + threadIdx.x;
    if (idx >= STOT) return;
    float src;
    __nv_bfloat16 *hi, *lo;
    int off;
    if (idx < S0) {
        off = idx;
        int k = off % 352;
        src = (k < 322) ? W1[(off / 352) * 322 + k] : 0.f;
        hi = W1h; lo = W1l;
    } else if (idx < S0 + S1) {
        off = idx - S0; src = Wih[off]; hi = Wihh; lo = Wihl;
    } else if (idx < S0 + S1 + S2) {
        off = idx - S0 - S1; src = Whh[off]; hi = Whhh; lo = Whhl;
    } else if (idx < S0 + S1 + S2 + S3) {
        off = idx - S0 - S1 - S2; src = Wp1[off]; hi = Wp1h; lo = Wp1l;
    } else if (idx < S0 + S1 + S2 + S3 + S4) {
        off = idx - S0 - S1 - S2 - S3;
        int rr = off >> 8, cc = off & 255;
        src = (rr < 64) ? Wq[rr * 256 + cc] : Wk[(size_t)(rr - 64) * (HID + REL) + cc];
        hi = Bqkh; lo = Bqkl;
    } else if (idx < S0 + S1 + S2 + S3 + S4 + S5) {
        off = idx - S0 - S1 - S2 - S3 - S4;
        int rr = off / 288, cc = off % 288;
        src = (rr < 256) ? Wg1[rr * 288 + cc] : Wd1[(rr - 256) * 288 + cc];
        hi = Bgdh; lo = Bgdl;
    } else {
        off = idx - (S0 + S1 + S2 + S3 + S4 + S5);
        if (off < 128) pbqk[off] = (off < 64) ? bq[off] : 0.f;
        else { int o = off - 128; pbgd[o] = (o < 256) ? bg1[o] : bd1[o - 256]; }
        return;
    }
    __nv_bfloat16 h = __float2bfloat16(src);
    hi[off] = h;
    lo[off] = __float2bfloat16(src - __bfloat162float(h));
}

// ================= generic GEMM (Wp2, N=33 only) =================
template<int EPI>
__global__ void __launch_bounds__(256)
gemm_tn(const float* __restrict__ A, int lda,
        const float* __restrict__ B, int ldb,
        const float* __restrict__ bias,
        float* __restrict__ C, int ldc, int M, int N, int K)
{
    constexpr int BM = 128, BN = 64, BK = 16, TM = 8, TN = 4;
    __shared__ float As[BK][BM + 4];
    __shared__ float Bs[BK][BN + 4];
    const int tid = threadIdx.x;
    const int tx = tid & 15, ty = tid >> 4;
    const int m0 = blockIdx.x * BM, n0 = blockIdx.y * BN;

    float acc[TM][TN];
#pragma unroll
    for (int a = 0; a < TM; a++)
#pragma unroll
        for (int b = 0; b < TN; b++) acc[a][b] = 0.f;

    for (int k0 = 0; k0 < K; k0 += BK) {
#pragma unroll
        for (int i = 0; i < (BM * BK) / 256; i++) {
            int idx = tid + i * 256;
            int m = idx / BK, k = idx % BK;
            int gm = m0 + m, gk = k0 + k;
            As[k][m] = (gm < M && gk < K) ? A[(size_t)gm * lda + gk] : 0.f;
        }
#pragma unroll
        for (int i = 0; i < (BN * BK) / 256; i++) {
            int idx = tid + i * 256;
            int n = idx / BK, k = idx % BK;
            int gn = n0 + n, gk = k0 + k;
            Bs[k][n] = (gn < N && gk < K) ? B[(size_t)gn * ldb + gk] : 0.f;
        }
        __syncthreads();
#pragma unroll
        for (int k = 0; k < BK; k++) {
            float a[TM], b[TN];
#pragma unroll
            for (int tm = 0; tm < TM; tm++) a[tm] = As[k][ty * TM + tm];
#pragma unroll
            for (int tn = 0; tn < TN; tn++) b[tn] = Bs[k][tx * TN + tn];
#pragma unroll
            for (int tm = 0; tm < TM; tm++)
#pragma unroll
                for (int tn = 0; tn < TN; tn++)
                    acc[tm][tn] += a[tm] * b[tn];
        }
        __syncthreads();
    }
#pragma unroll
    for (int tm = 0; tm < TM; tm++) {
        int gm = m0 + ty * TM + tm;
        if (gm >= M) continue;
#pragma unroll
        for (int tn = 0; tn < TN; tn++) {
            int gn = n0 + tx * TN + tn;
            if (gn >= N) continue;
            float v = acc[tm][tn];
            if (EPI >= EPI_BIAS) v += bias[gn];
            if (EPI == EPI_BIAS_RELU) v = fmaxf(v, 0.f);
            C[(size_t)gm * ldc + gn] = v;
        }
    }
}

// ================= GRU: writes h (fp32), h-planes, fusion-planes[:,0:256] =============
__global__ void gru_kernel(const float* __restrict__ gi, const float* __restrict__ gh,
                           const float* __restrict__ hin, float* __restrict__ hout,
                           __nv_bfloat16* __restrict__ hh, __nv_bfloat16* __restrict__ hl,
                           __nv_bfloat16* __restrict__ fh, __nv_bfloat16* __restrict__ fl,
                           int total)
{
    int idx = blockIdx.x * blockDim.x + threadIdx.x;
    if (idx >= total) return;
    int r = idx >> 8, c = idx & 255;
    size_t base = (size_t)r * 768;
    float ir = gi[base + c], iz = gi[base + 256 + c], in_ = gi[base + 512 + c];
    float hr = gh[base + c], hz = gh[base + 256 + c], hn = gh[base + 512 + c];
    float rg = 1.f / (1.f + expf(-(ir + hr)));
    float zg = 1.f / (1.f + expf(-(iz + hz)));
    float ng = tanhf(in_ + rg * hn);
    float v = (1.f - zg) * ng + zg * hin[idx];
    hout[idx] = v;
    __nv_bfloat16 h = __float2bfloat16(v);
    __nv_bfloat16 l = __float2bfloat16(v - __bfloat162float(h));
    hh[idx] = h; hl[idx] = l;
    size_t fidx = (size_t)r * 288 + c;
    fh[fidx] = h; fl[fidx] = l;
}

// ================= logits post =================
__global__ void __launch_bounds__(256)
logits_post(const float* __restrict__ logits, const float* __restrict__ Wv,
            const float* __restrict__ bv,
            float* __restrict__ out, float* __restrict__ attack,
            float* __restrict__ sender)
{
    __shared__ float Wvs[32 * 29];
    __shared__ float bvs[32];
    __shared__ float vs[8][29];
    int tid = threadIdx.x;
    for (int t = tid; t < 32 * 29; t += 256) Wvs[t] = Wv[t];
    if (tid < 32) bvs[tid] = bv[tid];
    int w = tid >> 5, l = tid & 31;
    int row = blockIdx.x * 8 + w;
    const float* lrow = logits + (size_t)row * 33;
    float al = (l < 27) ? lrow[6 + l] : -INFINITY;
    float mx = al;
#pragma unroll
    for (int o = 16; o > 0; o >>= 1) mx = fmaxf(mx, __shfl_xor_sync(0xffffffffu, mx, o));
    float e = (l < 27) ? expf(al - mx) : 0.f;
    float sum = e;
#pragma unroll
    for (int o = 16; o > 0; o >>= 1) sum += __shfl_xor_sync(0xffffffffu, sum, o);
    float inv = 1.f / sum;
    if (l < 27) vs[w][l] = e * inv;
    if (l == 27) vs[w][27] = 1.0f;
    if (l == 28) vs[w][28] = inv;
    if (l < 27) attack[(size_t)row * 27 + l] = al;
    if (l < 6)  out[(size_t)row * 33 + l] = lrow[l];
    __syncthreads();
    float s = bvs[l];
#pragma unroll
    for (int r = 0; r < 29; r++) s += vs[w][r] * Wvs[l * 29 + r];
    sender[(size_t)row * 32 + l] = s;
}

// ================= qr / qb precompute =================
__global__ void qr_kernel(const float* __restrict__ qk, const float* __restrict__ Wk,
                          const float* __restrict__ bk,
                          float* __restrict__ qr, float* __restrict__ qb, int rows)
{
    int idx = blockIdx.x * blockDim.x + threadIdx.x;
    if (idx >= rows * 4) return;
    int row = idx >> 2, h = idx & 3;
    const float* qp = qk + (size_t)row * 128 + h * 16;
    float acc[5] = {0.f, 0.f, 0.f, 0.f, 0.f};
    float accb = 0.f;
#pragma unroll
    for (int d = 0; d < 16; d++) {
        float qd = qp[d];
        const float* wrow = Wk + (size_t)(h * 16 + d) * (HID + REL) + HID;
#pragma unroll
        for (int r = 0; r < 5; r++) acc[r] += qd * wrow[r];
        accb += qd * bk[h * 16 + d];
    }
#pragma unroll
    for (int r = 0; r < 5; r++) qr[(size_t)row * 20 + h * 5 + r] = acc[r];
    qb[(size_t)row * 4 + h] = accb;
}

// ================= batched attention -> fusion planes cols 256..287 =================
__global__ void __launch_bounds__(256)
attn_batch(const float* __restrict__ qk, const float* __restrict__ qr,
           const float* __restrict__ qb, const float* __restrict__ rel,
           const float* __restrict__ sender,
           const float* __restrict__ nullk, const float* __restrict__ nullv,
           const float* __restrict__ ln_g, const float* __restrict__ ln_b,
           __nv_bfloat16* __restrict__ fh, __nv_bfloat16* __restrict__ fl)
{
    __shared__ float qk_s[27 * 128];
    __shared__ float sender_s[27 * 32];
    __shared__ float rel_s[27 * 27 * 5];
    __shared__ float qr_s[27 * 20];
    __shared__ float qb_s[27 * 4];
    __shared__ float nk_s[64];
    __shared__ float nv_s[32];
    __shared__ float sc[27 * 112];

    const int b = blockIdx.x;
    const int tid = threadIdx.x;
    const size_t rbase = (size_t)b * 27;

    for (int t = tid; t < 27 * 128; t += 256) qk_s[t] = qk[rbase * 128 + t];
    for (int t = tid; t < 27 * 32; t += 256) sender_s[t] = sender[rbase * 32 + t];
    for (int t = tid; t < 27 * 27 * 5; t += 256) rel_s[t] = rel[(size_t)b * (27 * 27 * 5) + t];
    for (int t = tid; t < 27 * 20; t += 256) qr_s[t] = qr[rbase * 20 + t];
    for (int t = tid; t < 27 * 4; t += 256) qb_s[t] = qb[rbase * 4 + t];
    if (tid < 64) nk_s[tid] = nullk[tid];
    if (tid >= 64 && tid < 96) nv_s[tid - 64] = nullv[tid - 64];
    __syncthreads();

    for (int t = tid; t < 27 * 112; t += 256) {
        int i = t / 112;
        int rem = t - i * 112;
        int j = rem >> 2, h = rem & 3;
        float s;
        if (j == 27) {
            float d = 0.f;
#pragma unroll
            for (int dd = 0; dd < 16; dd++) d += qk_s[i * 128 + h * 16 + dd] * nk_s[h * 16 + dd];
            s = 0.25f * d;
        } else if (j == i) {
            s = NEG;
        } else {
            float d = qb_s[i * 4 + h];
#pragma unroll
            for (int dd = 0; dd < 16; dd++)
                d += qk_s[i * 128 + h * 16 + dd] * qk_s[j * 128 + 64 + h * 16 + dd];
            const float* rr = &rel_s[(i * 27 + j) * 5];
#pragma unroll
            for (int r = 0; r < 5; r++) d += qr_s[i * 20 + h * 5 + r] * rr[r];
            s = 0.25f * d;
        }
        sc[t] = s;
    }
    __syncthreads();

    for (int t = tid; t < 108; t += 256) {
        int i = t >> 2, h = t & 3;
        float* scp = &sc[i * 112 + h];
        float t0 = -INFINITY, t1 = -INFINITY, t2 = -INFINITY, t3 = -INFINITY;
#pragma unroll
        for (int j = 0; j < 28; j++) {
            float v = scp[j * 4];
            if (v > t0)      { t3 = t2; t2 = t1; t1 = t0; t0 = v; }
            else if (v > t1) { t3 = t2; t2 = t1; t1 = v; }
            else if (v > t2) { t3 = t2; t2 = v; }
            else if (v > t3) { t3 = v; }
        }
        float thr = t3, mxv = t0, sum = 0.f;
        float e[28];
#pragma unroll
        for (int j = 0; j < 28; j++) {
            float v = scp[j * 4];
            float ev = (v >= thr) ? expf(v - mxv) : 0.f;
            e[j] = ev; sum += ev;
        }
        float inv = 1.f / sum;
#pragma unroll
        for (int j = 0; j < 28; j++) scp[j * 4] = e[j] * inv;
    }
    __syncthreads();

    int w = tid >> 5, l = tid & 31;
    int h = l >> 3;
    for (int i = w; i < 27; i += 8) {
        const float* scp = &sc[i * 112];
        float m = scp[108 + h] * nv_s[l];
#pragma unroll
        for (int j = 0; j < 27; j++) m += scp[j * 4 + h] * sender_s[j * 32 + l];
        float s = m, s2 = m * m;
#pragma unroll
        for (int o = 16; o > 0; o >>= 1) {
            s  += __shfl_xor_sync(0xffffffffu, s, o);
            s2 += __shfl_xor_sync(0xffffffffu, s2, o);
        }
        float mu = s * (1.f / 32.f);
        float var = s2 * (1.f / 32.f) - mu * mu;
        float nm = (m - mu) * rsqrtf(var + 1e-5f) * ln_g[l] + ln_b[l];
        size_t fidx = (rbase + i) * 288 + 256 + l;
        __nv_bfloat16 hb = __float2bfloat16(nm);
        fh[fidx] = hb;
        fl[fidx] = __float2bfloat16(nm - __bfloat162float(hb));
    }
}

// ================= final =================
__global__ void __launch_bounds__(256)
final_kernel(const float* __restrict__ gd,
             const float* __restrict__ Wg2, const float* __restrict__ bg2,
             const float* __restrict__ Wd2, const float* __restrict__ bd2,
             const float* __restrict__ attack,
             float* __restrict__ out)
{
    __shared__ float Wd2s[256 * 28];
    __shared__ float wg2s[256];
    int tid = threadIdx.x;
    for (int t = tid; t < 27 * 256; t += 256) {
        int l = t >> 8, k = t & 255;
        Wd2s[k * 28 + l] = Wd2[t];
    }
    if (tid < 256) wg2s[tid] = Wg2[tid];
    __syncthreads();

    int w = tid >> 5, l = tid & 31;
    int row = blockIdx.x * 8 + w;
    const float* g1r = gd + (size_t)row * 512;
    const float* d1r = g1r + 256;
    float gs = 0.f;
#pragma unroll
    for (int i = 0; i < 8; i++) gs += g1r[l + i * 32] * wg2s[l + i * 32];
#pragma unroll
    for (int o = 16; o > 0; o >>= 1) gs += __shfl_xor_sync(0xffffffffu, gs, o);
    float gate = 1.f / (1.f + expf(-(gs + bg2[0])));
    if (l < 27) {
        float d = bd2[l];
#pragma unroll 8
        for (int k = 0; k < 256; k++) d += d1r[k] * Wd2s[k * 28 + l];
        out[(size_t)row * 33 + 6 + l] = attack[(size_t)row * 27 + l] + FUSE_SCALE * gate * d;
    }
}

// ================= host launcher =================
static float* sym(const void* symbol)
{
    void* p = nullptr;
    cudaGetSymbolAddress(&p, symbol);
    return (float*)p;
}
static __nv_bfloat16* symb(const void* symbol)
{
    void* p = nullptr;
    cudaGetSymbolAddress(&p, symbol);
    return (__nv_bfloat16*)p;
}

extern "C" void kernel_launch(void* const* d_in, const int* in_sizes, int n_in,
                              void* d_out, int out_size)
{
    const float* inputs = (const float*)d_in[0];
    const float* hidden = (const float*)d_in[1];
    const float* rel    = (const float*)d_in[2];
    const float* W1     = (const float*)d_in[3];
    const float* b1     = (const float*)d_in[4];
    const float* Wih    = (const float*)d_in[5];
    const float* bih    = (const float*)d_in[6];
    const float* Whh    = (const float*)d_in[7];
    const float* bhh    = (const float*)d_in[8];
    const float* Wp1    = (const float*)d_in[9];
    const float* bp1    = (const float*)d_in[10];
    const float* Wp2    = (const float*)d_in[11];
    const float* bp2    = (const float*)d_in[12];
    const float* Wq     = (const float*)d_in[13];
    const float* bq     = (const float*)d_in[14];
    const float* Wk     = (const float*)d_in[15];
    const float* bk     = (const float*)d_in[16];
    const float* Wv     = (const float*)d_in[17];
    const float* bv     = (const float*)d_in[18];
    const float* ln_g   = (const float*)d_in[19];
    const float* ln_b   = (const float*)d_in[20];
    const float* Wg1    = (const float*)d_in[21];
    const float* bg1    = (const float*)d_in[22];
    const float* Wg2    = (const float*)d_in[23];
    const float* bg2    = (const float*)d_in[24];
    const float* Wd1    = (const float*)d_in[25];
    const float* bd1    = (const float*)d_in[26];
    const float* Wd2    = (const float*)d_in[27];
    const float* bd2    = (const float*)d_in[28];
    const float* nullk  = (const float*)d_in[29];
    const float* nullv  = (const float*)d_in[30];

    const int rows = in_sizes[0] / INW;    // 27648
    const int bs = rows / Nn;
    float* out = (float*)d_out;

    float* pgi     = sym(g_gi);
    float* pgh     = sym(g_gh);
    float* pp      = sym(g_p);
    float* plogits = sym(g_logits);
    float* pattack = sym(g_attack);
    float* psender = sym(g_sender);
    float* pqk     = sym(g_qk);
    float* pqr     = sym(g_qr);
    float* pqb     = sym(g_qb);
    float* pgd     = sym(g_gd);
    float* pbqk    = sym(g_bqk);
    float* pbgd    = sym(g_bgd);

    __nv_bfloat16 *pW1h = symb(g_W1h),  *pW1l = symb(g_W1l);
    __nv_bfloat16 *pWihh = symb(g_Wihh), *pWihl = symb(g_Wihl);
    __nv_bfloat16 *pWhhh = symb(g_Whhh), *pWhhl = symb(g_Whhl);
    __nv_bfloat16 *pWp1h = symb(g_Wp1h), *pWp1l = symb(g_Wp1l);
    __nv_bfloat16 *pBqkh = symb(g_Bqkh), *pBqkl = symb(g_Bqkl);
    __nv_bfloat16 *pBgdh = symb(g_Bgdh), *pBgdl = symb(g_Bgdl);
    __nv_bfloat16 *pinh = symb(g_inh),  *pinl = symb(g_inl);
    __nv_bfloat16 *phidh = symb(g_hidh), *phidl = symb(g_hidl);
    __nv_bfloat16 *pxh = symb(g_xh),   *pxl = symb(g_xl);
    __nv_bfloat16 *phh = symb(g_hh),   *phl = symb(g_hl);
    __nv_bfloat16 *pfh = symb(g_fh),   *pfl = symb(g_fl);

    float* hout = (out_size >= rows * (NA + HID)) ? out + (size_t)rows * NA : sym(g_hfb);

    const int MB = rows / 128;   // 216

    cudaFuncSetAttribute((const void*)gemm_mma<EPI_BIAS>,        cudaFuncAttributeMaxDynamicSharedMemorySize, GSMEM);
    cudaFuncSetAttribute((const void*)gemm_mma<EPI_BIAS_RELU>,   cudaFuncAttributeMaxDynamicSharedMemorySize, GSMEM);
    cudaFuncSetAttribute((const void*)gemm_mma<EPI_PLANES_RELU>, cudaFuncAttributeMaxDynamicSharedMemorySize, GSMEM);

    // --- prep: weight planes + activation planes ---
    prep_all<<<(STOT + 255) / 256, 256>>>(W1, Wih, Whh, Wp1, Wq, Wk, Wg1, Wd1, bq, bg1, bd1,
                                          pW1h, pW1l, pWihh, pWihl, pWhhh, pWhhl, pWp1h, pWp1l,
                                          pBqkh, pBqkl, pBgdh, pBgdl, pbqk, pbgd);
    conv_split<<<(rows * 352 + 255) / 256, 256>>>(inputs, pinh, pinl, rows, 322, 352);
    conv_split<<<(rows * 256 + 255) / 256, 256>>>(hidden, phidh, phidl, rows, 256, 256);

    // 1. x-planes = relu(inputs @ W1^T + b1)            11 chunks
    gemm_mma<EPI_PLANES_RELU><<<dim3(MB, 2), 256, GSMEM>>>(pinh, pinl, 352, pW1h, pW1l, 352, b1,
                                                           nullptr, pxh, pxl, 256, 11);
    // 2. gi, gh                                          8 chunks
    gemm_mma<EPI_BIAS><<<dim3(MB, 6), 256, GSMEM>>>(pxh, pxl, 256, pWihh, pWihl, 256, bih,
                                                    pgi, nullptr, nullptr, 768, 8);
    gemm_mma<EPI_BIAS><<<dim3(MB, 6), 256, GSMEM>>>(phidh, phidl, 256, pWhhh, pWhhl, 256, bhh,
                                                    pgh, nullptr, nullptr, 768, 8);
    // 3. GRU -> h fp32 + h-planes + fusion-planes[:,0:256]
    gru_kernel<<<(rows * 256 + 255) / 256, 256>>>(pgi, pgh, hidden, hout, phh, phl, pfh, pfl, rows * 256);
    // 4. p = relu(h @ Wp1^T + bp1); logits = p @ Wp2^T + bp2
    gemm_mma<EPI_BIAS_RELU><<<dim3(MB, 2), 256, GSMEM>>>(phh, phl, 256, pWp1h, pWp1l, 256, bp1,
                                                         pp, nullptr, nullptr, 256, 8);
    gemm_tn<EPI_BIAS><<<dim3(MB, 1), 256>>>(pp, 256, Wp2, 256, bp2, plogits, NA, rows, NA, 256);
    // 5. softmax / sender values / base logits
    logits_post<<<rows / 8, 256>>>(plogits, Wv, bv, out, pattack, psender);
    // 6. [q | key_h] = h @ [Wq; Wk_h]^T + [bq; 0]
    gemm_mma<EPI_BIAS><<<dim3(MB, 1), 256, GSMEM>>>(phh, phl, 256, pBqkh, pBqkl, 256, pbqk,
                                                    pqk, nullptr, nullptr, 128, 8);
    // 7. qr, qb
    qr_kernel<<<(rows * 4 + 127) / 128, 128>>>(pqk, Wk, bk, pqr, pqb, rows);
    // 8. attention (batched) -> fusion-planes[:,256:288]
    attn_batch<<<bs, 256>>>(pqk, pqr, pqb, rel, psender, nullk, nullv, ln_g, ln_b, pfh, pfl);
    // 9. [g1 | d1] = relu(fusion @ [Wg1; Wd1]^T + [bg1; bd1])   9 chunks
    gemm_mma<EPI_BIAS_RELU><<<dim3(MB, 4), 256, GSMEM>>>(pfh, pfl, 288, pBgdh, pBgdl, 288, pbgd,
                                                         pgd, nullptr, nullptr, 512, 9);
    // 10. gate, delta, fused output
    final_kernel<<<rows / 8, 256>>>(pgd, Wg2, bg2, Wd2, bd2, pattack, out);
}

// round 9
// speedup vs baseline: 3.0687x; 1.0234x over previous
#include <cuda_runtime.h>
#include <cuda_bf16.h>
#include <math.h>
#include <stdint.h>

// ---------------- problem constants ----------------
#define Nn   27
#define NA   33
#define HID  256
#define REL  5
#define INW  322
#define FUSE_SCALE 0.1f
#define NEG  (-10000000000.0f)
#define MAXROWS 27648

// ---------------- scratch (device globals) -------------
__device__ float g_rz    [MAXROWS * 512];   // summed r/z pre-activations
__device__ float g_inn   [MAXROWS * 256];
__device__ float g_hn    [MAXROWS * 256];
__device__ float g_lgp   [MAXROWS * 128];   // padded logits
__device__ float g_attack[MAXROWS * 27];
__device__ float g_sender[MAXROWS * 32];
__device__ float g_qk    [MAXROWS * 128];
__device__ float g_qr    [MAXROWS * 20];
__device__ float g_qb    [MAXROWS * 4];
__device__ float g_gd    [MAXROWS * 512];
__device__ float g_hfb   [MAXROWS * 256];
__device__ float g_bqk   [128];
__device__ float g_bgd   [512];
__device__ float g_brz   [512];
__device__ float g_bp2p  [128];
// bf16 hi/lo weight planes
__device__ __nv_bfloat16 g_W1h [256 * 352],  g_W1l [256 * 352];
__device__ __nv_bfloat16 g_Brzh[512 * 512],  g_Brzl[512 * 512];
__device__ __nv_bfloat16 g_Wnih[256 * 256],  g_Wnil[256 * 256];
__device__ __nv_bfloat16 g_Wnhh[256 * 256],  g_Wnhl[256 * 256];
__device__ __nv_bfloat16 g_Wp1h[256 * 256],  g_Wp1l[256 * 256];
__device__ __nv_bfloat16 g_Wp2h[128 * 256],  g_Wp2l[128 * 256];
__device__ __nv_bfloat16 g_Bqkh[128 * 256],  g_Bqkl[128 * 256];
__device__ __nv_bfloat16 g_Bgdh[512 * 288],  g_Bgdl[512 * 288];
// bf16 hi/lo activation planes
__device__ __nv_bfloat16 g_inh [MAXROWS * 352], g_inl [MAXROWS * 352];
__device__ __nv_bfloat16 g_cath[MAXROWS * 512], g_catl[MAXROWS * 512]; // [x | hidden]
__device__ __nv_bfloat16 g_hh  [MAXROWS * 256], g_hl  [MAXROWS * 256];
__device__ __nv_bfloat16 g_ph  [MAXROWS * 256], g_pl  [MAXROWS * 256];
__device__ __nv_bfloat16 g_fh  [MAXROWS * 288], g_fl  [MAXROWS * 288];

#define EPI_BIAS 1
#define EPI_BIAS_RELU 2
#define EPI_PLANES_RELU 3

// =================== helpers ===============
__device__ __forceinline__ uint32_t smem_u32(const void* p) {
    uint32_t a;
    asm("{ .reg .u64 t; cvta.to.shared.u64 t, %1; cvt.u32.u64 %0, t; }" : "=r"(a) : "l"(p));
    return a;
}
#define CP_ASYNC16(dst, src) \
    asm volatile("cp.async.cg.shared.global [%0], [%1], 16;" :: "r"(dst), "l"(src) : "memory")
#define CP_COMMIT() asm volatile("cp.async.commit_group;" ::: "memory")
#define CP_WAIT0()  asm volatile("cp.async.wait_group 0;" ::: "memory")

__device__ __forceinline__ void ldsm4(uint32_t* d, uint32_t addr) {
    asm volatile("ldmatrix.sync.aligned.m8n8.x4.shared.b16 {%0,%1,%2,%3}, [%4];"
                 : "=r"(d[0]), "=r"(d[1]), "=r"(d[2]), "=r"(d[3]) : "r"(addr));
}
__device__ __forceinline__ void mma16816(float* c, const uint32_t* a, const uint32_t* b) {
    asm volatile("mma.sync.aligned.m16n8k16.row.col.f32.bf16.bf16.f32 "
                 "{%0,%1,%2,%3}, {%4,%5,%6,%7}, {%8,%9}, {%0,%1,%2,%3};"
                 : "+f"(c[0]), "+f"(c[1]), "+f"(c[2]), "+f"(c[3])
                 : "r"(a[0]), "r"(a[1]), "r"(a[2]), "r"(a[3]), "r"(b[0]), "r"(b[1]));
}

// =================== pipelined mma.sync bf16 3-pass GEMM ===================
// grid: x = N tile (fast, shares A tile in L2), y = M tile.
#define PLNB   10240
#define STAGEB (4 * PLNB)
#define GSMEM  (2 * STAGEB)

template<int EPI>
__global__ void __launch_bounds__(256, 2)
gemm_mma(const __nv_bfloat16* __restrict__ Ahi, const __nv_bfloat16* __restrict__ Alo, int lda,
         const __nv_bfloat16* __restrict__ Bhi, const __nv_bfloat16* __restrict__ Blo, int ldb,
         const float* __restrict__ bias,
         float* __restrict__ C, __nv_bfloat16* __restrict__ Ch, __nv_bfloat16* __restrict__ Cl,
         int ldc, int nChunks)
{
    extern __shared__ __align__(16) char smx[];

    const int tid = threadIdx.x;
    const int wid = tid >> 5, lane = tid & 31;
    const int m0 = blockIdx.y * 128, n0 = blockIdx.x * 128;
    const int r = tid >> 1, hf = tid & 1;

    const uint32_t sbase = smem_u32(smx);
    const uint32_t stO = (uint32_t)r * 80 + hf * 32;

    const int warp_m = (wid & 1) * 64, warp_n = (wid >> 1) * 32;
    const uint32_t aOff = (uint32_t)(warp_m + (lane & 15)) * 80 + (lane >> 4) * 16;
    const uint32_t bRow = (uint32_t)(warp_n + (lane & 7) + ((lane >> 4) << 3));
    const uint32_t bOff = bRow * 80 + ((lane >> 3) & 1) * 16;

    float c[4][4][4];
#pragma unroll
    for (int mt = 0; mt < 4; mt++)
#pragma unroll
        for (int nt = 0; nt < 4; nt++)
#pragma unroll
            for (int q = 0; q < 4; q++) c[mt][nt][q] = 0.f;

    const __nv_bfloat16* ArH = Ahi + (size_t)(m0 + r) * lda + hf * 16;
    const __nv_bfloat16* ArL = Alo + (size_t)(m0 + r) * lda + hf * 16;
    const __nv_bfloat16* BrH = Bhi + (size_t)(n0 + r) * ldb + hf * 16;
    const __nv_bfloat16* BrL = Blo + (size_t)(n0 + r) * ldb + hf * 16;

    auto issue = [&](int ch, int st) {
        const int kc = ch * 32;
        const uint32_t base = sbase + st * STAGEB;
        CP_ASYNC16(base + stO,                 ArH + kc);
        CP_ASYNC16(base + stO + 16,            ArH + kc + 8);
        CP_ASYNC16(base + PLNB + stO,          ArL + kc);
        CP_ASYNC16(base + PLNB + stO + 16,     ArL + kc + 8);
        CP_ASYNC16(base + 2 * PLNB + stO,      BrH + kc);
        CP_ASYNC16(base + 2 * PLNB + stO + 16, BrH + kc + 8);
        CP_ASYNC16(base + 3 * PLNB + stO,      BrL + kc);
        CP_ASYNC16(base + 3 * PLNB + stO + 16, BrL + kc + 8);
        CP_COMMIT();
    };

    issue(0, 0);
    CP_WAIT0();
    __syncthreads();

    for (int ch = 0; ch < nChunks; ch++) {
        const int cur = ch & 1, nxt = cur ^ 1;
        const bool more = (ch + 1 < nChunks);
        if (more) issue(ch + 1, nxt);

        const uint32_t base = sbase + cur * STAGEB;
        const uint32_t sAhi = base, sAlo = base + PLNB;
        const uint32_t sBhi = base + 2 * PLNB, sBlo = base + 3 * PLNB;
#pragma unroll
        for (int ks = 0; ks < 2; ks++) {
            const uint32_t ko = ks * 32;
            uint32_t aF[4][4], bF[4][2];

            // pass 1: Ahi x Bhi
#pragma unroll
            for (int mt = 0; mt < 4; mt++) ldsm4(aF[mt], sAhi + aOff + ko + mt * (16 * 80));
#pragma unroll
            for (int p = 0; p < 2; p++) {
                uint32_t t[4];
                ldsm4(t, sBhi + bOff + ko + p * (16 * 80));
                bF[2 * p][0] = t[0]; bF[2 * p][1] = t[1];
                bF[2 * p + 1][0] = t[2]; bF[2 * p + 1][1] = t[3];
            }
#pragma unroll
            for (int mt = 0; mt < 4; mt++)
#pragma unroll
                for (int nt = 0; nt < 4; nt++) mma16816(c[mt][nt], aF[mt], bF[nt]);

            // pass 2: Ahi x Blo
#pragma unroll
            for (int p = 0; p < 2; p++) {
                uint32_t t[4];
                ldsm4(t, sBlo + bOff + ko + p * (16 * 80));
                bF[2 * p][0] = t[0]; bF[2 * p][1] = t[1];
                bF[2 * p + 1][0] = t[2]; bF[2 * p + 1][1] = t[3];
            }
#pragma unroll
            for (int mt = 0; mt < 4; mt++)
#pragma unroll
                for (int nt = 0; nt < 4; nt++) mma16816(c[mt][nt], aF[mt], bF[nt]);

            // pass 3: Alo x Bhi
#pragma unroll
            for (int mt = 0; mt < 4; mt++) ldsm4(aF[mt], sAlo + aOff + ko + mt * (16 * 80));
#pragma unroll
            for (int p = 0; p < 2; p++) {
                uint32_t t[4];
                ldsm4(t, sBhi + bOff + ko + p * (16 * 80));
                bF[2 * p][0] = t[0]; bF[2 * p][1] = t[1];
                bF[2 * p + 1][0] = t[2]; bF[2 * p + 1][1] = t[3];
            }
#pragma unroll
            for (int mt = 0; mt < 4; mt++)
#pragma unroll
                for (int nt = 0; nt < 4; nt++) mma16816(c[mt][nt], aF[mt], bF[nt]);
        }

        if (more) CP_WAIT0();
        __syncthreads();
    }

    // ---- epilogue ----
#pragma unroll
    for (int mt = 0; mt < 4; mt++) {
        const int row = m0 + warp_m + mt * 16 + (lane >> 2);
#pragma unroll
        for (int nt = 0; nt < 4; nt++) {
            const int col = n0 + warp_n + nt * 8 + (lane & 3) * 2;
            const float b0 = bias[col], b1 = bias[col + 1];
            float v0 = c[mt][nt][0] + b0, v1 = c[mt][nt][1] + b1;
            float v2 = c[mt][nt][2] + b0, v3 = c[mt][nt][3] + b1;
            if (EPI != EPI_BIAS) {
                v0 = fmaxf(v0, 0.f); v1 = fmaxf(v1, 0.f);
                v2 = fmaxf(v2, 0.f); v3 = fmaxf(v3, 0.f);
            }
            if (EPI == EPI_PLANES_RELU) {
                __nv_bfloat16 h0 = __float2bfloat16(v0), h1 = __float2bfloat16(v1);
                __nv_bfloat16 h2 = __float2bfloat16(v2), h3 = __float2bfloat16(v3);
                *(__nv_bfloat162*)(Ch + (size_t)row * ldc + col) = __nv_bfloat162(h0, h1);
                *(__nv_bfloat162*)(Ch + (size_t)(row + 8) * ldc + col) = __nv_bfloat162(h2, h3);
                *(__nv_bfloat162*)(Cl + (size_t)row * ldc + col) =
                    __nv_bfloat162(__float2bfloat16(v0 - __bfloat162float(h0)),
                                   __float2bfloat16(v1 - __bfloat162float(h1)));
                *(__nv_bfloat162*)(Cl + (size_t)(row + 8) * ldc + col) =
                    __nv_bfloat162(__float2bfloat16(v2 - __bfloat162float(h2)),
                                   __float2bfloat16(v3 - __bfloat162float(h3)));
            } else {
                *(float2*)(C + (size_t)row * ldc + col) = make_float2(v0, v1);
                *(float2*)(C + (size_t)(row + 8) * ldc + col) = make_float2(v2, v3);
            }
        }
    }
}

// ================= activation split with offset/stride =================
__global__ void conv_split(const float* __restrict__ src, __nv_bfloat16* __restrict__ hi,
                           __nv_bfloat16* __restrict__ lo, int Mrows, int K, int Kpad,
                           int ldo, int off)
{
    int idx = blockIdx.x * blockDim.x + threadIdx.x;
    if (idx >= Mrows * Kpad) return;
    int m = idx / Kpad, k = idx - m * Kpad;
    float v = (k < K) ? src[(size_t)m * K + k] : 0.f;
    __nv_bfloat16 h = __float2bfloat16(v);
    size_t o = (size_t)m * ldo + off + k;
    hi[o] = h;
    lo[o] = __float2bfloat16(v - __bfloat162float(h));
}

// ================= one-shot weight prep =================
#define T0 (256*352)     // W1
#define T1 (512*512)     // Brz = [Wih_rz | Whh_rz]
#define T2 (256*256)     // Wn_i
#define T3 (256*256)     // Wn_h
#define T4 (256*256)     // Wp1
#define T5 (128*256)     // Wp2 padded
#define T6 (128*256)     // Bqk
#define T7 (512*288)     // Bgd
#define T8 (128+512+512+128)  // pbqk, pbgd, brz, bp2p
#define TTOT (T0+T1+T2+T3+T4+T5+T6+T7+T8)

__global__ void prep_all(const float* __restrict__ W1,  const float* __restrict__ Wih,
                         const float* __restrict__ Whh, const float* __restrict__ Wp1,
                         const float* __restrict__ Wp2, const float* __restrict__ Wq,
                         const float* __restrict__ Wk,  const float* __restrict__ Wg1,
                         const float* __restrict__ Wd1,
                         const float* __restrict__ bq,  const float* __restrict__ bg1,
                         const float* __restrict__ bd1, const float* __restrict__ bih,
                         const float* __restrict__ bhh, const float* __restrict__ bp2,
                         __nv_bfloat16* __restrict__ W1h,  __nv_bfloat16* __restrict__ W1l,
                         __nv_bfloat16* __restrict__ Brzh, __nv_bfloat16* __restrict__ Brzl,
                         __nv_bfloat16* __restrict__ Wnih, __nv_bfloat16* __restrict__ Wnil,
                         __nv_bfloat16* __restrict__ Wnhh, __nv_bfloat16* __restrict__ Wnhl,
                         __nv_bfloat16* __restrict__ Wp1h, __nv_bfloat16* __restrict__ Wp1l,
                         __nv_bfloat16* __restrict__ Wp2h, __nv_bfloat16* __restrict__ Wp2l,
                         __nv_bfloat16* __restrict__ Bqkh, __nv_bfloat16* __restrict__ Bqkl,
                         __nv_bfloat16* __restrict__ Bgdh, __nv_bfloat16* __restrict__ Bgdl,
                         float* __restrict__ pbqk, float* __restrict__ pbgd,
                         float* __restrict__ pbrz, float* __restrict__ pbp2p)
{
    int idx = blockIdx.x * blockDim.x + threadIdx.x;
    if (idx >= TTOT) return;
    float src;
    __nv_bfloat16 *hi, *lo;
    int off;
    if (idx < T0) {
        off = idx;
        int k = off % 352;
        src = (k < 322) ? W1[(off / 352) * 322 + k] : 0.f;
        hi = W1h; lo = W1l;
    } else if (idx < T0 + T1) {
        off = idx - T0;
        int n = off >> 9, k = off & 511;
        src = (k < 256) ? Wih[n * 256 + k] : Whh[n * 256 + (k - 256)];
        hi = Brzh; lo = Brzl;
    } else if (idx < T0 + T1 + T2) {
        off = idx - T0 - T1;
        src = Wih[512 * 256 + off];
        hi = Wnih; lo = Wnil;
    } else if (idx < T0 + T1 + T2 + T3) {
        off = idx - T0 - T1 - T2;
        src = Whh[512 * 256 + off];
        hi = Wnhh; lo = Wnhl;
    } else if (idx < T0 + T1 + T2 + T3 + T4) {
        off = idx - T0 - T1 - T2 - T3;
        src = Wp1[off];
        hi = Wp1h; lo = Wp1l;
    } else if (idx < T0 + T1 + T2 + T3 + T4 + T5) {
        off = idx - T0 - T1 - T2 - T3 - T4;
        int n = off >> 8;
        src = (n < NA) ? Wp2[n * 256 + (off & 255)] : 0.f;
        hi = Wp2h; lo = Wp2l;
    } else if (idx < T0 + T1 + T2 + T3 + T4 + T5 + T6) {
        off = idx - T0 - T1 - T2 - T3 - T4 - T5;
        int rr = off >> 8, cc = off & 255;
        src = (rr < 64) ? Wq[rr * 256 + cc] : Wk[(size_t)(rr - 64) * (HID + REL) + cc];
        hi = Bqkh; lo = Bqkl;
    } else if (idx < T0 + T1 + T2 + T3 + T4 + T5 + T6 + T7) {
        off = idx - T0 - T1 - T2 - T3 - T4 - T5 - T6;
        int rr = off / 288, cc = off % 288;
        src = (rr < 256) ? Wg1[rr * 288 + cc] : Wd1[(rr - 256) * 288 + cc];
        hi = Bgdh; lo = Bgdl;
    } else {
        off = idx - (T0 + T1 + T2 + T3 + T4 + T5 + T6 + T7);
        if (off < 128) pbqk[off] = (off < 64) ? bq[off] : 0.f;
        else if (off < 640) { int o = off - 128; pbgd[o] = (o < 256) ? bg1[o] : bd1[o - 256]; }
        else if (off < 1152) { int o = off - 640; pbrz[o] = bih[o] + bhh[o]; }
        else { int o = off - 1152; pbp2p[o] = (o < NA) ? bp2[o] : 0.f; }
        return;
    }
    __nv_bfloat16 h = __float2bfloat16(src);
    hi[off] = h;
    lo[off] = __float2bfloat16(src - __bfloat162float(h));
}

// ================= GRU: rz(summed) + inn + hn -> h, planes =================
__global__ void gru_kernel(const float* __restrict__ rz, const float* __restrict__ inn,
                           const float* __restrict__ hn, const float* __restrict__ hin,
                           float* __restrict__ hout,
                           __nv_bfloat16* __restrict__ hh, __nv_bfloat16* __restrict__ hl,
                           __nv_bfloat16* __restrict__ fh, __nv_bfloat16* __restrict__ fl,
                           int total)
{
    int idx = blockIdx.x * blockDim.x + threadIdx.x;
    if (idx >= total) return;
    int r = idx >> 8, c = idx & 255;
    size_t rb = (size_t)r * 512;
    float rg = 1.f / (1.f + expf(-rz[rb + c]));
    float zg = 1.f / (1.f + expf(-rz[rb + 256 + c]));
    float ng = tanhf(inn[idx] + rg * hn[idx]);
    float v = (1.f - zg) * ng + zg * hin[idx];
    hout[idx] = v;
    __nv_bfloat16 h = __float2bfloat16(v);
    __nv_bfloat16 l = __float2bfloat16(v - __bfloat162float(h));
    hh[idx] = h; hl[idx] = l;
    size_t fidx = (size_t)r * 288 + c;
    fh[fidx] = h; fl[fidx] = l;
}

// ================= logits post (padded logits, ld=128) =================
__global__ void __launch_bounds__(256)
logits_post(const float* __restrict__ logits, const float* __restrict__ Wv,
            const float* __restrict__ bv,
            float* __restrict__ out, float* __restrict__ attack,
            float* __restrict__ sender)
{
    __shared__ float Wvs[32 * 29];
    __shared__ float bvs[32];
    __shared__ float vs[8][29];
    int tid = threadIdx.x;
    for (int t = tid; t < 32 * 29; t += 256) Wvs[t] = Wv[t];
    if (tid < 32) bvs[tid] = bv[tid];
    int w = tid >> 5, l = tid & 31;
    int row = blockIdx.x * 8 + w;
    const float* lrow = logits + (size_t)row * 128;
    float al = (l < 27) ? lrow[6 + l] : -INFINITY;
    float mx = al;
#pragma unroll
    for (int o = 16; o > 0; o >>= 1) mx = fmaxf(mx, __shfl_xor_sync(0xffffffffu, mx, o));
    float e = (l < 27) ? expf(al - mx) : 0.f;
    float sum = e;
#pragma unroll
    for (int o = 16; o > 0; o >>= 1) sum += __shfl_xor_sync(0xffffffffu, sum, o);
    float inv = 1.f / sum;
    if (l < 27) vs[w][l] = e * inv;
    if (l == 27) vs[w][27] = 1.0f;
    if (l == 28) vs[w][28] = inv;
    if (l < 27) attack[(size_t)row * 27 + l] = al;
    if (l < 6)  out[(size_t)row * 33 + l] = lrow[l];
    __syncthreads();
    float s = bvs[l];
#pragma unroll
    for (int r = 0; r < 29; r++) s += vs[w][r] * Wvs[l * 29 + r];
    sender[(size_t)row * 32 + l] = s;
}

// ================= qr / qb precompute =================
__global__ void qr_kernel(const float* __restrict__ qk, const float* __restrict__ Wk,
                          const float* __restrict__ bk,
                          float* __restrict__ qr, float* __restrict__ qb, int rows)
{
    int idx = blockIdx.x * blockDim.x + threadIdx.x;
    if (idx >= rows * 4) return;
    int row = idx >> 2, h = idx & 3;
    const float* qp = qk + (size_t)row * 128 + h * 16;
    float acc[5] = {0.f, 0.f, 0.f, 0.f, 0.f};
    float accb = 0.f;
#pragma unroll
    for (int d = 0; d < 16; d++) {
        float qd = qp[d];
        const float* wrow = Wk + (size_t)(h * 16 + d) * (HID + REL) + HID;
#pragma unroll
        for (int r = 0; r < 5; r++) acc[r] += qd * wrow[r];
        accb += qd * bk[h * 16 + d];
    }
#pragma unroll
    for (int r = 0; r < 5; r++) qr[(size_t)row * 20 + h * 5 + r] = acc[r];
    qb[(size_t)row * 4 + h] = accb;
}

// ================= batched attention -> fusion planes cols 256..287 =================
__global__ void __launch_bounds__(256)
attn_batch(const float* __restrict__ qk, const float* __restrict__ qr,
           const float* __restrict__ qb, const float* __restrict__ rel,
           const float* __restrict__ sender,
           const float* __restrict__ nullk, const float* __restrict__ nullv,
           const float* __restrict__ ln_g, const float* __restrict__ ln_b,
           __nv_bfloat16* __restrict__ fh, __nv_bfloat16* __restrict__ fl)
{
    __shared__ float qk_s[27 * 128];
    __shared__ float sender_s[27 * 32];
    __shared__ float rel_s[27 * 27 * 5];
    __shared__ float qr_s[27 * 20];
    __shared__ float qb_s[27 * 4];
    __shared__ float nk_s[64];
    __shared__ float nv_s[32];
    __shared__ float sc[27 * 112];

    const int b = blockIdx.x;
    const int tid = threadIdx.x;
    const size_t rbase = (size_t)b * 27;

    for (int t = tid; t < 27 * 128; t += 256) qk_s[t] = qk[rbase * 128 + t];
    for (int t = tid; t < 27 * 32; t += 256) sender_s[t] = sender[rbase * 32 + t];
    for (int t = tid; t < 27 * 27 * 5; t += 256) rel_s[t] = rel[(size_t)b * (27 * 27 * 5) + t];
    for (int t = tid; t < 27 * 20; t += 256) qr_s[t] = qr[rbase * 20 + t];
    for (int t = tid; t < 27 * 4; t += 256) qb_s[t] = qb[rbase * 4 + t];
    if (tid < 64) nk_s[tid] = nullk[tid];
    if (tid >= 64 && tid < 96) nv_s[tid - 64] = nullv[tid - 64];
    __syncthreads();

    for (int t = tid; t < 27 * 112; t += 256) {
        int i = t / 112;
        int rem = t - i * 112;
        int j = rem >> 2, h = rem & 3;
        float s;
        if (j == 27) {
            float d = 0.f;
#pragma unroll
            for (int dd = 0; dd < 16; dd++) d += qk_s[i * 128 + h * 16 + dd] * nk_s[h * 16 + dd];
            s = 0.25f * d;
        } else if (j == i) {
            s = NEG;
        } else {
            float d = qb_s[i * 4 + h];
#pragma unroll
            for (int dd = 0; dd < 16; dd++)
                d += qk_s[i * 128 + h * 16 + dd] * qk_s[j * 128 + 64 + h * 16 + dd];
            const float* rr = &rel_s[(i * 27 + j) * 5];
#pragma unroll
            for (int r = 0; r < 5; r++) d += qr_s[i * 20 + h * 5 + r] * rr[r];
            s = 0.25f * d;
        }
        sc[t] = s;
    }
    __syncthreads();

    for (int t = tid; t < 108; t += 256) {
        int i = t >> 2, h = t & 3;
        float* scp = &sc[i * 112 + h];
        float t0 = -INFINITY, t1 = -INFINITY, t2 = -INFINITY, t3 = -INFINITY;
#pragma unroll
        for (int j = 0; j < 28; j++) {
            float v = scp[j * 4];
            if (v > t0)      { t3 = t2; t2 = t1; t1 = t0; t0 = v; }
            else if (v > t1) { t3 = t2; t2 = t1; t1 = v; }
            else if (v > t2) { t3 = t2; t2 = v; }
            else if (v > t3) { t3 = v; }
        }
        float thr = t3, mxv = t0, sum = 0.f;
        float e[28];
#pragma unroll
        for (int j = 0; j < 28; j++) {
            float v = scp[j * 4];
            float ev = (v >= thr) ? expf(v - mxv) : 0.f;
            e[j] = ev; sum += ev;
        }
        float inv = 1.f / sum;
#pragma unroll
        for (int j = 0; j < 28; j++) scp[j * 4] = e[j] * inv;
    }
    __syncthreads();

    int w = tid >> 5, l = tid & 31;
    int h = l >> 3;
    for (int i = w; i < 27; i += 8) {
        const float* scp = &sc[i * 112];
        float m = scp[108 + h] * nv_s[l];
#pragma unroll
        for (int j = 0; j < 27; j++) m += scp[j * 4 + h] * sender_s[j * 32 + l];
        float s = m, s2 = m * m;
#pragma unroll
        for (int o = 16; o > 0; o >>= 1) {
            s  += __shfl_xor_sync(0xffffffffu, s, o);
            s2 += __shfl_xor_sync(0xffffffffu, s2, o);
        }
        float mu = s * (1.f / 32.f);
        float var = s2 * (1.f / 32.f) - mu * mu;
        float nm = (m - mu) * rsqrtf(var + 1e-5f) * ln_g[l] + ln_b[l];
        size_t fidx = (rbase + i) * 288 + 256 + l;
        __nv_bfloat16 hb = __float2bfloat16(nm);
        fh[fidx] = hb;
        fl[fidx] = __float2bfloat16(nm - __bfloat162float(hb));
    }
}

// ================= final =================
__global__ void __launch_bounds__(256)
final_kernel(const float* __restrict__ gd,
             const float* __restrict__ Wg2, const float* __restrict__ bg2,
             const float* __restrict__ Wd2, const float* __restrict__ bd2,
             const float* __restrict__ attack,
             float* __restrict__ out)
{
    __shared__ float Wd2s[256 * 28];
    __shared__ float wg2s[256];
    int tid = threadIdx.x;
    for (int t = tid; t < 27 * 256; t += 256) {
        int l = t >> 8, k = t & 255;
        Wd2s[k * 28 + l] = Wd2[t];
    }
    if (tid < 256) wg2s[tid] = Wg2[tid];
    __syncthreads();

    int w = tid >> 5, l = tid & 31;
    int row = blockIdx.x * 8 + w;
    const float* g1r = gd + (size_t)row * 512;
    const float* d1r = g1r + 256;
    float gs = 0.f;
#pragma unroll
    for (int i = 0; i < 8; i++) gs += g1r[l + i * 32] * wg2s[l + i * 32];
#pragma unroll
    for (int o = 16; o > 0; o >>= 1) gs += __shfl_xor_sync(0xffffffffu, gs, o);
    float gate = 1.f / (1.f + expf(-(gs + bg2[0])));
    if (l < 27) {
        float d = bd2[l];
#pragma unroll 8
        for (int k = 0; k < 256; k++) d += d1r[k] * Wd2s[k * 28 + l];
        out[(size_t)row * 33 + 6 + l] = attack[(size_t)row * 27 + l] + FUSE_SCALE * gate * d;
    }
}

// ================= host launcher =================
static float* sym(const void* symbol)
{
    void* p = nullptr;
    cudaGetSymbolAddress(&p, symbol);
    return (float*)p;
}
static __nv_bfloat16* symb(const void* symbol)
{
    void* p = nullptr;
    cudaGetSymbolAddress(&p, symbol);
    return (__nv_bfloat16*)p;
}

extern "C" void kernel_launch(void* const* d_in, const int* in_sizes, int n_in,
                              void* d_out, int out_size)
{
    const float* inputs = (const float*)d_in[0];
    const float* hidden = (const float*)d_in[1];
    const float* rel    = (const float*)d_in[2];
    const float* W1     = (const float*)d_in[3];
    const float* b1     = (const float*)d_in[4];
    const float* Wih    = (const float*)d_in[5];
    const float* bih    = (const float*)d_in[6];
    const float* Whh    = (const float*)d_in[7];
    const float* bhh    = (const float*)d_in[8];
    const float* Wp1    = (const float*)d_in[9];
    const float* bp1    = (const float*)d_in[10];
    const float* Wp2    = (const float*)d_in[11];
    const float* bp2    = (const float*)d_in[12];
    const float* Wq     = (const float*)d_in[13];
    const float* bq     = (const float*)d_in[14];
    const float* Wk     = (const float*)d_in[15];
    const float* bk     = (const float*)d_in[16];
    const float* Wv     = (const float*)d_in[17];
    const float* bv     = (const float*)d_in[18];
    const float* ln_g   = (const float*)d_in[19];
    const float* ln_b   = (const float*)d_in[20];
    const float* Wg1    = (const float*)d_in[21];
    const float* bg1    = (const float*)d_in[22];
    const float* Wg2    = (const float*)d_in[23];
    const float* bg2    = (const float*)d_in[24];
    const float* Wd1    = (const float*)d_in[25];
    const float* bd1    = (const float*)d_in[26];
    const float* Wd2    = (const float*)d_in[27];
    const float* bd2    = (const float*)d_in[28];
    const float* nullk  = (const float*)d_in[29];
    const float* nullv  = (const float*)d_in[30];

    const int rows = in_sizes[0] / INW;    // 27648
    const int bs = rows / Nn;
    float* out = (float*)d_out;

    float* prz     = sym(g_rz);
    float* pinn    = sym(g_inn);
    float* phn     = sym(g_hn);
    float* plgp    = sym(g_lgp);
    float* pattack = sym(g_attack);
    float* psender = sym(g_sender);
    float* pqk     = sym(g_qk);
    float* pqr     = sym(g_qr);
    float* pqb     = sym(g_qb);
    float* pgd     = sym(g_gd);
    float* pbqk    = sym(g_bqk);
    float* pbgd    = sym(g_bgd);
    float* pbrz    = sym(g_brz);
    float* pbp2p   = sym(g_bp2p);

    __nv_bfloat16 *pW1h = symb(g_W1h),   *pW1l = symb(g_W1l);
    __nv_bfloat16 *pBrzh = symb(g_Brzh), *pBrzl = symb(g_Brzl);
    __nv_bfloat16 *pWnih = symb(g_Wnih), *pWnil = symb(g_Wnil);
    __nv_bfloat16 *pWnhh = symb(g_Wnhh), *pWnhl = symb(g_Wnhl);
    __nv_bfloat16 *pWp1h = symb(g_Wp1h), *pWp1l = symb(g_Wp1l);
    __nv_bfloat16 *pWp2h = symb(g_Wp2h), *pWp2l = symb(g_Wp2l);
    __nv_bfloat16 *pBqkh = symb(g_Bqkh), *pBqkl = symb(g_Bqkl);
    __nv_bfloat16 *pBgdh = symb(g_Bgdh), *pBgdl = symb(g_Bgdl);
    __nv_bfloat16 *pinh = symb(g_inh),   *pinl = symb(g_inl);
    __nv_bfloat16 *pcath = symb(g_cath), *pcatl = symb(g_catl);
    __nv_bfloat16 *phh = symb(g_hh),     *phl = symb(g_hl);
    __nv_bfloat16 *pph = symb(g_ph),     *ppl = symb(g_pl);
    __nv_bfloat16 *pfh = symb(g_fh),     *pfl = symb(g_fl);

    float* hout = (out_size >= rows * (NA + HID)) ? out + (size_t)rows * NA : sym(g_hfb);

    const int MB = rows / 128;   // 216

    cudaFuncSetAttribute((const void*)gemm_mma<EPI_BIAS>,        cudaFuncAttributeMaxDynamicSharedMemorySize, GSMEM);
    cudaFuncSetAttribute((const void*)gemm_mma<EPI_BIAS_RELU>,   cudaFuncAttributeMaxDynamicSharedMemorySize, GSMEM);
    cudaFuncSetAttribute((const void*)gemm_mma<EPI_PLANES_RELU>, cudaFuncAttributeMaxDynamicSharedMemorySize, GSMEM);

    // --- prep: weight planes + biases ---
    prep_all<<<(TTOT + 255) / 256, 256>>>(W1, Wih, Whh, Wp1, Wp2, Wq, Wk, Wg1, Wd1,
                                          bq, bg1, bd1, bih, bhh, bp2,
                                          pW1h, pW1l, pBrzh, pBrzl, pWnih, pWnil, pWnhh, pWnhl,
                                          pWp1h, pWp1l, pWp2h, pWp2l, pBqkh, pBqkl, pBgdh, pBgdl,
                                          pbqk, pbgd, pbrz, pbp2p);
    // activation planes: inputs -> in planes; hidden -> cat cols 256..511
    conv_split<<<(rows * 352 + 255) / 256, 256>>>(inputs, pinh, pinl, rows, 322, 352, 352, 0);
    conv_split<<<(rows * 256 + 255) / 256, 256>>>(hidden, pcath, pcatl, rows, 256, 256, 512, 256);

    // 1. x-planes = relu(inputs @ W1^T + b1) -> cat cols 0..255     (11 chunks)
    gemm_mma<EPI_PLANES_RELU><<<dim3(2, MB), 256, GSMEM>>>(pinh, pinl, 352, pW1h, pW1l, 352, b1,
                                                           nullptr, pcath, pcatl, 512, 11);
    // 2. rz = [x|hidden] @ Brz^T + (bih+bhh)[0:512]                 (16 chunks)
    gemm_mma<EPI_BIAS><<<dim3(4, MB), 256, GSMEM>>>(pcath, pcatl, 512, pBrzh, pBrzl, 512, pbrz,
                                                    prz, nullptr, nullptr, 512, 16);
    //    inn = x @ Wn_i^T + bih[512:]; hn = hidden @ Wn_h^T + bhh[512:]
    gemm_mma<EPI_BIAS><<<dim3(2, MB), 256, GSMEM>>>(pcath, pcatl, 512, pWnih, pWnil, 256, bih + 512,
                                                    pinn, nullptr, nullptr, 256, 8);
    gemm_mma<EPI_BIAS><<<dim3(2, MB), 256, GSMEM>>>(pcath + 256, pcatl + 256, 512, pWnhh, pWnhl, 256, bhh + 512,
                                                    phn, nullptr, nullptr, 256, 8);
    // 3. GRU -> h fp32 + h planes + fusion planes cols 0..255
    gru_kernel<<<(rows * 256 + 255) / 256, 256>>>(prz, pinn, phn, hidden, hout, phh, phl, pfh, pfl, rows * 256);
    // 4. p-planes = relu(h @ Wp1^T + bp1); logits = p @ Wp2p^T + bp2p (padded N=128)
    gemm_mma<EPI_PLANES_RELU><<<dim3(2, MB), 256, GSMEM>>>(phh, phl, 256, pWp1h, pWp1l, 256, bp1,
                                                           nullptr, pph, ppl, 256, 8);
    gemm_mma<EPI_BIAS><<<dim3(1, MB), 256, GSMEM>>>(pph, ppl, 256, pWp2h, pWp2l, 256, pbp2p,
                                                    plgp, nullptr, nullptr, 128, 8);
    // 5. softmax / sender values / base logits
    logits_post<<<rows / 8, 256>>>(plgp, Wv, bv, out, pattack, psender);
    // 6. [q | key_h] = h @ [Wq; Wk_h]^T + [bq; 0]
    gemm_mma<EPI_BIAS><<<dim3(1, MB), 256, GSMEM>>>(phh, phl, 256, pBqkh, pBqkl, 256, pbqk,
                                                    pqk, nullptr, nullptr, 128, 8);
    // 7. qr, qb
    qr_kernel<<<(rows * 4 + 127) / 128, 128>>>(pqk, Wk, bk, pqr, pqb, rows);
    // 8. attention (batched) -> fusion planes cols 256..287
    attn_batch<<<bs, 256>>>(pqk, pqr, pqb, rel, psender, nullk, nullv, ln_g, ln_b, pfh, pfl);
    // 9. [g1 | d1] = relu(fusion @ [Wg1; Wd1]^T + [bg1; bd1])       (9 chunks)
    gemm_mma<EPI_BIAS_RELU><<<dim3(4, MB), 256, GSMEM>>>(pfh, pfl, 288, pBgdh, pBgdl, 288, pbgd,
                                                         pgd, nullptr, nullptr, 512, 9);
    // 10. gate, delta, fused output
    final_kernel<<<rows / 8, 256>>>(pgd, Wg2, bg2, Wd2, bd2, pattack, out);
}

// round 10
// speedup vs baseline: 3.1537x; 1.0277x over previous
#include <cuda_runtime.h>
#include <cuda_bf16.h>
#include <math.h>
#include <stdint.h>

// ---------------- problem constants ----------------
#define Nn   27
#define NA   33
#define HID  256
#define REL  5
#define INW  322
#define FUSE_SCALE 0.1f
#define NEG  (-10000000000.0f)
#define MAXROWS 27648

// ---------------- scratch (device globals) -------------
__device__ float g_rz    [MAXROWS * 512];
__device__ float g_inn   [MAXROWS * 256];
__device__ float g_hn    [MAXROWS * 256];
__device__ float g_lgp   [MAXROWS * 128];
__device__ float g_attack[MAXROWS * 27];
__device__ float g_sender[MAXROWS * 32];
__device__ float g_qk    [MAXROWS * 128];
__device__ float g_qr    [MAXROWS * 20];
__device__ float g_qb    [MAXROWS * 4];
__device__ float g_gd    [MAXROWS * 512];
__device__ float g_hfb   [MAXROWS * 256];
__device__ float g_bpq   [384];
__device__ float g_bgd   [512];
__device__ float g_brz   [512];
__device__ float g_bp2p  [128];
// bf16 hi/lo weight planes
__device__ __nv_bfloat16 g_W1h [256 * 352],  g_W1l [256 * 352];
__device__ __nv_bfloat16 g_Brzh[512 * 512],  g_Brzl[512 * 512];
__device__ __nv_bfloat16 g_Wnih[256 * 256],  g_Wnil[256 * 256];
__device__ __nv_bfloat16 g_Wnhh[256 * 256],  g_Wnhl[256 * 256];
__device__ __nv_bfloat16 g_Bpqh[384 * 256],  g_Bpql[384 * 256];
__device__ __nv_bfloat16 g_Wp2h[128 * 256],  g_Wp2l[128 * 256];
__device__ __nv_bfloat16 g_Bgdh[512 * 288],  g_Bgdl[512 * 288];
// bf16 hi/lo activation planes
__device__ __nv_bfloat16 g_inh [MAXROWS * 352], g_inl [MAXROWS * 352];
__device__ __nv_bfloat16 g_cath[MAXROWS * 512], g_catl[MAXROWS * 512];
__device__ __nv_bfloat16 g_hh  [MAXROWS * 256], g_hl  [MAXROWS * 256];
__device__ __nv_bfloat16 g_ph  [MAXROWS * 256], g_pl  [MAXROWS * 256];
__device__ __nv_bfloat16 g_fh  [MAXROWS * 288], g_fl  [MAXROWS * 288];

#define EPI_BIAS 1
#define EPI_BIAS_RELU 2
#define EPI_PLANES_RELU 3
#define EPI_MIX 4

// =================== helpers ===============
__device__ __forceinline__ uint32_t smem_u32(const void* p) {
    uint32_t a;
    asm("{ .reg .u64 t; cvta.to.shared.u64 t, %1; cvt.u32.u64 %0, t; }" : "=r"(a) : "l"(p));
    return a;
}
#define CP_ASYNC16(dst, src) \
    asm volatile("cp.async.cg.shared.global [%0], [%1], 16;" :: "r"(dst), "l"(src) : "memory")
#define CP_COMMIT() asm volatile("cp.async.commit_group;" ::: "memory")
#define CP_WAIT0()  asm volatile("cp.async.wait_group 0;" ::: "memory")

__device__ __forceinline__ void ldsm4(uint32_t* d, uint32_t addr) {
    asm volatile("ldmatrix.sync.aligned.m8n8.x4.shared.b16 {%0,%1,%2,%3}, [%4];"
                 : "=r"(d[0]), "=r"(d[1]), "=r"(d[2]), "=r"(d[3]) : "r"(addr));
}
__device__ __forceinline__ void mma16816(float* c, const uint32_t* a, const uint32_t* b) {
    asm volatile("mma.sync.aligned.m16n8k16.row.col.f32.bf16.bf16.f32 "
                 "{%0,%1,%2,%3}, {%4,%5,%6,%7}, {%8,%9}, {%0,%1,%2,%3};"
                 : "+f"(c[0]), "+f"(c[1]), "+f"(c[2]), "+f"(c[3])
                 : "r"(a[0]), "r"(a[1]), "r"(a[2]), "r"(a[3]), "r"(b[0]), "r"(b[1]));
}

// =================== pipelined mma.sync bf16 3-pass GEMM ===================
#define PLNB   10240
#define STAGEB (4 * PLNB)
#define GSMEM  (2 * STAGEB)

template<int EPI>
__global__ void __launch_bounds__(256, 2)
gemm_mma(const __nv_bfloat16* __restrict__ Ahi, const __nv_bfloat16* __restrict__ Alo, int lda,
         const __nv_bfloat16* __restrict__ Bhi, const __nv_bfloat16* __restrict__ Blo, int ldb,
         const float* __restrict__ bias,
         float* __restrict__ C, __nv_bfloat16* __restrict__ Ch, __nv_bfloat16* __restrict__ Cl,
         int ldc, int nChunks, int ldc2)
{
    extern __shared__ __align__(16) char smx[];

    const int tid = threadIdx.x;
    const int wid = tid >> 5, lane = tid & 31;
    const int m0 = blockIdx.y * 128, n0 = blockIdx.x * 128;
    const int r = tid >> 1, hf = tid & 1;

    const uint32_t sbase = smem_u32(smx);
    const uint32_t stO = (uint32_t)r * 80 + hf * 32;

    const int warp_m = (wid & 1) * 64, warp_n = (wid >> 1) * 32;
    const uint32_t aOff = (uint32_t)(warp_m + (lane & 15)) * 80 + (lane >> 4) * 16;
    const uint32_t bRow = (uint32_t)(warp_n + (lane & 7) + ((lane >> 4) << 3));
    const uint32_t bOff = bRow * 80 + ((lane >> 3) & 1) * 16;

    float c[4][4][4];
#pragma unroll
    for (int mt = 0; mt < 4; mt++)
#pragma unroll
        for (int nt = 0; nt < 4; nt++)
#pragma unroll
            for (int q = 0; q < 4; q++) c[mt][nt][q] = 0.f;

    const __nv_bfloat16* ArH = Ahi + (size_t)(m0 + r) * lda + hf * 16;
    const __nv_bfloat16* ArL = Alo + (size_t)(m0 + r) * lda + hf * 16;
    const __nv_bfloat16* BrH = Bhi + (size_t)(n0 + r) * ldb + hf * 16;
    const __nv_bfloat16* BrL = Blo + (size_t)(n0 + r) * ldb + hf * 16;

    auto issue = [&](int ch, int st) {
        const int kc = ch * 32;
        const uint32_t base = sbase + st * STAGEB;
        CP_ASYNC16(base + stO,                 ArH + kc);
        CP_ASYNC16(base + stO + 16,            ArH + kc + 8);
        CP_ASYNC16(base + PLNB + stO,          ArL + kc);
        CP_ASYNC16(base + PLNB + stO + 16,     ArL + kc + 8);
        CP_ASYNC16(base + 2 * PLNB + stO,      BrH + kc);
        CP_ASYNC16(base + 2 * PLNB + stO + 16, BrH + kc + 8);
        CP_ASYNC16(base + 3 * PLNB + stO,      BrL + kc);
        CP_ASYNC16(base + 3 * PLNB + stO + 16, BrL + kc + 8);
        CP_COMMIT();
    };

    issue(0, 0);
    CP_WAIT0();
    __syncthreads();

    for (int ch = 0; ch < nChunks; ch++) {
        const int cur = ch & 1, nxt = cur ^ 1;
        const bool more = (ch + 1 < nChunks);
        if (more) issue(ch + 1, nxt);

        const uint32_t base = sbase + cur * STAGEB;
        const uint32_t sAhi = base, sAlo = base + PLNB;
        const uint32_t sBhi = base + 2 * PLNB, sBlo = base + 3 * PLNB;
#pragma unroll
        for (int ks = 0; ks < 2; ks++) {
            const uint32_t ko = ks * 32;
            uint32_t aF[4][4], bF[4][2];

            // pass 1: Ahi x Bhi
#pragma unroll
            for (int mt = 0; mt < 4; mt++) ldsm4(aF[mt], sAhi + aOff + ko + mt * (16 * 80));
#pragma unroll
            for (int p = 0; p < 2; p++) {
                uint32_t t[4];
                ldsm4(t, sBhi + bOff + ko + p * (16 * 80));
                bF[2 * p][0] = t[0]; bF[2 * p][1] = t[1];
                bF[2 * p + 1][0] = t[2]; bF[2 * p + 1][1] = t[3];
            }
#pragma unroll
            for (int mt = 0; mt < 4; mt++)
#pragma unroll
                for (int nt = 0; nt < 4; nt++) mma16816(c[mt][nt], aF[mt], bF[nt]);

            // pass 2: Ahi x Blo
#pragma unroll
            for (int p = 0; p < 2; p++) {
                uint32_t t[4];
                ldsm4(t, sBlo + bOff + ko + p * (16 * 80));
                bF[2 * p][0] = t[0]; bF[2 * p][1] = t[1];
                bF[2 * p + 1][0] = t[2]; bF[2 * p + 1][1] = t[3];
            }
#pragma unroll
            for (int mt = 0; mt < 4; mt++)
#pragma unroll
                for (int nt = 0; nt < 4; nt++) mma16816(c[mt][nt], aF[mt], bF[nt]);

            // pass 3: Alo x Bhi
#pragma unroll
            for (int mt = 0; mt < 4; mt++) ldsm4(aF[mt], sAlo + aOff + ko + mt * (16 * 80));
#pragma unroll
            for (int p = 0; p < 2; p++) {
                uint32_t t[4];
                ldsm4(t, sBhi + bOff + ko + p * (16 * 80));
                bF[2 * p][0] = t[0]; bF[2 * p][1] = t[1];
                bF[2 * p + 1][0] = t[2]; bF[2 * p + 1][1] = t[3];
            }
#pragma unroll
            for (int mt = 0; mt < 4; mt++)
#pragma unroll
                for (int nt = 0; nt < 4; nt++) mma16816(c[mt][nt], aF[mt], bF[nt]);
        }

        if (more) CP_WAIT0();
        __syncthreads();
    }

    // ---- epilogue ----
    const bool mix_planes = (EPI != EPI_MIX) || (n0 < 256);
#pragma unroll
    for (int mt = 0; mt < 4; mt++) {
        const int row = m0 + warp_m + mt * 16 + (lane >> 2);
#pragma unroll
        for (int nt = 0; nt < 4; nt++) {
            const int col = n0 + warp_n + nt * 8 + (lane & 3) * 2;
            const float b0 = bias[col], b1 = bias[col + 1];
            float v0 = c[mt][nt][0] + b0, v1 = c[mt][nt][1] + b1;
            float v2 = c[mt][nt][2] + b0, v3 = c[mt][nt][3] + b1;
            const bool relu = (EPI == EPI_BIAS_RELU) || (EPI == EPI_PLANES_RELU) ||
                              (EPI == EPI_MIX && mix_planes);
            if (relu) {
                v0 = fmaxf(v0, 0.f); v1 = fmaxf(v1, 0.f);
                v2 = fmaxf(v2, 0.f); v3 = fmaxf(v3, 0.f);
            }
            if (EPI == EPI_PLANES_RELU || (EPI == EPI_MIX && mix_planes)) {
                __nv_bfloat16 h0 = __float2bfloat16(v0), h1 = __float2bfloat16(v1);
                __nv_bfloat16 h2 = __float2bfloat16(v2), h3 = __float2bfloat16(v3);
                *(__nv_bfloat162*)(Ch + (size_t)row * ldc + col) = __nv_bfloat162(h0, h1);
                *(__nv_bfloat162*)(Ch + (size_t)(row + 8) * ldc + col) = __nv_bfloat162(h2, h3);
                *(__nv_bfloat162*)(Cl + (size_t)row * ldc + col) =
                    __nv_bfloat162(__float2bfloat16(v0 - __bfloat162float(h0)),
                                   __float2bfloat16(v1 - __bfloat162float(h1)));
                *(__nv_bfloat162*)(Cl + (size_t)(row + 8) * ldc + col) =
                    __nv_bfloat162(__float2bfloat16(v2 - __bfloat162float(h2)),
                                   __float2bfloat16(v3 - __bfloat162float(h3)));
            } else if (EPI == EPI_MIX) {
                const int c2 = col - 256;
                *(float2*)(C + (size_t)row * ldc2 + c2) = make_float2(v0, v1);
                *(float2*)(C + (size_t)(row + 8) * ldc2 + c2) = make_float2(v2, v3);
            } else {
                *(float2*)(C + (size_t)row * ldc + col) = make_float2(v0, v1);
                *(float2*)(C + (size_t)(row + 8) * ldc + col) = make_float2(v2, v3);
            }
        }
    }
}

// ================= activation split with offset/stride =================
__global__ void conv_split(const float* __restrict__ src, __nv_bfloat16* __restrict__ hi,
                           __nv_bfloat16* __restrict__ lo, int Mrows, int K, int Kpad,
                           int ldo, int off)
{
    int idx = blockIdx.x * blockDim.x + threadIdx.x;
    if (idx >= Mrows * Kpad) return;
    int m = idx / Kpad, k = idx - m * Kpad;
    float v = (k < K) ? src[(size_t)m * K + k] : 0.f;
    __nv_bfloat16 h = __float2bfloat16(v);
    size_t o = (size_t)m * ldo + off + k;
    hi[o] = h;
    lo[o] = __float2bfloat16(v - __bfloat162float(h));
}

// ================= one-shot weight prep =================
#define T0 (256*352)     // W1
#define T1 (512*512)     // Brz
#define T2 (256*256)     // Wn_i
#define T3 (256*256)     // Wn_h
#define T4 (384*256)     // Bpq = [Wp1; Wq; Wk_h]
#define T5 (128*256)     // Wp2 padded
#define T6 (512*288)     // Bgd
#define T7 (384+512+512+128)
#define TTOT (T0+T1+T2+T3+T4+T5+T6+T7)

__global__ void prep_all(const float* __restrict__ W1,  const float* __restrict__ Wih,
                         const float* __restrict__ Whh, const float* __restrict__ Wp1,
                         const float* __restrict__ Wp2, const float* __restrict__ Wq,
                         const float* __restrict__ Wk,  const float* __restrict__ Wg1,
                         const float* __restrict__ Wd1,
                         const float* __restrict__ bp1, const float* __restrict__ bq,
                         const float* __restrict__ bg1, const float* __restrict__ bd1,
                         const float* __restrict__ bih, const float* __restrict__ bhh,
                         const float* __restrict__ bp2,
                         __nv_bfloat16* __restrict__ W1h,  __nv_bfloat16* __restrict__ W1l,
                         __nv_bfloat16* __restrict__ Brzh, __nv_bfloat16* __restrict__ Brzl,
                         __nv_bfloat16* __restrict__ Wnih, __nv_bfloat16* __restrict__ Wnil,
                         __nv_bfloat16* __restrict__ Wnhh, __nv_bfloat16* __restrict__ Wnhl,
                         __nv_bfloat16* __restrict__ Bpqh, __nv_bfloat16* __restrict__ Bpql,
                         __nv_bfloat16* __restrict__ Wp2h, __nv_bfloat16* __restrict__ Wp2l,
                         __nv_bfloat16* __restrict__ Bgdh, __nv_bfloat16* __restrict__ Bgdl,
                         float* __restrict__ pbpq, float* __restrict__ pbgd,
                         float* __restrict__ pbrz, float* __restrict__ pbp2p)
{
    int idx = blockIdx.x * blockDim.x + threadIdx.x;
    if (idx >= TTOT) return;
    float src;
    __nv_bfloat16 *hi, *lo;
    int off;
    if (idx < T0) {
        off = idx;
        int k = off % 352;
        src = (k < 322) ? W1[(off / 352) * 322 + k] : 0.f;
        hi = W1h; lo = W1l;
    } else if (idx < T0 + T1) {
        off = idx - T0;
        int n = off >> 9, k = off & 511;
        src = (k < 256) ? Wih[n * 256 + k] : Whh[n * 256 + (k - 256)];
        hi = Brzh; lo = Brzl;
    } else if (idx < T0 + T1 + T2) {
        off = idx - T0 - T1;
        src = Wih[512 * 256 + off];
        hi = Wnih; lo = Wnil;
    } else if (idx < T0 + T1 + T2 + T3) {
        off = idx - T0 - T1 - T2;
        src = Whh[512 * 256 + off];
        hi = Wnhh; lo = Wnhl;
    } else if (idx < T0 + T1 + T2 + T3 + T4) {
        off = idx - T0 - T1 - T2 - T3;
        int rr = off >> 8, cc = off & 255;
        if (rr < 256) src = Wp1[rr * 256 + cc];
        else if (rr < 320) src = Wq[(rr - 256) * 256 + cc];
        else src = Wk[(size_t)(rr - 320) * (HID + REL) + cc];
        hi = Bpqh; lo = Bpql;
    } else if (idx < T0 + T1 + T2 + T3 + T4 + T5) {
        off = idx - T0 - T1 - T2 - T3 - T4;
        int n = off >> 8;
        src = (n < NA) ? Wp2[n * 256 + (off & 255)] : 0.f;
        hi = Wp2h; lo = Wp2l;
    } else if (idx < T0 + T1 + T2 + T3 + T4 + T5 + T6) {
        off = idx - T0 - T1 - T2 - T3 - T4 - T5;
        int rr = off / 288, cc = off % 288;
        src = (rr < 256) ? Wg1[rr * 288 + cc] : Wd1[(rr - 256) * 288 + cc];
        hi = Bgdh; lo = Bgdl;
    } else {
        off = idx - (T0 + T1 + T2 + T3 + T4 + T5 + T6);
        if (off < 384) {
            pbpq[off] = (off < 256) ? bp1[off] : ((off < 320) ? bq[off - 256] : 0.f);
        } else if (off < 896) {
            int o = off - 384; pbgd[o] = (o < 256) ? bg1[o] : bd1[o - 256];
        } else if (off < 1408) {
            int o = off - 896; pbrz[o] = bih[o] + bhh[o];
        } else {
            int o = off - 1408; pbp2p[o] = (o < NA) ? bp2[o] : 0.f;
        }
        return;
    }
    __nv_bfloat16 h = __float2bfloat16(src);
    hi[off] = h;
    lo[off] = __float2bfloat16(src - __bfloat162float(h));
}

// ================= GRU =================
__global__ void gru_kernel(const float* __restrict__ rz, const float* __restrict__ inn,
                           const float* __restrict__ hn, const float* __restrict__ hin,
                           float* __restrict__ hout,
                           __nv_bfloat16* __restrict__ hh, __nv_bfloat16* __restrict__ hl,
                           __nv_bfloat16* __restrict__ fh, __nv_bfloat16* __restrict__ fl,
                           int total)
{
    int idx = blockIdx.x * blockDim.x + threadIdx.x;
    if (idx >= total) return;
    int r = idx >> 8, c = idx & 255;
    size_t rb = (size_t)r * 512;
    float rg = 1.f / (1.f + expf(-rz[rb + c]));
    float zg = 1.f / (1.f + expf(-rz[rb + 256 + c]));
    float ng = tanhf(inn[idx] + rg * hn[idx]);
    float v = (1.f - zg) * ng + zg * hin[idx];
    hout[idx] = v;
    __nv_bfloat16 h = __float2bfloat16(v);
    __nv_bfloat16 l = __float2bfloat16(v - __bfloat162float(h));
    hh[idx] = h; hl[idx] = l;
    size_t fidx = (size_t)r * 288 + c;
    fh[fidx] = h; fl[fidx] = l;
}

// ================= logits post (padded logits, ld=128) =================
__global__ void __launch_bounds__(256)
logits_post(const float* __restrict__ logits, const float* __restrict__ Wv,
            const float* __restrict__ bv,
            float* __restrict__ out, float* __restrict__ attack,
            float* __restrict__ sender)
{
    __shared__ float Wvs[32 * 29];
    __shared__ float bvs[32];
    __shared__ float vs[8][29];
    int tid = threadIdx.x;
    for (int t = tid; t < 32 * 29; t += 256) Wvs[t] = Wv[t];
    if (tid < 32) bvs[tid] = bv[tid];
    int w = tid >> 5, l = tid & 31;
    int row = blockIdx.x * 8 + w;
    const float* lrow = logits + (size_t)row * 128;
    float al = (l < 27) ? lrow[6 + l] : -INFINITY;
    float mx = al;
#pragma unroll
    for (int o = 16; o > 0; o >>= 1) mx = fmaxf(mx, __shfl_xor_sync(0xffffffffu, mx, o));
    float e = (l < 27) ? expf(al - mx) : 0.f;
    float sum = e;
#pragma unroll
    for (int o = 16; o > 0; o >>= 1) sum += __shfl_xor_sync(0xffffffffu, sum, o);
    float inv = 1.f / sum;
    if (l < 27) vs[w][l] = e * inv;
    if (l == 27) vs[w][27] = 1.0f;
    if (l == 28) vs[w][28] = inv;
    if (l < 27) attack[(size_t)row * 27 + l] = al;
    if (l < 6)  out[(size_t)row * 33 + l] = lrow[l];
    __syncthreads();
    float s = bvs[l];
#pragma unroll
    for (int r = 0; r < 29; r++) s += vs[w][r] * Wvs[l * 29 + r];
    sender[(size_t)row * 32 + l] = s;
}

// ================= qr / qb precompute =================
__global__ void qr_kernel(const float* __restrict__ qk, const float* __restrict__ Wk,
                          const float* __restrict__ bk,
                          float* __restrict__ qr, float* __restrict__ qb, int rows)
{
    int idx = blockIdx.x * blockDim.x + threadIdx.x;
    if (idx >= rows * 4) return;
    int row = idx >> 2, h = idx & 3;
    const float* qp = qk + (size_t)row * 128 + h * 16;
    float acc[5] = {0.f, 0.f, 0.f, 0.f, 0.f};
    float accb = 0.f;
#pragma unroll
    for (int d = 0; d < 16; d++) {
        float qd = qp[d];
        const float* wrow = Wk + (size_t)(h * 16 + d) * (HID + REL) + HID;
#pragma unroll
        for (int r = 0; r < 5; r++) acc[r] += qd * wrow[r];
        accb += qd * bk[h * 16 + d];
    }
#pragma unroll
    for (int r = 0; r < 5; r++) qr[(size_t)row * 20 + h * 5 + r] = acc[r];
    qb[(size_t)row * 4 + h] = accb;
}

// ================= batched attention =================
__global__ void __launch_bounds__(256)
attn_batch(const float* __restrict__ qk, const float* __restrict__ qr,
           const float* __restrict__ qb, const float* __restrict__ rel,
           const float* __restrict__ sender,
           const float* __restrict__ nullk, const float* __restrict__ nullv,
           const float* __restrict__ ln_g, const float* __restrict__ ln_b,
           __nv_bfloat16* __restrict__ fh, __nv_bfloat16* __restrict__ fl)
{
    __shared__ float qk_s[27 * 128];
    __shared__ float sender_s[27 * 32];
    __shared__ float rel_s[27 * 27 * 5];
    __shared__ float qr_s[27 * 20];
    __shared__ float qb_s[27 * 4];
    __shared__ float nk_s[64];
    __shared__ float nv_s[32];
    __shared__ float sc[27 * 112];

    const int b = blockIdx.x;
    const int tid = threadIdx.x;
    const size_t rbase = (size_t)b * 27;

    for (int t = tid; t < 27 * 128; t += 256) qk_s[t] = qk[rbase * 128 + t];
    for (int t = tid; t < 27 * 32; t += 256) sender_s[t] = sender[rbase * 32 + t];
    for (int t = tid; t < 27 * 27 * 5; t += 256) rel_s[t] = rel[(size_t)b * (27 * 27 * 5) + t];
    for (int t = tid; t < 27 * 20; t += 256) qr_s[t] = qr[rbase * 20 + t];
    for (int t = tid; t < 27 * 4; t += 256) qb_s[t] = qb[rbase * 4 + t];
    if (tid < 64) nk_s[tid] = nullk[tid];
    if (tid >= 64 && tid < 96) nv_s[tid - 64] = nullv[tid - 64];
    __syncthreads();

    for (int t = tid; t < 27 * 112; t += 256) {
        int i = t / 112;
        int rem = t - i * 112;
        int j = rem >> 2, h = rem & 3;
        float s;
        if (j == 27) {
            float d = 0.f;
#pragma unroll
            for (int dd = 0; dd < 16; dd++) d += qk_s[i * 128 + h * 16 + dd] * nk_s[h * 16 + dd];
            s = 0.25f * d;
        } else if (j == i) {
            s = NEG;
        } else {
            float d = qb_s[i * 4 + h];
#pragma unroll
            for (int dd = 0; dd < 16; dd++)
                d += qk_s[i * 128 + h * 16 + dd] * qk_s[j * 128 + 64 + h * 16 + dd];
            const float* rr = &rel_s[(i * 27 + j) * 5];
#pragma unroll
            for (int r = 0; r < 5; r++) d += qr_s[i * 20 + h * 5 + r] * rr[r];
            s = 0.25f * d;
        }
        sc[t] = s;
    }
    __syncthreads();

    for (int t = tid; t < 108; t += 256) {
        int i = t >> 2, h = t & 3;
        float* scp = &sc[i * 112 + h];
        float t0 = -INFINITY, t1 = -INFINITY, t2 = -INFINITY, t3 = -INFINITY;
#pragma unroll
        for (int j = 0; j < 28; j++) {
            float v = scp[j * 4];
            if (v > t0)      { t3 = t2; t2 = t1; t1 = t0; t0 = v; }
            else if (v > t1) { t3 = t2; t2 = t1; t1 = v; }
            else if (v > t2) { t3 = t2; t2 = v; }
            else if (v > t3) { t3 = v; }
        }
        float thr = t3, mxv = t0, sum = 0.f;
        float e[28];
#pragma unroll
        for (int j = 0; j < 28; j++) {
            float v = scp[j * 4];
            float ev = (v >= thr) ? expf(v - mxv) : 0.f;
            e[j] = ev; sum += ev;
        }
        float inv = 1.f / sum;
#pragma unroll
        for (int j = 0; j < 28; j++) scp[j * 4] = e[j] * inv;
    }
    __syncthreads();

    int w = tid >> 5, l = tid & 31;
    int h = l >> 3;
    for (int i = w; i < 27; i += 8) {
        const float* scp = &sc[i * 112];
        float m = scp[108 + h] * nv_s[l];
#pragma unroll
        for (int j = 0; j < 27; j++) m += scp[j * 4 + h] * sender_s[j * 32 + l];
        float s = m, s2 = m * m;
#pragma unroll
        for (int o = 16; o > 0; o >>= 1) {
            s  += __shfl_xor_sync(0xffffffffu, s, o);
            s2 += __shfl_xor_sync(0xffffffffu, s2, o);
        }
        float mu = s * (1.f / 32.f);
        float var = s2 * (1.f / 32.f) - mu * mu;
        float nm = (m - mu) * rsqrtf(var + 1e-5f) * ln_g[l] + ln_b[l];
        size_t fidx = (rbase + i) * 288 + 256 + l;
        __nv_bfloat16 hb = __float2bfloat16(nm);
        fh[fidx] = hb;
        fl[fidx] = __float2bfloat16(nm - __bfloat162float(hb));
    }
}

// ================= final =================
__global__ void __launch_bounds__(256)
final_kernel(const float* __restrict__ gd,
             const float* __restrict__ Wg2, const float* __restrict__ bg2,
             const float* __restrict__ Wd2, const float* __restrict__ bd2,
             const float* __restrict__ attack,
             float* __restrict__ out)
{
    __shared__ float Wd2s[256 * 28];
    __shared__ float wg2s[256];
    int tid = threadIdx.x;
    for (int t = tid; t < 27 * 256; t += 256) {
        int l = t >> 8, k = t & 255;
        Wd2s[k * 28 + l] = Wd2[t];
    }
    if (tid < 256) wg2s[tid] = Wg2[tid];
    __syncthreads();

    int w = tid >> 5, l = tid & 31;
    int row = blockIdx.x * 8 + w;
    const float* g1r = gd + (size_t)row * 512;
    const float* d1r = g1r + 256;
    float gs = 0.f;
#pragma unroll
    for (int i = 0; i < 8; i++) gs += g1r[l + i * 32] * wg2s[l + i * 32];
#pragma unroll
    for (int o = 16; o > 0; o >>= 1) gs += __shfl_xor_sync(0xffffffffu, gs, o);
    float gate = 1.f / (1.f + expf(-(gs + bg2[0])));
    if (l < 27) {
        float d = bd2[l];
#pragma unroll 8
        for (int k = 0; k < 256; k++) d += d1r[k] * Wd2s[k * 28 + l];
        out[(size_t)row * 33 + 6 + l] = attack[(size_t)row * 27 + l] + FUSE_SCALE * gate * d;
    }
}

// ================= host launcher =================
static float* sym(const void* symbol)
{
    void* p = nullptr;
    cudaGetSymbolAddress(&p, symbol);
    return (float*)p;
}
static __nv_bfloat16* symb(const void* symbol)
{
    void* p = nullptr;
    cudaGetSymbolAddress(&p, symbol);
    return (__nv_bfloat16*)p;
}

extern "C" void kernel_launch(void* const* d_in, const int* in_sizes, int n_in,
                              void* d_out, int out_size)
{
    const float* inputs = (const float*)d_in[0];
    const float* hidden = (const float*)d_in[1];
    const float* rel    = (const float*)d_in[2];
    const float* W1     = (const float*)d_in[3];
    const float* b1     = (const float*)d_in[4];
    const float* Wih    = (const float*)d_in[5];
    const float* bih    = (const float*)d_in[6];
    const float* Whh    = (const float*)d_in[7];
    const float* bhh    = (const float*)d_in[8];
    const float* Wp1    = (const float*)d_in[9];
    const float* bp1    = (const float*)d_in[10];
    const float* Wp2    = (const float*)d_in[11];
    const float* bp2    = (const float*)d_in[12];
    const float* Wq     = (const float*)d_in[13];
    const float* bq     = (const float*)d_in[14];
    const float* Wk     = (const float*)d_in[15];
    const float* bk     = (const float*)d_in[16];
    const float* Wv     = (const float*)d_in[17];
    const float* bv     = (const float*)d_in[18];
    const float* ln_g   = (const float*)d_in[19];
    const float* ln_b   = (const float*)d_in[20];
    const float* Wg1    = (const float*)d_in[21];
    const float* bg1    = (const float*)d_in[22];
    const float* Wg2    = (const float*)d_in[23];
    const float* bg2    = (const float*)d_in[24];
    const float* Wd1    = (const float*)d_in[25];
    const float* bd1    = (const float*)d_in[26];
    const float* Wd2    = (const float*)d_in[27];
    const float* bd2    = (const float*)d_in[28];
    const float* nullk  = (const float*)d_in[29];
    const float* nullv  = (const float*)d_in[30];

    const int rows = in_sizes[0] / INW;    // 27648
    const int bs = rows / Nn;
    float* out = (float*)d_out;

    float* prz     = sym(g_rz);
    float* pinn    = sym(g_inn);
    float* phn     = sym(g_hn);
    float* plgp    = sym(g_lgp);
    float* pattack = sym(g_attack);
    float* psender = sym(g_sender);
    float* pqk     = sym(g_qk);
    float* pqr     = sym(g_qr);
    float* pqb     = sym(g_qb);
    float* pgd     = sym(g_gd);
    float* pbpq    = sym(g_bpq);
    float* pbgd    = sym(g_bgd);
    float* pbrz    = sym(g_brz);
    float* pbp2p   = sym(g_bp2p);

    __nv_bfloat16 *pW1h = symb(g_W1h),   *pW1l = symb(g_W1l);
    __nv_bfloat16 *pBrzh = symb(g_Brzh), *pBrzl = symb(g_Brzl);
    __nv_bfloat16 *pWnih = symb(g_Wnih), *pWnil = symb(g_Wnil);
    __nv_bfloat16 *pWnhh = symb(g_Wnhh), *pWnhl = symb(g_Wnhl);
    __nv_bfloat16 *pBpqh = symb(g_Bpqh), *pBpql = symb(g_Bpql);
    __nv_bfloat16 *pWp2h = symb(g_Wp2h), *pWp2l = symb(g_Wp2l);
    __nv_bfloat16 *pBgdh = symb(g_Bgdh), *pBgdl = symb(g_Bgdl);
    __nv_bfloat16 *pinh = symb(g_inh),   *pinl = symb(g_inl);
    __nv_bfloat16 *pcath = symb(g_cath), *pcatl = symb(g_catl);
    __nv_bfloat16 *phh = symb(g_hh),     *phl = symb(g_hl);
    __nv_bfloat16 *pph = symb(g_ph),     *ppl = symb(g_pl);
    __nv_bfloat16 *pfh = symb(g_fh),     *pfl = symb(g_fl);

    float* hout = (out_size >= rows * (NA + HID)) ? out + (size_t)rows * NA : sym(g_hfb);

    const int MB = rows / 128;   // 216

    cudaFuncSetAttribute((const void*)gemm_mma<EPI_BIAS>,        cudaFuncAttributeMaxDynamicSharedMemorySize, GSMEM);
    cudaFuncSetAttribute((const void*)gemm_mma<EPI_BIAS_RELU>,   cudaFuncAttributeMaxDynamicSharedMemorySize, GSMEM);
    cudaFuncSetAttribute((const void*)gemm_mma<EPI_PLANES_RELU>, cudaFuncAttributeMaxDynamicSharedMemorySize, GSMEM);
    cudaFuncSetAttribute((const void*)gemm_mma<EPI_MIX>,         cudaFuncAttributeMaxDynamicSharedMemorySize, GSMEM);

    // side stream + fork/join events (created once; graph capture records parallel branches)
    static cudaStream_t s1 = nullptr;
    static cudaEvent_t e0 = nullptr, eH = nullptr, eN = nullptr, e2 = nullptr, eQ = nullptr;
    if (!s1) {
        cudaStreamCreateWithFlags(&s1, cudaStreamNonBlocking);
        cudaEventCreateWithFlags(&e0, cudaEventDisableTiming);
        cudaEventCreateWithFlags(&eH, cudaEventDisableTiming);
        cudaEventCreateWithFlags(&eN, cudaEventDisableTiming);
        cudaEventCreateWithFlags(&e2, cudaEventDisableTiming);
        cudaEventCreateWithFlags(&eQ, cudaEventDisableTiming);
    }

    // --- prep (stream 0) ---
    prep_all<<<(TTOT + 255) / 256, 256>>>(W1, Wih, Whh, Wp1, Wp2, Wq, Wk, Wg1, Wd1,
                                          bp1, bq, bg1, bd1, bih, bhh, bp2,
                                          pW1h, pW1l, pBrzh, pBrzl, pWnih, pWnil, pWnhh, pWnhl,
                                          pBpqh, pBpql, pWp2h, pWp2l, pBgdh, pBgdl,
                                          pbpq, pbgd, pbrz, pbp2p);
    conv_split<<<(rows * 352 + 255) / 256, 256>>>(inputs, pinh, pinl, rows, 322, 352, 352, 0);

    // fork: s1 does conv_split(hidden) -> hn GEMM
    cudaEventRecord(e0, 0);
    cudaStreamWaitEvent(s1, e0, 0);
    conv_split<<<(rows * 256 + 255) / 256, 256, 0, s1>>>(hidden, pcath, pcatl, rows, 256, 256, 512, 256);
    cudaEventRecord(eH, s1);
    gemm_mma<EPI_BIAS><<<dim3(2, MB), 256, GSMEM, s1>>>(pcath + 256, pcatl + 256, 512, pWnhh, pWnhl, 256,
                                                        bhh + 512, phn, nullptr, nullptr, 256, 8, 0);
    cudaEventRecord(eN, s1);

    // main chain (stream 0)
    // 1. x-planes = relu(inputs @ W1^T + b1) -> cat cols 0..255
    gemm_mma<EPI_PLANES_RELU><<<dim3(2, MB), 256, GSMEM>>>(pinh, pinl, 352, pW1h, pW1l, 352, b1,
                                                           nullptr, pcath, pcatl, 512, 11, 0);
    // 2. rz (needs hidden planes from s1)
    cudaStreamWaitEvent(0, eH, 0);
    gemm_mma<EPI_BIAS><<<dim3(4, MB), 256, GSMEM>>>(pcath, pcatl, 512, pBrzh, pBrzl, 512, pbrz,
                                                    prz, nullptr, nullptr, 512, 16, 0);
    gemm_mma<EPI_BIAS><<<dim3(2, MB), 256, GSMEM>>>(pcath, pcatl, 512, pWnih, pWnil, 256, bih + 512,
                                                    pinn, nullptr, nullptr, 256, 8, 0);
    // 3. GRU (needs hn from s1)
    cudaStreamWaitEvent(0, eN, 0);
    gru_kernel<<<(rows * 256 + 255) / 256, 256>>>(prz, pinn, phn, hidden, hout, phh, phl, pfh, pfl, rows * 256);
    // 4. merged [p-planes | qk] = h @ Bpq^T + bpq  (cols 0-255 planes+relu, 256-383 fp32)
    gemm_mma<EPI_MIX><<<dim3(3, MB), 256, GSMEM>>>(phh, phl, 256, pBpqh, pBpql, 256, pbpq,
                                                   pqk, pph, ppl, 256, 8, 128);
    cudaEventRecord(e2, 0);
    // s1: qr from qk
    cudaStreamWaitEvent(s1, e2, 0);
    qr_kernel<<<(rows * 4 + 127) / 128, 128, 0, s1>>>(pqk, Wk, bk, pqr, pqb, rows);
    cudaEventRecord(eQ, s1);
    // 5. logits chain on stream 0
    gemm_mma<EPI_BIAS><<<dim3(1, MB), 256, GSMEM>>>(pph, ppl, 256, pWp2h, pWp2l, 256, pbp2p,
                                                    plgp, nullptr, nullptr, 128, 8, 0);
    logits_post<<<rows / 8, 256>>>(plgp, Wv, bv, out, pattack, psender);
    // 6. attention (needs qr from s1)
    cudaStreamWaitEvent(0, eQ, 0);
    attn_batch<<<bs, 256>>>(pqk, pqr, pqb, rel, psender, nullk, nullv, ln_g, ln_b, pfh, pfl);
    // 7. [g1 | d1]
    gemm_mma<EPI_BIAS_RELU><<<dim3(4, MB), 256, GSMEM>>>(pfh, pfl, 288, pBgdh, pBgdl, 288, pbgd,
                                                         pgd, nullptr, nullptr, 512, 9, 0);
    // 8. final
    final_kernel<<<rows / 8, 256>>>(pgd, Wg2, bg2, Wd2, bd2, pattack, out);
}

// round 11
// speedup vs baseline: 3.7104x; 1.1765x over previous
#include <cuda_runtime.h>
#include <cuda_fp16.h>
#include <math.h>
#include <stdint.h>

// ---------------- problem constants ----------------
#define Nn   27
#define NA   33
#define HID  256
#define REL  5
#define INW  322
#define FUSE_SCALE 0.1f
#define NEG  (-10000000000.0f)
#define MAXROWS 27648

// ---------------- scratch (device globals) -------------
__device__ float g_rz    [MAXROWS * 512];
__device__ float g_inn   [MAXROWS * 256];
__device__ float g_hn    [MAXROWS * 256];
__device__ float g_lgp   [MAXROWS * 128];
__device__ float g_attack[MAXROWS * 27];
__device__ float g_sender[MAXROWS * 32];
__device__ float g_qk    [MAXROWS * 128];
__device__ float g_qr    [MAXROWS * 20];
__device__ float g_qb    [MAXROWS * 4];
__device__ float g_gd    [MAXROWS * 512];
__device__ float g_hfb   [MAXROWS * 256];
__device__ float g_bpq   [384];
__device__ float g_bgd   [512];
__device__ float g_brz   [512];
__device__ float g_bp2p  [128];
// fp16 weight planes (single plane; K padded to 32-multiples)
__device__ __half g_W1h [256 * 352];
__device__ __half g_Brzh[512 * 512];
__device__ __half g_Wnih[256 * 256];
__device__ __half g_Wnhh[256 * 256];
__device__ __half g_Bpqh[384 * 256];
__device__ __half g_Wp2h[128 * 256];
__device__ __half g_Bgdh[512 * 288];
// fp16 hi/lo activation planes
__device__ __half g_inh [MAXROWS * 352], g_inl [MAXROWS * 352];
__device__ __half g_cath[MAXROWS * 512], g_catl[MAXROWS * 512];
__device__ __half g_hh  [MAXROWS * 256], g_hl  [MAXROWS * 256];
__device__ __half g_ph  [MAXROWS * 256], g_pl  [MAXROWS * 256];
__device__ __half g_fh  [MAXROWS * 288], g_fl  [MAXROWS * 288];

#define EPI_BIAS 1
#define EPI_BIAS_RELU 2
#define EPI_PLANES_RELU 3
#define EPI_MIX 4

// =================== helpers ===============
__device__ __forceinline__ uint32_t smem_u32(const void* p) {
    uint32_t a;
    asm("{ .reg .u64 t; cvta.to.shared.u64 t, %1; cvt.u32.u64 %0, t; }" : "=r"(a) : "l"(p));
    return a;
}
#define CP_ASYNC16(dst, src) \
    asm volatile("cp.async.cg.shared.global [%0], [%1], 16;" :: "r"(dst), "l"(src) : "memory")
#define CP_COMMIT() asm volatile("cp.async.commit_group;" ::: "memory")
#define CP_WAIT0()  asm volatile("cp.async.wait_group 0;" ::: "memory")

__device__ __forceinline__ void ldsm4(uint32_t* d, uint32_t addr) {
    asm volatile("ldmatrix.sync.aligned.m8n8.x4.shared.b16 {%0,%1,%2,%3}, [%4];"
                 : "=r"(d[0]), "=r"(d[1]), "=r"(d[2]), "=r"(d[3]) : "r"(addr));
}
__device__ __forceinline__ void mma16816(float* c, const uint32_t* a, const uint32_t* b) {
    asm volatile("mma.sync.aligned.m16n8k16.row.col.f32.f16.f16.f32 "
                 "{%0,%1,%2,%3}, {%4,%5,%6,%7}, {%8,%9}, {%0,%1,%2,%3};"
                 : "+f"(c[0]), "+f"(c[1]), "+f"(c[2]), "+f"(c[3])
                 : "r"(a[0]), "r"(a[1]), "r"(a[2]), "r"(a[3]), "r"(b[0]), "r"(b[1]));
}

// =================== pipelined mma.sync fp16 2-pass GEMM ===================
// C[M,N] = (Ahi+Alo)[M,Kpad] @ Bh[N,Kpad]^T (+bias)(relu)
// Block tile 128x128, 8 warps (2m x 4n), warp tile 64x32, BK=32, 2-stage cp.async.
// Planes per stage: Ahi, Alo, Bh (3 x 10240 B). 2 CTAs/SM.
#define PLNB   10240
#define STAGEB (3 * PLNB)
#define GSMEM  (2 * STAGEB)

template<int EPI>
__global__ void __launch_bounds__(256, 2)
gemm_mma(const __half* __restrict__ Ahi, const __half* __restrict__ Alo, int lda,
         const __half* __restrict__ Bh, int ldb,
         const float* __restrict__ bias,
         float* __restrict__ C, __half* __restrict__ Ch, __half* __restrict__ Cl,
         int ldc, int nChunks, int ldc2)
{
    extern __shared__ __align__(16) char smx[];

    const int tid = threadIdx.x;
    const int wid = tid >> 5, lane = tid & 31;
    const int m0 = blockIdx.y * 128, n0 = blockIdx.x * 128;
    const int r = tid >> 1, hf = tid & 1;

    const uint32_t sbase = smem_u32(smx);
    const uint32_t stO = (uint32_t)r * 80 + hf * 32;

    const int warp_m = (wid & 1) * 64, warp_n = (wid >> 1) * 32;
    const uint32_t aOff = (uint32_t)(warp_m + (lane & 15)) * 80 + (lane >> 4) * 16;
    const uint32_t bRow = (uint32_t)(warp_n + (lane & 7) + ((lane >> 4) << 3));
    const uint32_t bOff = bRow * 80 + ((lane >> 3) & 1) * 16;

    float c[4][4][4];
#pragma unroll
    for (int mt = 0; mt < 4; mt++)
#pragma unroll
        for (int nt = 0; nt < 4; nt++)
#pragma unroll
            for (int q = 0; q < 4; q++) c[mt][nt][q] = 0.f;

    const __half* ArH = Ahi + (size_t)(m0 + r) * lda + hf * 16;
    const __half* ArL = Alo + (size_t)(m0 + r) * lda + hf * 16;
    const __half* BrH = Bh + (size_t)(n0 + r) * ldb + hf * 16;

    auto issue = [&](int ch, int st) {
        const int kc = ch * 32;
        const uint32_t base = sbase + st * STAGEB;
        CP_ASYNC16(base + stO,                 ArH + kc);
        CP_ASYNC16(base + stO + 16,            ArH + kc + 8);
        CP_ASYNC16(base + PLNB + stO,          ArL + kc);
        CP_ASYNC16(base + PLNB + stO + 16,     ArL + kc + 8);
        CP_ASYNC16(base + 2 * PLNB + stO,      BrH + kc);
        CP_ASYNC16(base + 2 * PLNB + stO + 16, BrH + kc + 8);
        CP_COMMIT();
    };

    issue(0, 0);
    CP_WAIT0();
    __syncthreads();

    for (int ch = 0; ch < nChunks; ch++) {
        const int cur = ch & 1, nxt = cur ^ 1;
        const bool more = (ch + 1 < nChunks);
        if (more) issue(ch + 1, nxt);

        const uint32_t base = sbase + cur * STAGEB;
        const uint32_t sAhi = base, sAlo = base + PLNB;
        const uint32_t sBh = base + 2 * PLNB;
#pragma unroll
        for (int ks = 0; ks < 2; ks++) {
            const uint32_t ko = ks * 32;
            uint32_t aF[4][4], bF[4][2];

            // B fragments loaded once, reused by both passes
#pragma unroll
            for (int p = 0; p < 2; p++) {
                uint32_t t[4];
                ldsm4(t, sBh + bOff + ko + p * (16 * 80));
                bF[2 * p][0] = t[0]; bF[2 * p][1] = t[1];
                bF[2 * p + 1][0] = t[2]; bF[2 * p + 1][1] = t[3];
            }
            // pass 1: Ahi x B
#pragma unroll
            for (int mt = 0; mt < 4; mt++) ldsm4(aF[mt], sAhi + aOff + ko + mt * (16 * 80));
#pragma unroll
            for (int mt = 0; mt < 4; mt++)
#pragma unroll
                for (int nt = 0; nt < 4; nt++) mma16816(c[mt][nt], aF[mt], bF[nt]);
            // pass 2: Alo x B
#pragma unroll
            for (int mt = 0; mt < 4; mt++) ldsm4(aF[mt], sAlo + aOff + ko + mt * (16 * 80));
#pragma unroll
            for (int mt = 0; mt < 4; mt++)
#pragma unroll
                for (int nt = 0; nt < 4; nt++) mma16816(c[mt][nt], aF[mt], bF[nt]);
        }

        if (more) CP_WAIT0();
        __syncthreads();
    }

    // ---- epilogue ----
    const bool mix_planes = (EPI != EPI_MIX) || (n0 < 256);
#pragma unroll
    for (int mt = 0; mt < 4; mt++) {
        const int row = m0 + warp_m + mt * 16 + (lane >> 2);
#pragma unroll
        for (int nt = 0; nt < 4; nt++) {
            const int col = n0 + warp_n + nt * 8 + (lane & 3) * 2;
            const float b0 = bias[col], b1 = bias[col + 1];
            float v0 = c[mt][nt][0] + b0, v1 = c[mt][nt][1] + b1;
            float v2 = c[mt][nt][2] + b0, v3 = c[mt][nt][3] + b1;
            const bool relu = (EPI == EPI_BIAS_RELU) || (EPI == EPI_PLANES_RELU) ||
                              (EPI == EPI_MIX && mix_planes);
            if (relu) {
                v0 = fmaxf(v0, 0.f); v1 = fmaxf(v1, 0.f);
                v2 = fmaxf(v2, 0.f); v3 = fmaxf(v3, 0.f);
            }
            if (EPI == EPI_PLANES_RELU || (EPI == EPI_MIX && mix_planes)) {
                __half h0 = __float2half(v0), h1 = __float2half(v1);
                __half h2 = __float2half(v2), h3 = __float2half(v3);
                *(__half2*)(Ch + (size_t)row * ldc + col) = __halves2half2(h0, h1);
                *(__half2*)(Ch + (size_t)(row + 8) * ldc + col) = __halves2half2(h2, h3);
                *(__half2*)(Cl + (size_t)row * ldc + col) =
                    __halves2half2(__float2half(v0 - __half2float(h0)),
                                   __float2half(v1 - __half2float(h1)));
                *(__half2*)(Cl + (size_t)(row + 8) * ldc + col) =
                    __halves2half2(__float2half(v2 - __half2float(h2)),
                                   __float2half(v3 - __half2float(h3)));
            } else if (EPI == EPI_MIX) {
                const int c2 = col - 256;
                *(float2*)(C + (size_t)row * ldc2 + c2) = make_float2(v0, v1);
                *(float2*)(C + (size_t)(row + 8) * ldc2 + c2) = make_float2(v2, v3);
            } else {
                *(float2*)(C + (size_t)row * ldc + col) = make_float2(v0, v1);
                *(float2*)(C + (size_t)(row + 8) * ldc + col) = make_float2(v2, v3);
            }
        }
    }
}

// ================= activation split: fp32 -> fp16 hi/lo =================
__global__ void conv_split(const float* __restrict__ src, __half* __restrict__ hi,
                           __half* __restrict__ lo, int Mrows, int K, int Kpad,
                           int ldo, int off)
{
    int idx = blockIdx.x * blockDim.x + threadIdx.x;
    if (idx >= Mrows * Kpad) return;
    int m = idx / Kpad, k = idx - m * Kpad;
    float v = (k < K) ? src[(size_t)m * K + k] : 0.f;
    __half h = __float2half(v);
    size_t o = (size_t)m * ldo + off + k;
    hi[o] = h;
    lo[o] = __float2half(v - __half2float(h));
}

// ================= one-shot weight prep (single fp16 plane) =================
#define T0 (256*352)     // W1
#define T1 (512*512)     // Brz
#define T2 (256*256)     // Wn_i
#define T3 (256*256)     // Wn_h
#define T4 (384*256)     // Bpq = [Wp1; Wq; Wk_h]
#define T5 (128*256)     // Wp2 padded
#define T6 (512*288)     // Bgd
#define T7 (384+512+512+128)
#define TTOT (T0+T1+T2+T3+T4+T5+T6+T7)

__global__ void prep_all(const float* __restrict__ W1,  const float* __restrict__ Wih,
                         const float* __restrict__ Whh, const float* __restrict__ Wp1,
                         const float* __restrict__ Wp2, const float* __restrict__ Wq,
                         const float* __restrict__ Wk,  const float* __restrict__ Wg1,
                         const float* __restrict__ Wd1,
                         const float* __restrict__ bp1, const float* __restrict__ bq,
                         const float* __restrict__ bg1, const float* __restrict__ bd1,
                         const float* __restrict__ bih, const float* __restrict__ bhh,
                         const float* __restrict__ bp2,
                         __half* __restrict__ W1h,  __half* __restrict__ Brzh,
                         __half* __restrict__ Wnih, __half* __restrict__ Wnhh,
                         __half* __restrict__ Bpqh, __half* __restrict__ Wp2h,
                         __half* __restrict__ Bgdh,
                         float* __restrict__ pbpq, float* __restrict__ pbgd,
                         float* __restrict__ pbrz, float* __restrict__ pbp2p)
{
    int idx = blockIdx.x * blockDim.x + threadIdx.x;
    if (idx >= TTOT) return;
    float src;
    __half* dst;
    int off;
    if (idx < T0) {
        off = idx;
        int k = off % 352;
        src = (k < 322) ? W1[(off / 352) * 322 + k] : 0.f;
        dst = W1h;
    } else if (idx < T0 + T1) {
        off = idx - T0;
        int n = off >> 9, k = off & 511;
        src = (k < 256) ? Wih[n * 256 + k] : Whh[n * 256 + (k - 256)];
        dst = Brzh;
    } else if (idx < T0 + T1 + T2) {
        off = idx - T0 - T1;
        src = Wih[512 * 256 + off];
        dst = Wnih;
    } else if (idx < T0 + T1 + T2 + T3) {
        off = idx - T0 - T1 - T2;
        src = Whh[512 * 256 + off];
        dst = Wnhh;
    } else if (idx < T0 + T1 + T2 + T3 + T4) {
        off = idx - T0 - T1 - T2 - T3;
        int rr = off >> 8, cc = off & 255;
        if (rr < 256) src = Wp1[rr * 256 + cc];
        else if (rr < 320) src = Wq[(rr - 256) * 256 + cc];
        else src = Wk[(size_t)(rr - 320) * (HID + REL) + cc];
        dst = Bpqh;
    } else if (idx < T0 + T1 + T2 + T3 + T4 + T5) {
        off = idx - T0 - T1 - T2 - T3 - T4;
        int n = off >> 8;
        src = (n < NA) ? Wp2[n * 256 + (off & 255)] : 0.f;
        dst = Wp2h;
    } else if (idx < T0 + T1 + T2 + T3 + T4 + T5 + T6) {
        off = idx - T0 - T1 - T2 - T3 - T4 - T5;
        int rr = off / 288, cc = off % 288;
        src = (rr < 256) ? Wg1[rr * 288 + cc] : Wd1[(rr - 256) * 288 + cc];
        dst = Bgdh;
    } else {
        off = idx - (T0 + T1 + T2 + T3 + T4 + T5 + T6);
        if (off < 384) {
            pbpq[off] = (off < 256) ? bp1[off] : ((off < 320) ? bq[off - 256] : 0.f);
        } else if (off < 896) {
            int o = off - 384; pbgd[o] = (o < 256) ? bg1[o] : bd1[o - 256];
        } else if (off < 1408) {
            int o = off - 896; pbrz[o] = bih[o] + bhh[o];
        } else {
            int o = off - 1408; pbp2p[o] = (o < NA) ? bp2[o] : 0.f;
        }
        return;
    }
    dst[off] = __float2half(src);
}

// ================= GRU =================
__global__ void gru_kernel(const float* __restrict__ rz, const float* __restrict__ inn,
                           const float* __restrict__ hn, const float* __restrict__ hin,
                           float* __restrict__ hout,
                           __half* __restrict__ hh, __half* __restrict__ hl,
                           __half* __restrict__ fh, __half* __restrict__ fl,
                           int total)
{
    int idx = blockIdx.x * blockDim.x + threadIdx.x;
    if (idx >= total) return;
    int r = idx >> 8, c = idx & 255;
    size_t rb = (size_t)r * 512;
    float rg = 1.f / (1.f + expf(-rz[rb + c]));
    float zg = 1.f / (1.f + expf(-rz[rb + 256 + c]));
    float ng = tanhf(inn[idx] + rg * hn[idx]);
    float v = (1.f - zg) * ng + zg * hin[idx];
    hout[idx] = v;
    __half h = __float2half(v);
    __half l = __float2half(v - __half2float(h));
    hh[idx] = h; hl[idx] = l;
    size_t fidx = (size_t)r * 288 + c;
    fh[fidx] = h; fl[fidx] = l;
}

// ================= logits post (padded logits, ld=128) =================
__global__ void __launch_bounds__(256)
logits_post(const float* __restrict__ logits, const float* __restrict__ Wv,
            const float* __restrict__ bv,
            float* __restrict__ out, float* __restrict__ attack,
            float* __restrict__ sender)
{
    __shared__ float Wvs[32 * 29];
    __shared__ float bvs[32];
    __shared__ float vs[8][29];
    int tid = threadIdx.x;
    for (int t = tid; t < 32 * 29; t += 256) Wvs[t] = Wv[t];
    if (tid < 32) bvs[tid] = bv[tid];
    int w = tid >> 5, l = tid & 31;
    int row = blockIdx.x * 8 + w;
    const float* lrow = logits + (size_t)row * 128;
    float al = (l < 27) ? lrow[6 + l] : -INFINITY;
    float mx = al;
#pragma unroll
    for (int o = 16; o > 0; o >>= 1) mx = fmaxf(mx, __shfl_xor_sync(0xffffffffu, mx, o));
    float e = (l < 27) ? expf(al - mx) : 0.f;
    float sum = e;
#pragma unroll
    for (int o = 16; o > 0; o >>= 1) sum += __shfl_xor_sync(0xffffffffu, sum, o);
    float inv = 1.f / sum;
    if (l < 27) vs[w][l] = e * inv;
    if (l == 27) vs[w][27] = 1.0f;
    if (l == 28) vs[w][28] = inv;
    if (l < 27) attack[(size_t)row * 27 + l] = al;
    if (l < 6)  out[(size_t)row * 33 + l] = lrow[l];
    __syncthreads();
    float s = bvs[l];
#pragma unroll
    for (int r = 0; r < 29; r++) s += vs[w][r] * Wvs[l * 29 + r];
    sender[(size_t)row * 32 + l] = s;
}

// ================= qr / qb precompute =================
__global__ void qr_kernel(const float* __restrict__ qk, const float* __restrict__ Wk,
                          const float* __restrict__ bk,
                          float* __restrict__ qr, float* __restrict__ qb, int rows)
{
    int idx = blockIdx.x * blockDim.x + threadIdx.x;
    if (idx >= rows * 4) return;
    int row = idx >> 2, h = idx & 3;
    const float* qp = qk + (size_t)row * 128 + h * 16;
    float acc[5] = {0.f, 0.f, 0.f, 0.f, 0.f};
    float accb = 0.f;
#pragma unroll
    for (int d = 0; d < 16; d++) {
        float qd = qp[d];
        const float* wrow = Wk + (size_t)(h * 16 + d) * (HID + REL) + HID;
#pragma unroll
        for (int r = 0; r < 5; r++) acc[r] += qd * wrow[r];
        accb += qd * bk[h * 16 + d];
    }
#pragma unroll
    for (int r = 0; r < 5; r++) qr[(size_t)row * 20 + h * 5 + r] = acc[r];
    qb[(size_t)row * 4 + h] = accb;
}

// ================= batched attention =================
__global__ void __launch_bounds__(256)
attn_batch(const float* __restrict__ qk, const float* __restrict__ qr,
           const float* __restrict__ qb, const float* __restrict__ rel,
           const float* __restrict__ sender,
           const float* __restrict__ nullk, const float* __restrict__ nullv,
           const float* __restrict__ ln_g, const float* __restrict__ ln_b,
           __half* __restrict__ fh, __half* __restrict__ fl)
{
    __shared__ float qk_s[27 * 128];
    __shared__ float sender_s[27 * 32];
    __shared__ float rel_s[27 * 27 * 5];
    __shared__ float qr_s[27 * 20];
    __shared__ float qb_s[27 * 4];
    __shared__ float nk_s[64];
    __shared__ float nv_s[32];
    __shared__ float sc[27 * 112];

    const int b = blockIdx.x;
    const int tid = threadIdx.x;
    const size_t rbase = (size_t)b * 27;

    for (int t = tid; t < 27 * 128; t += 256) qk_s[t] = qk[rbase * 128 + t];
    for (int t = tid; t < 27 * 32; t += 256) sender_s[t] = sender[rbase * 32 + t];
    for (int t = tid; t < 27 * 27 * 5; t += 256) rel_s[t] = rel[(size_t)b * (27 * 27 * 5) + t];
    for (int t = tid; t < 27 * 20; t += 256) qr_s[t] = qr[rbase * 20 + t];
    for (int t = tid; t < 27 * 4; t += 256) qb_s[t] = qb[rbase * 4 + t];
    if (tid < 64) nk_s[tid] = nullk[tid];
    if (tid >= 64 && tid < 96) nv_s[tid - 64] = nullv[tid - 64];
    __syncthreads();

    for (int t = tid; t < 27 * 112; t += 256) {
        int i = t / 112;
        int rem = t - i * 112;
        int j = rem >> 2, h = rem & 3;
        float s;
        if (j == 27) {
            float d = 0.f;
#pragma unroll
            for (int dd = 0; dd < 16; dd++) d += qk_s[i * 128 + h * 16 + dd] * nk_s[h * 16 + dd];
            s = 0.25f * d;
        } else if (j == i) {
            s = NEG;
        } else {
            float d = qb_s[i * 4 + h];
#pragma unroll
            for (int dd = 0; dd < 16; dd++)
                d += qk_s[i * 128 + h * 16 + dd] * qk_s[j * 128 + 64 + h * 16 + dd];
            const float* rr = &rel_s[(i * 27 + j) * 5];
#pragma unroll
            for (int r = 0; r < 5; r++) d += qr_s[i * 20 + h * 5 + r] * rr[r];
            s = 0.25f * d;
        }
        sc[t] = s;
    }
    __syncthreads();

    for (int t = tid; t < 108; t += 256) {
        int i = t >> 2, h = t & 3;
        float* scp = &sc[i * 112 + h];
        float t0 = -INFINITY, t1 = -INFINITY, t2 = -INFINITY, t3 = -INFINITY;
#pragma unroll
        for (int j = 0; j < 28; j++) {
            float v = scp[j * 4];
            if (v > t0)      { t3 = t2; t2 = t1; t1 = t0; t0 = v; }
            else if (v > t1) { t3 = t2; t2 = t1; t1 = v; }
            else if (v > t2) { t3 = t2; t2 = v; }
            else if (v > t3) { t3 = v; }
        }
        float thr = t3, mxv = t0, sum = 0.f;
        float e[28];
#pragma unroll
        for (int j = 0; j < 28; j++) {
            float v = scp[j * 4];
            float ev = (v >= thr) ? expf(v - mxv) : 0.f;
            e[j] = ev; sum += ev;
        }
        float inv = 1.f / sum;
#pragma unroll
        for (int j = 0; j < 28; j++) scp[j * 4] = e[j] * inv;
    }
    __syncthreads();

    int w = tid >> 5, l = tid & 31;
    int h = l >> 3;
    for (int i = w; i < 27; i += 8) {
        const float* scp = &sc[i * 112];
        float m = scp[108 + h] * nv_s[l];
#pragma unroll
        for (int j = 0; j < 27; j++) m += scp[j * 4 + h] * sender_s[j * 32 + l];
        float s = m, s2 = m * m;
#pragma unroll
        for (int o = 16; o > 0; o >>= 1) {
            s  += __shfl_xor_sync(0xffffffffu, s, o);
            s2 += __shfl_xor_sync(0xffffffffu, s2, o);
        }
        float mu = s * (1.f / 32.f);
        float var = s2 * (1.f / 32.f) - mu * mu;
        float nm = (m - mu) * rsqrtf(var + 1e-5f) * ln_g[l] + ln_b[l];
        size_t fidx = (rbase + i) * 288 + 256 + l;
        __half hb = __float2half(nm);
        fh[fidx] = hb;
        fl[fidx] = __float2half(nm - __half2float(hb));
    }
}

// ================= final =================
__global__ void __launch_bounds__(256)
final_kernel(const float* __restrict__ gd,
             const float* __restrict__ Wg2, const float* __restrict__ bg2,
             const float* __restrict__ Wd2, const float* __restrict__ bd2,
             const float* __restrict__ attack,
             float* __restrict__ out)
{
    __shared__ float Wd2s[256 * 28];
    __shared__ float wg2s[256];
    int tid = threadIdx.x;
    for (int t = tid; t < 27 * 256; t += 256) {
        int l = t >> 8, k = t & 255;
        Wd2s[k * 28 + l] = Wd2[t];
    }
    if (tid < 256) wg2s[tid] = Wg2[tid];
    __syncthreads();

    int w = tid >> 5, l = tid & 31;
    int row = blockIdx.x * 8 + w;
    const float* g1r = gd + (size_t)row * 512;
    const float* d1r = g1r + 256;
    float gs = 0.f;
#pragma unroll
    for (int i = 0; i < 8; i++) gs += g1r[l + i * 32] * wg2s[l + i * 32];
#pragma unroll
    for (int o = 16; o > 0; o >>= 1) gs += __shfl_xor_sync(0xffffffffu, gs, o);
    float gate = 1.f / (1.f + expf(-(gs + bg2[0])));
    if (l < 27) {
        float d = bd2[l];
#pragma unroll 8
        for (int k = 0; k < 256; k++) d += d1r[k] * Wd2s[k * 28 + l];
        out[(size_t)row * 33 + 6 + l] = attack[(size_t)row * 27 + l] + FUSE_SCALE * gate * d;
    }
}

// ================= host launcher =================
static float* sym(const void* symbol)
{
    void* p = nullptr;
    cudaGetSymbolAddress(&p, symbol);
    return (float*)p;
}
static __half* symh(const void* symbol)
{
    void* p = nullptr;
    cudaGetSymbolAddress(&p, symbol);
    return (__half*)p;
}

extern "C" void kernel_launch(void* const* d_in, const int* in_sizes, int n_in,
                              void* d_out, int out_size)
{
    const float* inputs = (const float*)d_in[0];
    const float* hidden = (const float*)d_in[1];
    const float* rel    = (const float*)d_in[2];
    const float* W1     = (const float*)d_in[3];
    const float* b1     = (const float*)d_in[4];
    const float* Wih    = (const float*)d_in[5];
    const float* bih    = (const float*)d_in[6];
    const float* Whh    = (const float*)d_in[7];
    const float* bhh    = (const float*)d_in[8];
    const float* Wp1    = (const float*)d_in[9];
    const float* bp1    = (const float*)d_in[10];
    const float* Wp2    = (const float*)d_in[11];
    const float* bp2    = (const float*)d_in[12];
    const float* Wq     = (const float*)d_in[13];
    const float* bq     = (const float*)d_in[14];
    const float* Wk     = (const float*)d_in[15];
    const float* bk     = (const float*)d_in[16];
    const float* Wv     = (const float*)d_in[17];
    const float* bv     = (const float*)d_in[18];
    const float* ln_g   = (const float*)d_in[19];
    const float* ln_b   = (const float*)d_in[20];
    const float* Wg1    = (const float*)d_in[21];
    const float* bg1    = (const float*)d_in[22];
    const float* Wg2    = (const float*)d_in[23];
    const float* bg2    = (const float*)d_in[24];
    const float* Wd1    = (const float*)d_in[25];
    const float* bd1    = (const float*)d_in[26];
    const float* Wd2    = (const float*)d_in[27];
    const float* bd2    = (const float*)d_in[28];
    const float* nullk  = (const float*)d_in[29];
    const float* nullv  = (const float*)d_in[30];

    const int rows = in_sizes[0] / INW;    // 27648
    const int bs = rows / Nn;
    float* out = (float*)d_out;

    float* prz     = sym(g_rz);
    float* pinn    = sym(g_inn);
    float* phn     = sym(g_hn);
    float* plgp    = sym(g_lgp);
    float* pattack = sym(g_attack);
    float* psender = sym(g_sender);
    float* pqk     = sym(g_qk);
    float* pqr     = sym(g_qr);
    float* pqb     = sym(g_qb);
    float* pgd     = sym(g_gd);
    float* pbpq    = sym(g_bpq);
    float* pbgd    = sym(g_bgd);
    float* pbrz    = sym(g_brz);
    float* pbp2p   = sym(g_bp2p);

    __half *pW1h = symh(g_W1h);
    __half *pBrzh = symh(g_Brzh);
    __half *pWnih = symh(g_Wnih);
    __half *pWnhh = symh(g_Wnhh);
    __half *pBpqh = symh(g_Bpqh);
    __half *pWp2h = symh(g_Wp2h);
    __half *pBgdh = symh(g_Bgdh);
    __half *pinh = symh(g_inh),   *pinl = symh(g_inl);
    __half *pcath = symh(g_cath), *pcatl = symh(g_catl);
    __half *phh = symh(g_hh),     *phl = symh(g_hl);
    __half *pph = symh(g_ph),     *ppl = symh(g_pl);
    __half *pfh = symh(g_fh),     *pfl = symh(g_fl);

    float* hout = (out_size >= rows * (NA + HID)) ? out + (size_t)rows * NA : sym(g_hfb);

    const int MB = rows / 128;   // 216

    cudaFuncSetAttribute((const void*)gemm_mma<EPI_BIAS>,        cudaFuncAttributeMaxDynamicSharedMemorySize, GSMEM);
    cudaFuncSetAttribute((const void*)gemm_mma<EPI_BIAS_RELU>,   cudaFuncAttributeMaxDynamicSharedMemorySize, GSMEM);
    cudaFuncSetAttribute((const void*)gemm_mma<EPI_PLANES_RELU>, cudaFuncAttributeMaxDynamicSharedMemorySize, GSMEM);
    cudaFuncSetAttribute((const void*)gemm_mma<EPI_MIX>,         cudaFuncAttributeMaxDynamicSharedMemorySize, GSMEM);

    // side stream + fork/join events
    static cudaStream_t s1 = nullptr;
    static cudaEvent_t e0 = nullptr, eH = nullptr, eN = nullptr, e2 = nullptr, eQ = nullptr;
    if (!s1) {
        cudaStreamCreateWithFlags(&s1, cudaStreamNonBlocking);
        cudaEventCreateWithFlags(&e0, cudaEventDisableTiming);
        cudaEventCreateWithFlags(&eH, cudaEventDisableTiming);
        cudaEventCreateWithFlags(&eN, cudaEventDisableTiming);
        cudaEventCreateWithFlags(&e2, cudaEventDisableTiming);
        cudaEventCreateWithFlags(&eQ, cudaEventDisableTiming);
    }

    // --- prep (stream 0) ---
    prep_all<<<(TTOT + 255) / 256, 256>>>(W1, Wih, Whh, Wp1, Wp2, Wq, Wk, Wg1, Wd1,
                                          bp1, bq, bg1, bd1, bih, bhh, bp2,
                                          pW1h, pBrzh, pWnih, pWnhh, pBpqh, pWp2h, pBgdh,
                                          pbpq, pbgd, pbrz, pbp2p);
    conv_split<<<(rows * 352 + 255) / 256, 256>>>(inputs, pinh, pinl, rows, 322, 352, 352, 0);

    // fork: s1 does conv_split(hidden) -> hn GEMM
    cudaEventRecord(e0, 0);
    cudaStreamWaitEvent(s1, e0, 0);
    conv_split<<<(rows * 256 + 255) / 256, 256, 0, s1>>>(hidden, pcath, pcatl, rows, 256, 256, 512, 256);
    cudaEventRecord(eH, s1);
    gemm_mma<EPI_BIAS><<<dim3(2, MB), 256, GSMEM, s1>>>(pcath + 256, pcatl + 256, 512, pWnhh, 256,
                                                        bhh + 512, phn, nullptr, nullptr, 256, 8, 0);
    cudaEventRecord(eN, s1);

    // main chain (stream 0)
    gemm_mma<EPI_PLANES_RELU><<<dim3(2, MB), 256, GSMEM>>>(pinh, pinl, 352, pW1h, 352, b1,
                                                           nullptr, pcath, pcatl, 512, 11, 0);
    cudaStreamWaitEvent(0, eH, 0);
    gemm_mma<EPI_BIAS><<<dim3(4, MB), 256, GSMEM>>>(pcath, pcatl, 512, pBrzh, 512, pbrz,
                                                    prz, nullptr, nullptr, 512, 16, 0);
    gemm_mma<EPI_BIAS><<<dim3(2, MB), 256, GSMEM>>>(pcath, pcatl, 512, pWnih, 256, bih + 512,
                                                    pinn, nullptr, nullptr, 256, 8, 0);
    cudaStreamWaitEvent(0, eN, 0);
    gru_kernel<<<(rows * 256 + 255) / 256, 256>>>(prz, pinn, phn, hidden, hout, phh, phl, pfh, pfl, rows * 256);
    // merged [p-planes | qk]
    gemm_mma<EPI_MIX><<<dim3(3, MB), 256, GSMEM>>>(phh, phl, 256, pBpqh, 256, pbpq,
                                                   pqk, pph, ppl, 256, 8, 128);
    cudaEventRecord(e2, 0);
    cudaStreamWaitEvent(s1, e2, 0);
    qr_kernel<<<(rows * 4 + 127) / 128, 128, 0, s1>>>(pqk, Wk, bk, pqr, pqb, rows);
    cudaEventRecord(eQ, s1);
    gemm_mma<EPI_BIAS><<<dim3(1, MB), 256, GSMEM>>>(pph, ppl, 256, pWp2h, 256, pbp2p,
                                                    plgp, nullptr, nullptr, 128, 8, 0);
    logits_post<<<rows / 8, 256>>>(plgp, Wv, bv, out, pattack, psender);
    cudaStreamWaitEvent(0, eQ, 0);
    attn_batch<<<bs, 256>>>(pqk, pqr, pqb, rel, psender, nullk, nullv, ln_g, ln_b, pfh, pfl);
    gemm_mma<EPI_BIAS_RELU><<<dim3(4, MB), 256, GSMEM>>>(pfh, pfl, 288, pBgdh, 288, pbgd,
                                                         pgd, nullptr, nullptr, 512, 9, 0);
    final_kernel<<<rows / 8, 256>>>(pgd, Wg2, bg2, Wd2, bd2, pattack, out);
}

// round 12
// speedup vs baseline: 3.8025x; 1.0248x over previous
#include <cuda_runtime.h>
#include <cuda_fp16.h>
#include <math.h>
#include <stdint.h>

// ---------------- problem constants ----------------
#define Nn   27
#define NA   33
#define HID  256
#define REL  5
#define INW  322
#define FUSE_SCALE 0.1f
#define NEG  (-10000000000.0f)
#define MAXROWS 27648

// ---------------- scratch (device globals) -------------
__device__ float g_rz    [MAXROWS * 512];
__device__ float g_inn   [MAXROWS * 256];
__device__ float g_hn    [MAXROWS * 256];
__device__ float g_lgp   [MAXROWS * 128];
__device__ float g_attack[MAXROWS * 27];
__device__ float g_sender[MAXROWS * 32];
__device__ float g_qk    [MAXROWS * 128];
__device__ float g_qr    [MAXROWS * 20];
__device__ float g_qb    [MAXROWS * 4];
__device__ float g_gd    [MAXROWS * 512];
__device__ float g_hfb   [MAXROWS * 256];
__device__ float g_bpq   [384];
__device__ float g_bgd   [512];
__device__ float g_brz   [512];
__device__ float g_bp2p  [128];
// fp16 weight planes (single plane; K padded to 32-multiples)
__device__ __half g_W1h [256 * 352];
__device__ __half g_Brzh[512 * 512];
__device__ __half g_Wnih[256 * 256];
__device__ __half g_Wnhh[256 * 256];
__device__ __half g_Bpqh[384 * 256];
__device__ __half g_Wp2h[128 * 256];
__device__ __half g_Bgdh[512 * 288];
// fp16 hi/lo activation planes
__device__ __half g_inh [MAXROWS * 352], g_inl [MAXROWS * 352];
__device__ __half g_cath[MAXROWS * 512], g_catl[MAXROWS * 512];
__device__ __half g_hh  [MAXROWS * 256], g_hl  [MAXROWS * 256];
__device__ __half g_ph  [MAXROWS * 256], g_pl  [MAXROWS * 256];
__device__ __half g_fh  [MAXROWS * 288], g_fl  [MAXROWS * 288];

#define EPI_BIAS 1
#define EPI_BIAS_RELU 2
#define EPI_PLANES_RELU 3
#define EPI_MIX 4

// =================== helpers ===============
__device__ __forceinline__ uint32_t smem_u32(const void* p) {
    uint32_t a;
    asm("{ .reg .u64 t; cvta.to.shared.u64 t, %1; cvt.u32.u64 %0, t; }" : "=r"(a) : "l"(p));
    return a;
}
#define CP_ASYNC16(dst, src) \
    asm volatile("cp.async.cg.shared.global [%0], [%1], 16;" :: "r"(dst), "l"(src) : "memory")
#define CP_COMMIT() asm volatile("cp.async.commit_group;" ::: "memory")
#define CP_WAIT0()  asm volatile("cp.async.wait_group 0;" ::: "memory")
#define CP_WAIT1()  asm volatile("cp.async.wait_group 1;" ::: "memory")

__device__ __forceinline__ void ldsm4(uint32_t* d, uint32_t addr) {
    asm volatile("ldmatrix.sync.aligned.m8n8.x4.shared.b16 {%0,%1,%2,%3}, [%4];"
                 : "=r"(d[0]), "=r"(d[1]), "=r"(d[2]), "=r"(d[3]) : "r"(addr));
}
__device__ __forceinline__ void mma16816(float* c, const uint32_t* a, const uint32_t* b) {
    asm volatile("mma.sync.aligned.m16n8k16.row.col.f32.f16.f16.f32 "
                 "{%0,%1,%2,%3}, {%4,%5,%6,%7}, {%8,%9}, {%0,%1,%2,%3};"
                 : "+f"(c[0]), "+f"(c[1]), "+f"(c[2]), "+f"(c[3])
                 : "r"(a[0]), "r"(a[1]), "r"(a[2]), "r"(a[3]), "r"(b[0]), "r"(b[1]));
}

// =================== 3-stage pipelined mma.sync fp16 GEMM ===================
// C[M,N] = (Ahi[+Alo])[M,Kpad] @ Bh[N,Kpad]^T (+bias)(relu)
// Block tile 128x128, 8 warps (2m x 4n), warp tile 64x32, BK=32.
// 3-stage cp.async double-ahead pipeline. Planes/stage: Ahi, Alo, Bh.
#define PLNB   10240
#define STAGEB (3 * PLNB)
#define GSMEM  (3 * STAGEB)        // 92160 B per CTA, 2 CTAs/SM = 180 KB

template<int EPI, int PASSES>
__global__ void __launch_bounds__(256, 2)
gemm_mma(const __half* __restrict__ Ahi, const __half* __restrict__ Alo, int lda,
         const __half* __restrict__ Bh, int ldb,
         const float* __restrict__ bias,
         float* __restrict__ C, __half* __restrict__ Ch, __half* __restrict__ Cl,
         int ldc, int nChunks, int ldc2)
{
    extern __shared__ __align__(16) char smx[];

    const int tid = threadIdx.x;
    const int wid = tid >> 5, lane = tid & 31;
    const int m0 = blockIdx.y * 128, n0 = blockIdx.x * 128;
    const int r = tid >> 1, hf = tid & 1;

    const uint32_t sbase = smem_u32(smx);
    const uint32_t stO = (uint32_t)r * 80 + hf * 32;

    const int warp_m = (wid & 1) * 64, warp_n = (wid >> 1) * 32;
    const uint32_t aOff = (uint32_t)(warp_m + (lane & 15)) * 80 + (lane >> 4) * 16;
    const uint32_t bRow = (uint32_t)(warp_n + (lane & 7) + ((lane >> 4) << 3));
    const uint32_t bOff = bRow * 80 + ((lane >> 3) & 1) * 16;

    float c[4][4][4];
#pragma unroll
    for (int mt = 0; mt < 4; mt++)
#pragma unroll
        for (int nt = 0; nt < 4; nt++)
#pragma unroll
            for (int q = 0; q < 4; q++) c[mt][nt][q] = 0.f;

    const __half* ArH = Ahi + (size_t)(m0 + r) * lda + hf * 16;
    const __half* ArL = (PASSES == 2) ? (Alo + (size_t)(m0 + r) * lda + hf * 16) : nullptr;
    const __half* BrH = Bh + (size_t)(n0 + r) * ldb + hf * 16;

    auto issue = [&](int ch, int st) {
        const int kc = ch * 32;
        const uint32_t base = sbase + st * STAGEB;
        CP_ASYNC16(base + stO,                 ArH + kc);
        CP_ASYNC16(base + stO + 16,            ArH + kc + 8);
        if (PASSES == 2) {
            CP_ASYNC16(base + PLNB + stO,      ArL + kc);
            CP_ASYNC16(base + PLNB + stO + 16, ArL + kc + 8);
        }
        CP_ASYNC16(base + 2 * PLNB + stO,      BrH + kc);
        CP_ASYNC16(base + 2 * PLNB + stO + 16, BrH + kc + 8);
        CP_COMMIT();
    };

    issue(0, 0);
    if (nChunks > 1) issue(1, 1);

    for (int ch = 0; ch < nChunks; ch++) {
        if (ch + 1 < nChunks) { CP_WAIT1(); } else { CP_WAIT0(); }
        __syncthreads();
        if (ch + 2 < nChunks) {
            int st = ch + 2;
            st = (st >= 3) ? ((st >= 6) ? ((st >= 9) ? ((st >= 12) ? ((st >= 15) ? st - 15 : st - 12) : st - 9) : st - 6) : st - 3) : st;
            issue(ch + 2, st);
        }

        int cs = ch;
        cs = (cs >= 3) ? ((cs >= 6) ? ((cs >= 9) ? ((cs >= 12) ? ((cs >= 15) ? cs - 15 : cs - 12) : cs - 9) : cs - 6) : cs - 3) : cs;
        const uint32_t base = sbase + cs * STAGEB;
        const uint32_t sAhi = base, sAlo = base + PLNB;
        const uint32_t sBh = base + 2 * PLNB;
#pragma unroll
        for (int ks = 0; ks < 2; ks++) {
            const uint32_t ko = ks * 32;
            uint32_t aF[4][4], bF[4][2];
#pragma unroll
            for (int p = 0; p < 2; p++) {
                uint32_t t[4];
                ldsm4(t, sBh + bOff + ko + p * (16 * 80));
                bF[2 * p][0] = t[0]; bF[2 * p][1] = t[1];
                bF[2 * p + 1][0] = t[2]; bF[2 * p + 1][1] = t[3];
            }
#pragma unroll
            for (int mt = 0; mt < 4; mt++) ldsm4(aF[mt], sAhi + aOff + ko + mt * (16 * 80));
#pragma unroll
            for (int mt = 0; mt < 4; mt++)
#pragma unroll
                for (int nt = 0; nt < 4; nt++) mma16816(c[mt][nt], aF[mt], bF[nt]);
            if (PASSES == 2) {
#pragma unroll
                for (int mt = 0; mt < 4; mt++) ldsm4(aF[mt], sAlo + aOff + ko + mt * (16 * 80));
#pragma unroll
                for (int mt = 0; mt < 4; mt++)
#pragma unroll
                    for (int nt = 0; nt < 4; nt++) mma16816(c[mt][nt], aF[mt], bF[nt]);
            }
        }
        __syncthreads();
    }

    // ---- epilogue ----
    const bool mix_planes = (EPI != EPI_MIX) || (n0 < 256);
#pragma unroll
    for (int mt = 0; mt < 4; mt++) {
        const int row = m0 + warp_m + mt * 16 + (lane >> 2);
#pragma unroll
        for (int nt = 0; nt < 4; nt++) {
            const int col = n0 + warp_n + nt * 8 + (lane & 3) * 2;
            const float b0 = bias[col], b1 = bias[col + 1];
            float v0 = c[mt][nt][0] + b0, v1 = c[mt][nt][1] + b1;
            float v2 = c[mt][nt][2] + b0, v3 = c[mt][nt][3] + b1;
            const bool relu = (EPI == EPI_BIAS_RELU) || (EPI == EPI_PLANES_RELU) ||
                              (EPI == EPI_MIX && mix_planes);
            if (relu) {
                v0 = fmaxf(v0, 0.f); v1 = fmaxf(v1, 0.f);
                v2 = fmaxf(v2, 0.f); v3 = fmaxf(v3, 0.f);
            }
            if (EPI == EPI_PLANES_RELU || (EPI == EPI_MIX && mix_planes)) {
                __half h0 = __float2half(v0), h1 = __float2half(v1);
                __half h2 = __float2half(v2), h3 = __float2half(v3);
                *(__half2*)(Ch + (size_t)row * ldc + col) = __halves2half2(h0, h1);
                *(__half2*)(Ch + (size_t)(row + 8) * ldc + col) = __halves2half2(h2, h3);
                *(__half2*)(Cl + (size_t)row * ldc + col) =
                    __halves2half2(__float2half(v0 - __half2float(h0)),
                                   __float2half(v1 - __half2float(h1)));
                *(__half2*)(Cl + (size_t)(row + 8) * ldc + col) =
                    __halves2half2(__float2half(v2 - __half2float(h2)),
                                   __float2half(v3 - __half2float(h3)));
            } else if (EPI == EPI_MIX) {
                const int c2 = col - 256;
                *(float2*)(C + (size_t)row * ldc2 + c2) = make_float2(v0, v1);
                *(float2*)(C + (size_t)(row + 8) * ldc2 + c2) = make_float2(v2, v3);
            } else {
                *(float2*)(C + (size_t)row * ldc + col) = make_float2(v0, v1);
                *(float2*)(C + (size_t)(row + 8) * ldc + col) = make_float2(v2, v3);
            }
        }
    }
}

// ================= activation split: fp32 -> fp16 hi/lo =================
__global__ void conv_split(const float* __restrict__ src, __half* __restrict__ hi,
                           __half* __restrict__ lo, int Mrows, int K, int Kpad,
                           int ldo, int off)
{
    int idx = blockIdx.x * blockDim.x + threadIdx.x;
    if (idx >= Mrows * Kpad) return;
    int m = idx / Kpad, k = idx - m * Kpad;
    float v = (k < K) ? src[(size_t)m * K + k] : 0.f;
    __half h = __float2half(v);
    size_t o = (size_t)m * ldo + off + k;
    hi[o] = h;
    lo[o] = __float2half(v - __half2float(h));
}

// ================= one-shot weight prep =================
#define T0 (256*352)
#define T1 (512*512)
#define T2 (256*256)
#define T3 (256*256)
#define T4 (384*256)
#define T5 (128*256)
#define T6 (512*288)
#define T7 (384+512+512+128)
#define TTOT (T0+T1+T2+T3+T4+T5+T6+T7)

__global__ void prep_all(const float* __restrict__ W1,  const float* __restrict__ Wih,
                         const float* __restrict__ Whh, const float* __restrict__ Wp1,
                         const float* __restrict__ Wp2, const float* __restrict__ Wq,
                         const float* __restrict__ Wk,  const float* __restrict__ Wg1,
                         const float* __restrict__ Wd1,
                         const float* __restrict__ bp1, const float* __restrict__ bq,
                         const float* __restrict__ bg1, const float* __restrict__ bd1,
                         const float* __restrict__ bih, const float* __restrict__ bhh,
                         const float* __restrict__ bp2,
                         __half* __restrict__ W1h,  __half* __restrict__ Brzh,
                         __half* __restrict__ Wnih, __half* __restrict__ Wnhh,
                         __half* __restrict__ Bpqh, __half* __restrict__ Wp2h,
                         __half* __restrict__ Bgdh,
                         float* __restrict__ pbpq, float* __restrict__ pbgd,
                         float* __restrict__ pbrz, float* __restrict__ pbp2p)
{
    int idx = blockIdx.x * blockDim.x + threadIdx.x;
    if (idx >= TTOT) return;
    float src;
    __half* dst;
    int off;
    if (idx < T0) {
        off = idx;
        int k = off % 352;
        src = (k < 322) ? W1[(off / 352) * 322 + k] : 0.f;
        dst = W1h;
    } else if (idx < T0 + T1) {
        off = idx - T0;
        int n = off >> 9, k = off & 511;
        src = (k < 256) ? Wih[n * 256 + k] : Whh[n * 256 + (k - 256)];
        dst = Brzh;
    } else if (idx < T0 + T1 + T2) {
        off = idx - T0 - T1;
        src = Wih[512 * 256 + off];
        dst = Wnih;
    } else if (idx < T0 + T1 + T2 + T3) {
        off = idx - T0 - T1 - T2;
        src = Whh[512 * 256 + off];
        dst = Wnhh;
    } else if (idx < T0 + T1 + T2 + T3 + T4) {
        off = idx - T0 - T1 - T2 - T3;
        int rr = off >> 8, cc = off & 255;
        if (rr < 256) src = Wp1[rr * 256 + cc];
        else if (rr < 320) src = Wq[(rr - 256) * 256 + cc];
        else src = Wk[(size_t)(rr - 320) * (HID + REL) + cc];
        dst = Bpqh;
    } else if (idx < T0 + T1 + T2 + T3 + T4 + T5) {
        off = idx - T0 - T1 - T2 - T3 - T4;
        int n = off >> 8;
        src = (n < NA) ? Wp2[n * 256 + (off & 255)] : 0.f;
        dst = Wp2h;
    } else if (idx < T0 + T1 + T2 + T3 + T4 + T5 + T6) {
        off = idx - T0 - T1 - T2 - T3 - T4 - T5;
        int rr = off / 288, cc = off % 288;
        src = (rr < 256) ? Wg1[rr * 288 + cc] : Wd1[(rr - 256) * 288 + cc];
        dst = Bgdh;
    } else {
        off = idx - (T0 + T1 + T2 + T3 + T4 + T5 + T6);
        if (off < 384) {
            pbpq[off] = (off < 256) ? bp1[off] : ((off < 320) ? bq[off - 256] : 0.f);
        } else if (off < 896) {
            int o = off - 384; pbgd[o] = (o < 256) ? bg1[o] : bd1[o - 256];
        } else if (off < 1408) {
            int o = off - 896; pbrz[o] = bih[o] + bhh[o];
        } else {
            int o = off - 1408; pbp2p[o] = (o < NA) ? bp2[o] : 0.f;
        }
        return;
    }
    dst[off] = __float2half(src);
}

// ================= GRU =================
__global__ void gru_kernel(const float* __restrict__ rz, const float* __restrict__ inn,
                           const float* __restrict__ hn, const float* __restrict__ hin,
                           float* __restrict__ hout,
                           __half* __restrict__ hh, __half* __restrict__ hl,
                           __half* __restrict__ fh, __half* __restrict__ fl,
                           int total)
{
    int idx = blockIdx.x * blockDim.x + threadIdx.x;
    if (idx >= total) return;
    int r = idx >> 8, c = idx & 255;
    size_t rb = (size_t)r * 512;
    float rg = 1.f / (1.f + expf(-rz[rb + c]));
    float zg = 1.f / (1.f + expf(-rz[rb + 256 + c]));
    float ng = tanhf(inn[idx] + rg * hn[idx]);
    float v = (1.f - zg) * ng + zg * hin[idx];
    hout[idx] = v;
    __half h = __float2half(v);
    __half l = __float2half(v - __half2float(h));
    hh[idx] = h; hl[idx] = l;
    size_t fidx = (size_t)r * 288 + c;
    fh[fidx] = h; fl[fidx] = l;
}

// ================= logits post (padded logits, ld=128) =================
__global__ void __launch_bounds__(256)
logits_post(const float* __restrict__ logits, const float* __restrict__ Wv,
            const float* __restrict__ bv,
            float* __restrict__ out, float* __restrict__ attack,
            float* __restrict__ sender)
{
    __shared__ float Wvs[32 * 29];
    __shared__ float bvs[32];
    __shared__ float vs[8][29];
    int tid = threadIdx.x;
    for (int t = tid; t < 32 * 29; t += 256) Wvs[t] = Wv[t];
    if (tid < 32) bvs[tid] = bv[tid];
    int w = tid >> 5, l = tid & 31;
    int row = blockIdx.x * 8 + w;
    const float* lrow = logits + (size_t)row * 128;
    float al = (l < 27) ? lrow[6 + l] : -INFINITY;
    float mx = al;
#pragma unroll
    for (int o = 16; o > 0; o >>= 1) mx = fmaxf(mx, __shfl_xor_sync(0xffffffffu, mx, o));
    float e = (l < 27) ? expf(al - mx) : 0.f;
    float sum = e;
#pragma unroll
    for (int o = 16; o > 0; o >>= 1) sum += __shfl_xor_sync(0xffffffffu, sum, o);
    float inv = 1.f / sum;
    if (l < 27) vs[w][l] = e * inv;
    if (l == 27) vs[w][27] = 1.0f;
    if (l == 28) vs[w][28] = inv;
    if (l < 27) attack[(size_t)row * 27 + l] = al;
    if (l < 6)  out[(size_t)row * 33 + l] = lrow[l];
    __syncthreads();
    float s = bvs[l];
#pragma unroll
    for (int r = 0; r < 29; r++) s += vs[w][r] * Wvs[l * 29 + r];
    sender[(size_t)row * 32 + l] = s;
}

// ================= qr / qb precompute =================
__global__ void qr_kernel(const float* __restrict__ qk, const float* __restrict__ Wk,
                          const float* __restrict__ bk,
                          float* __restrict__ qr, float* __restrict__ qb, int rows)
{
    int idx = blockIdx.x * blockDim.x + threadIdx.x;
    if (idx >= rows * 4) return;
    int row = idx >> 2, h = idx & 3;
    const float* qp = qk + (size_t)row * 128 + h * 16;
    float acc[5] = {0.f, 0.f, 0.f, 0.f, 0.f};
    float accb = 0.f;
#pragma unroll
    for (int d = 0; d < 16; d++) {
        float qd = qp[d];
        const float* wrow = Wk + (size_t)(h * 16 + d) * (HID + REL) + HID;
#pragma unroll
        for (int r = 0; r < 5; r++) acc[r] += qd * wrow[r];
        accb += qd * bk[h * 16 + d];
    }
#pragma unroll
    for (int r = 0; r < 5; r++) qr[(size_t)row * 20 + h * 5 + r] = acc[r];
    qb[(size_t)row * 4 + h] = accb;
}

// ================= batched attention =================
__global__ void __launch_bounds__(256)
attn_batch(const float* __restrict__ qk, const float* __restrict__ qr,
           const float* __restrict__ qb, const float* __restrict__ rel,
           const float* __restrict__ sender,
           const float* __restrict__ nullk, const float* __restrict__ nullv,
           const float* __restrict__ ln_g, const float* __restrict__ ln_b,
           __half* __restrict__ fh, __half* __restrict__ fl)
{
    __shared__ float qk_s[27 * 128];
    __shared__ float sender_s[27 * 32];
    __shared__ float rel_s[27 * 27 * 5];
    __shared__ float qr_s[27 * 20];
    __shared__ float qb_s[27 * 4];
    __shared__ float nk_s[64];
    __shared__ float nv_s[32];
    __shared__ float sc[27 * 112];

    const int b = blockIdx.x;
    const int tid = threadIdx.x;
    const size_t rbase = (size_t)b * 27;

    for (int t = tid; t < 27 * 128; t += 256) qk_s[t] = qk[rbase * 128 + t];
    for (int t = tid; t < 27 * 32; t += 256) sender_s[t] = sender[rbase * 32 + t];
    for (int t = tid; t < 27 * 27 * 5; t += 256) rel_s[t] = rel[(size_t)b * (27 * 27 * 5) + t];
    for (int t = tid; t < 27 * 20; t += 256) qr_s[t] = qr[rbase * 20 + t];
    for (int t = tid; t < 27 * 4; t += 256) qb_s[t] = qb[rbase * 4 + t];
    if (tid < 64) nk_s[tid] = nullk[tid];
    if (tid >= 64 && tid < 96) nv_s[tid - 64] = nullv[tid - 64];
    __syncthreads();

    for (int t = tid; t < 27 * 112; t += 256) {
        int i = t / 112;
        int rem = t - i * 112;
        int j = rem >> 2, h = rem & 3;
        float s;
        if (j == 27) {
            float d = 0.f;
#pragma unroll
            for (int dd = 0; dd < 16; dd++) d += qk_s[i * 128 + h * 16 + dd] * nk_s[h * 16 + dd];
            s = 0.25f * d;
        } else if (j == i) {
            s = NEG;
        } else {
            float d = qb_s[i * 4 + h];
#pragma unroll
            for (int dd = 0; dd < 16; dd++)
                d += qk_s[i * 128 + h * 16 + dd] * qk_s[j * 128 + 64 + h * 16 + dd];
            const float* rr = &rel_s[(i * 27 + j) * 5];
#pragma unroll
            for (int r = 0; r < 5; r++) d += qr_s[i * 20 + h * 5 + r] * rr[r];
            s = 0.25f * d;
        }
        sc[t] = s;
    }
    __syncthreads();

    for (int t = tid; t < 108; t += 256) {
        int i = t >> 2, h = t & 3;
        float* scp = &sc[i * 112 + h];
        float t0 = -INFINITY, t1 = -INFINITY, t2 = -INFINITY, t3 = -INFINITY;
#pragma unroll
        for (int j = 0; j < 28; j++) {
            float v = scp[j * 4];
            if (v > t0)      { t3 = t2; t2 = t1; t1 = t0; t0 = v; }
            else if (v > t1) { t3 = t2; t2 = t1; t1 = v; }
            else if (v > t2) { t3 = t2; t2 = v; }
            else if (v > t3) { t3 = v; }
        }
        float thr = t3, mxv = t0, sum = 0.f;
        float e[28];
#pragma unroll
        for (int j = 0; j < 28; j++) {
            float v = scp[j * 4];
            float ev = (v >= thr) ? expf(v - mxv) : 0.f;
            e[j] = ev; sum += ev;
        }
        float inv = 1.f / sum;
#pragma unroll
        for (int j = 0; j < 28; j++) scp[j * 4] = e[j] * inv;
    }
    __syncthreads();

    int w = tid >> 5, l = tid & 31;
    int h = l >> 3;
    for (int i = w; i < 27; i += 8) {
        const float* scp = &sc[i * 112];
        float m = scp[108 + h] * nv_s[l];
#pragma unroll
        for (int j = 0; j < 27; j++) m += scp[j * 4 + h] * sender_s[j * 32 + l];
        float s = m, s2 = m * m;
#pragma unroll
        for (int o = 16; o > 0; o >>= 1) {
            s  += __shfl_xor_sync(0xffffffffu, s, o);
            s2 += __shfl_xor_sync(0xffffffffu, s2, o);
        }
        float mu = s * (1.f / 32.f);
        float var = s2 * (1.f / 32.f) - mu * mu;
        float nm = (m - mu) * rsqrtf(var + 1e-5f) * ln_g[l] + ln_b[l];
        size_t fidx = (rbase + i) * 288 + 256 + l;
        __half hb = __float2half(nm);
        fh[fidx] = hb;
        fl[fidx] = __float2half(nm - __half2float(hb));
    }
}

// ================= final =================
__global__ void __launch_bounds__(256)
final_kernel(const float* __restrict__ gd,
             const float* __restrict__ Wg2, const float* __restrict__ bg2,
             const float* __restrict__ Wd2, const float* __restrict__ bd2,
             const float* __restrict__ attack,
             float* __restrict__ out)
{
    __shared__ float Wd2s[256 * 28];
    __shared__ float wg2s[256];
    int tid = threadIdx.x;
    for (int t = tid; t < 27 * 256; t += 256) {
        int l = t >> 8, k = t & 255;
        Wd2s[k * 28 + l] = Wd2[t];
    }
    if (tid < 256) wg2s[tid] = Wg2[tid];
    __syncthreads();

    int w = tid >> 5, l = tid & 31;
    int row = blockIdx.x * 8 + w;
    const float* g1r = gd + (size_t)row * 512;
    const float* d1r = g1r + 256;
    float gs = 0.f;
#pragma unroll
    for (int i = 0; i < 8; i++) gs += g1r[l + i * 32] * wg2s[l + i * 32];
#pragma unroll
    for (int o = 16; o > 0; o >>= 1) gs += __shfl_xor_sync(0xffffffffu, gs, o);
    float gate = 1.f / (1.f + expf(-(gs + bg2[0])));
    if (l < 27) {
        float d = bd2[l];
#pragma unroll 8
        for (int k = 0; k < 256; k++) d += d1r[k] * Wd2s[k * 28 + l];
        out[(size_t)row * 33 + 6 + l] = attack[(size_t)row * 27 + l] + FUSE_SCALE * gate * d;
    }
}

// ================= host launcher =================
static float* sym(const void* symbol)
{
    void* p = nullptr;
    cudaGetSymbolAddress(&p, symbol);
    return (float*)p;
}
static __half* symh(const void* symbol)
{
    void* p = nullptr;
    cudaGetSymbolAddress(&p, symbol);
    return (__half*)p;
}

extern "C" void kernel_launch(void* const* d_in, const int* in_sizes, int n_in,
                              void* d_out, int out_size)
{
    const float* inputs = (const float*)d_in[0];
    const float* hidden = (const float*)d_in[1];
    const float* rel    = (const float*)d_in[2];
    const float* W1     = (const float*)d_in[3];
    const float* b1     = (const float*)d_in[4];
    const float* Wih    = (const float*)d_in[5];
    const float* bih    = (const float*)d_in[6];
    const float* Whh    = (const float*)d_in[7];
    const float* bhh    = (const float*)d_in[8];
    const float* Wp1    = (const float*)d_in[9];
    const float* bp1    = (const float*)d_in[10];
    const float* Wp2    = (const float*)d_in[11];
    const float* bp2    = (const float*)d_in[12];
    const float* Wq     = (const float*)d_in[13];
    const float* bq     = (const float*)d_in[14];
    const float* Wk     = (const float*)d_in[15];
    const float* bk     = (const float*)d_in[16];
    const float* Wv     = (const float*)d_in[17];
    const float* bv     = (const float*)d_in[18];
    const float* ln_g   = (const float*)d_in[19];
    const float* ln_b   = (const float*)d_in[20];
    const float* Wg1    = (const float*)d_in[21];
    const float* bg1    = (const float*)d_in[22];
    const float* Wg2    = (const float*)d_in[23];
    const float* bg2    = (const float*)d_in[24];
    const float* Wd1    = (const float*)d_in[25];
    const float* bd1    = (const float*)d_in[26];
    const float* Wd2    = (const float*)d_in[27];
    const float* bd2    = (const float*)d_in[28];
    const float* nullk  = (const float*)d_in[29];
    const float* nullv  = (const float*)d_in[30];

    const int rows = in_sizes[0] / INW;    // 27648
    const int bs = rows / Nn;
    float* out = (float*)d_out;

    float* prz     = sym(g_rz);
    float* pinn    = sym(g_inn);
    float* phn     = sym(g_hn);
    float* plgp    = sym(g_lgp);
    float* pattack = sym(g_attack);
    float* psender = sym(g_sender);
    float* pqk     = sym(g_qk);
    float* pqr     = sym(g_qr);
    float* pqb     = sym(g_qb);
    float* pgd     = sym(g_gd);
    float* pbpq    = sym(g_bpq);
    float* pbgd    = sym(g_bgd);
    float* pbrz    = sym(g_brz);
    float* pbp2p   = sym(g_bp2p);

    __half *pW1h = symh(g_W1h);
    __half *pBrzh = symh(g_Brzh);
    __half *pWnih = symh(g_Wnih);
    __half *pWnhh = symh(g_Wnhh);
    __half *pBpqh = symh(g_Bpqh);
    __half *pWp2h = symh(g_Wp2h);
    __half *pBgdh = symh(g_Bgdh);
    __half *pinh = symh(g_inh),   *pinl = symh(g_inl);
    __half *pcath = symh(g_cath), *pcatl = symh(g_catl);
    __half *phh = symh(g_hh),     *phl = symh(g_hl);
    __half *pph = symh(g_ph),     *ppl = symh(g_pl);
    __half *pfh = symh(g_fh),     *pfl = symh(g_fl);

    float* hout = (out_size >= rows * (NA + HID)) ? out + (size_t)rows * NA : sym(g_hfb);

    const int MB = rows / 128;   // 216

    cudaFuncSetAttribute((const void*)gemm_mma<EPI_BIAS, 2>,        cudaFuncAttributeMaxDynamicSharedMemorySize, GSMEM);
    cudaFuncSetAttribute((const void*)gemm_mma<EPI_PLANES_RELU, 2>, cudaFuncAttributeMaxDynamicSharedMemorySize, GSMEM);
    cudaFuncSetAttribute((const void*)gemm_mma<EPI_MIX, 2>,         cudaFuncAttributeMaxDynamicSharedMemorySize, GSMEM);
    cudaFuncSetAttribute((const void*)gemm_mma<EPI_BIAS_RELU, 1>,   cudaFuncAttributeMaxDynamicSharedMemorySize, GSMEM);

    // side stream + fork/join events
    static cudaStream_t s1 = nullptr;
    static cudaEvent_t e0 = nullptr, eH = nullptr, eN = nullptr, e2 = nullptr, eQ = nullptr;
    if (!s1) {
        cudaStreamCreateWithFlags(&s1, cudaStreamNonBlocking);
        cudaEventCreateWithFlags(&e0, cudaEventDisableTiming);
        cudaEventCreateWithFlags(&eH, cudaEventDisableTiming);
        cudaEventCreateWithFlags(&eN, cudaEventDisableTiming);
        cudaEventCreateWithFlags(&e2, cudaEventDisableTiming);
        cudaEventCreateWithFlags(&eQ, cudaEventDisableTiming);
    }

    // --- prep (stream 0) ---
    prep_all<<<(TTOT + 255) / 256, 256>>>(W1, Wih, Whh, Wp1, Wp2, Wq, Wk, Wg1, Wd1,
                                          bp1, bq, bg1, bd1, bih, bhh, bp2,
                                          pW1h, pBrzh, pWnih, pWnhh, pBpqh, pWp2h, pBgdh,
                                          pbpq, pbgd, pbrz, pbp2p);
    conv_split<<<(rows * 352 + 255) / 256, 256>>>(inputs, pinh, pinl, rows, 322, 352, 352, 0);

    // fork: s1 does conv_split(hidden) -> hn GEMM
    cudaEventRecord(e0, 0);
    cudaStreamWaitEvent(s1, e0, 0);
    conv_split<<<(rows * 256 + 255) / 256, 256, 0, s1>>>(hidden, pcath, pcatl, rows, 256, 256, 512, 256);
    cudaEventRecord(eH, s1);
    gemm_mma<EPI_BIAS, 2><<<dim3(2, MB), 256, GSMEM, s1>>>(pcath + 256, pcatl + 256, 512, pWnhh, 256,
                                                           bhh + 512, phn, nullptr, nullptr, 256, 8, 0);
    cudaEventRecord(eN, s1);

    // main chain (stream 0)
    gemm_mma<EPI_PLANES_RELU, 2><<<dim3(2, MB), 256, GSMEM>>>(pinh, pinl, 352, pW1h, 352, b1,
                                                              nullptr, pcath, pcatl, 512, 11, 0);
    cudaStreamWaitEvent(0, eH, 0);
    gemm_mma<EPI_BIAS, 2><<<dim3(4, MB), 256, GSMEM>>>(pcath, pcatl, 512, pBrzh, 512, pbrz,
                                                       prz, nullptr, nullptr, 512, 16, 0);
    gemm_mma<EPI_BIAS, 2><<<dim3(2, MB), 256, GSMEM>>>(pcath, pcatl, 512, pWnih, 256, bih + 512,
                                                       pinn, nullptr, nullptr, 256, 8, 0);
    cudaStreamWaitEvent(0, eN, 0);
    gru_kernel<<<(rows * 256 + 255) / 256, 256>>>(prz, pinn, phn, hidden, hout, phh, phl, pfh, pfl, rows * 256);
    // merged [p-planes | qk]
    gemm_mma<EPI_MIX, 2><<<dim3(3, MB), 256, GSMEM>>>(phh, phl, 256, pBpqh, 256, pbpq,
                                                      pqk, pph, ppl, 256, 8, 128);
    cudaEventRecord(e2, 0);
    cudaStreamWaitEvent(s1, e2, 0);
    qr_kernel<<<(rows * 4 + 127) / 128, 128, 0, s1>>>(pqk, Wk, bk, pqr, pqb, rows);
    cudaEventRecord(eQ, s1);
    gemm_mma<EPI_BIAS, 2><<<dim3(1, MB), 256, GSMEM>>>(pph, ppl, 256, pWp2h, 256, pbp2p,
                                                       plgp, nullptr, nullptr, 128, 8, 0);
    logits_post<<<rows / 8, 256>>>(plgp, Wv, bv, out, pattack, psender);
    cudaStreamWaitEvent(0, eQ, 0);
    attn_batch<<<bs, 256>>>(pqk, pqr, pqb, rel, psender, nullk, nullv, ln_g, ln_b, pfh, pfl);
    // gd: single-pass fp16 (error damped by FUSE_SCALE*gate)
    gemm_mma<EPI_BIAS_RELU, 1><<<dim3(4, MB), 256, GSMEM>>>(pfh, pfl, 288, pBgdh, 288, pbgd,
                                                            pgd, nullptr, nullptr, 512, 9, 0);
    final_kernel<<<rows / 8, 256>>>(pgd, Wg2, bg2, Wd2, bd2, pattack, out);
}